// round 4
// baseline (speedup 1.0000x reference)
#include <cuda_runtime.h>
#include <cuda_bf16.h>
#include <math.h>
#include <stdint.h>

#define BBATCH 64
#define LLEN 128
#define TSTEPS 48
#define EDIM 512
#define HEDIM 1024
#define HDIM 1024

typedef __nv_bfloat16 bf16;

// ---------------- device scratch ----------------
__device__ bf16 g_Wih1[4096 * 1024];      // [4096][2*512] hi|lo, gate-interleaved rows
__device__ bf16 g_Whh1[4096 * 2048];
__device__ bf16 g_Wih2A[4096 * 2048];
__device__ bf16 g_Wih2B[4096 * 2048];
__device__ bf16 g_Whh2[4096 * 2048];
__device__ bf16 g_WcmA[1024 * 2048];
__device__ bf16 g_WcmB[1024 * 2048];
__device__ bf16 g_Watt[1024 * 2048];
__device__ bf16 g_enchl[8192 * 2048];
__device__ bf16 g_capshl[3072 * 1024];
__device__ float g_encproj[8192 * 1024];
__device__ float g_pregates[3072 * 4096];
__device__ bf16 g_h1hl[2][BBATCH * 2048];
__device__ bf16 g_h2hl[2][BBATCH * 2048];
__device__ bf16 g_ohl[BBATCH * 2048];
__device__ bf16 g_athl[BBATCH * 2048];
__device__ float g_c1[BBATCH * HDIM];
__device__ float g_c2[BBATCH * HDIM];
__device__ float g_h2f[BBATCH * HDIM];
__device__ float g_bg1[4096];
__device__ float g_bg2[4096];

__device__ __forceinline__ float sigm(float x) { return 1.f / (1.f + __expf(-x)); }

#define CP16(dst, src) \
    asm volatile("cp.async.cg.shared.global [%0], [%1], 16;\n" ::"r"(dst), "l"(src))
#define LDSM4(R0, R1, R2, R3, ADDR)                                        \
    asm volatile("ldmatrix.sync.aligned.m8n8.x4.shared.b16 {%0,%1,%2,%3},[%4];\n" \
                 : "=r"(R0), "=r"(R1), "=r"(R2), "=r"(R3)                  \
                 : "r"(ADDR))
#define MMA16816(C, A0, A1, A2, A3, B0, B1)                                    \
    asm volatile(                                                               \
        "mma.sync.aligned.m16n8k16.row.col.f32.bf16.bf16.f32 "                  \
        "{%0,%1,%2,%3},{%4,%5,%6,%7},{%8,%9},{%0,%1,%2,%3};\n"                  \
        : "+f"((C)[0]), "+f"((C)[1]), "+f"((C)[2]), "+f"((C)[3])                \
        : "r"(A0), "r"(A1), "r"(A2), "r"(A3), "r"(B0), "r"(B1))

// ---------------- conversions ----------------
__global__ void conv_whl(const float* __restrict__ src, int srcld, int colOff, int K,
                         bf16* __restrict__ dst, int interleave, int N) {
    int idx = blockIdx.x * 256 + threadIdx.x;
    if (idx >= N * K) return;
    int n = idx / K, k = idx - n * K;
    int srcn = interleave ? ((n & 3) * HDIM + (n >> 2)) : n;
    float v = src[(size_t)srcn * srcld + colOff + k];
    bf16 hi = __float2bfloat16(v);
    bf16 lo = __float2bfloat16(v - __bfloat162float(hi));
    dst[(size_t)n * 2 * K + k] = hi;
    dst[(size_t)n * 2 * K + K + k] = lo;
}

__global__ void conv_bias(const float* __restrict__ bi1, const float* __restrict__ bh1,
                          const float* __restrict__ bi2, const float* __restrict__ bh2) {
    int n = blockIdx.x * 256 + threadIdx.x;
    if (n >= 4096) return;
    int srcn = (n & 3) * HDIM + (n >> 2);
    g_bg1[n] = bi1[srcn] + bh1[srcn];
    g_bg2[n] = bi2[srcn] + bh2[srcn];
}

__global__ void init_k(const float* __restrict__ h1i, const float* __restrict__ c1i,
                       const float* __restrict__ h2i, const float* __restrict__ c2i) {
    int i = blockIdx.x * 256 + threadIdx.x;
    if (i >= BBATCH * HDIM) return;
    int b = i >> 10, k = i & 1023;
    g_c1[i] = c1i[i];
    g_c2[i] = c2i[i];
    g_h2f[i] = h2i[i];
    float v1 = h1i[i];
    bf16 h = __float2bfloat16(v1);
    bf16 l = __float2bfloat16(v1 - __bfloat162float(h));
    g_h1hl[0][b * 2048 + k] = h;
    g_h1hl[0][b * 2048 + 1024 + k] = l;
    float v2 = h2i[i];
    h = __float2bfloat16(v2);
    l = __float2bfloat16(v2 - __bfloat162float(h));
    g_h2hl[0][b * 2048 + k] = h;
    g_h2hl[0][b * 2048 + 1024 + k] = l;
    bf16 z = __float2bfloat16(0.f);
    g_ohl[b * 2048 + k] = z;
    g_ohl[b * 2048 + 1024 + k] = z;
}

// ---------------- merged 3-term compensated bf16 GEMM, 8 warps, kh-split ----------------
// CTA tile 64(M) x 32(N). Warpgroup wg handles k-halves 2*wg..2*wg+1 of each 64-chunk.
// Stage (24576B): [Ahi 8192][Alo 8192][Whi 4096][Wlo 4096]
#define STGB 24576
#define NSTG 4

__global__ __launch_bounds__(256) void mma3(
    const bf16* A0, const bf16* W0, int K0,
    const bf16* A1, const bf16* W1, int K1,
    const bf16* A2, const bf16* W2, int K2,
    int npairs,
    const float* __restrict__ biasV,
    const float* __restrict__ biasM,
    float* __restrict__ outF, int ldo,
    bf16* __restrict__ outHL,
    float* __restrict__ cstate,
    int mode) {
    extern __shared__ __align__(16) char smem[];

    const int tid = threadIdx.x;
    const int w = tid >> 5;
    const int l = tid & 31;
    const int wg = w >> 2;
    const int wm = w & 3;
    const int m0 = blockIdx.y * 64;
    const int n0 = blockIdx.x * 32;

    const bf16* Ab[3] = {A0, A1, A2};
    const bf16* Wb[3] = {W0, W1, W2};
    const int Kp[3] = {K0, K1, K2};

    int NCH = 0;
    for (int p = 0; p < npairs; ++p) NCH += Kp[p] >> 6;

    const uint32_t sB = (uint32_t)__cvta_generic_to_shared(smem);

    int cp = 0, ckt = 0;
    auto issue = [&](int stg) {
        const bf16* A = Ab[cp];
        const bf16* W = Wb[cp];
        const int K = Kp[cp];
        const int ld = K << 1;
        const uint32_t base = sB + stg * STGB;
#pragma unroll
        for (int i = 0; i < 6; ++i) {
            int c = tid + (i << 8);  // 0..1535
            if (c < 512) {            // Ahi
                int row = c >> 3, ch = c & 7;
                const bf16* src = A + (size_t)(m0 + row) * ld + ckt + (ch << 3);
                CP16(base + row * 128 + ((ch ^ (row & 7)) << 4), src);
            } else if (c < 1024) {    // Alo
                int c2 = c - 512;
                int row = c2 >> 3, ch = c2 & 7;
                const bf16* src = A + (size_t)(m0 + row) * ld + K + ckt + (ch << 3);
                CP16(base + 8192 + row * 128 + ((ch ^ (row & 7)) << 4), src);
            } else if (c < 1280) {    // Whi
                int c2 = c - 1024;
                int row = c2 >> 3, ch = c2 & 7;
                const bf16* src = W + (size_t)(n0 + row) * ld + ckt + (ch << 3);
                CP16(base + 16384 + row * 128 + ((ch ^ (row & 7)) << 4), src);
            } else {                  // Wlo
                int c2 = c - 1280;
                int row = c2 >> 3, ch = c2 & 7;
                const bf16* src = W + (size_t)(n0 + row) * ld + K + ckt + (ch << 3);
                CP16(base + 20480 + row * 128 + ((ch ^ (row & 7)) << 4), src);
            }
        }
        asm volatile("cp.async.commit_group;\n" ::);
        ckt += 64;
        if (ckt >= K) { ckt = 0; ++cp; }
    };

    float acc[4][4];
#pragma unroll
    for (int j = 0; j < 4; ++j)
#pragma unroll
        for (int i = 0; i < 4; ++i) acc[j][i] = 0.f;

    const int npre = (NCH < NSTG - 1) ? NCH : (NSTG - 1);
    for (int i = 0; i < npre; ++i) issue(i);

    const int arow = 16 * wm + (l & 15);
    const int asel = (l >> 4) & 1;
    const int nrow0 = (l & 7) + ((l & 16) >> 1);
    const int nrow1 = nrow0 + 16;
    const int bsel = (l >> 3) & 1;

    for (int it = 0; it < NCH; ++it) {
        const int pend = ((NCH < it + NSTG - 1) ? NCH : (it + NSTG - 1)) - (it + 1);
        if (pend >= 2)      asm volatile("cp.async.wait_group 2;\n" ::);
        else if (pend == 1) asm volatile("cp.async.wait_group 1;\n" ::);
        else                asm volatile("cp.async.wait_group 0;\n" ::);
        __syncthreads();
        if (it + NSTG - 1 < NCH) issue((it + NSTG - 1) & (NSTG - 1));

        const uint32_t aHi = sB + (it & (NSTG - 1)) * STGB;
        const uint32_t aLo = aHi + 8192;
        const uint32_t wHi = aHi + 16384;
        const uint32_t wLo = aHi + 20480;
#pragma unroll
        for (int kh2 = 0; kh2 < 2; ++kh2) {
            const int kh = 2 * wg + kh2;
            const int ac = 2 * kh + asel;
            const int bc = 2 * kh + bsel;
            const uint32_t aoff = arow * 128 + ((ac ^ (arow & 7)) << 4);
            const uint32_t boff0 = nrow0 * 128 + ((bc ^ (nrow0 & 7)) << 4);
            const uint32_t boff1 = nrow1 * 128 + ((bc ^ (nrow1 & 7)) << 4);
            uint32_t ah0, ah1, ah2, ah3, al0, al1, al2, al3;
            LDSM4(ah0, ah1, ah2, ah3, aHi + aoff);
            LDSM4(al0, al1, al2, al3, aLo + aoff);
            uint32_t bh0, bh1, bh2, bh3, bh4, bh5, bh6, bh7;
            LDSM4(bh0, bh1, bh2, bh3, wHi + boff0);
            LDSM4(bh4, bh5, bh6, bh7, wHi + boff1);
            uint32_t bl0, bl1, bl2, bl3, bl4, bl5, bl6, bl7;
            LDSM4(bl0, bl1, bl2, bl3, wLo + boff0);
            LDSM4(bl4, bl5, bl6, bl7, wLo + boff1);
            MMA16816(acc[0], ah0, ah1, ah2, ah3, bh0, bh1);
            MMA16816(acc[1], ah0, ah1, ah2, ah3, bh2, bh3);
            MMA16816(acc[2], ah0, ah1, ah2, ah3, bh4, bh5);
            MMA16816(acc[3], ah0, ah1, ah2, ah3, bh6, bh7);
            MMA16816(acc[0], ah0, ah1, ah2, ah3, bl0, bl1);
            MMA16816(acc[1], ah0, ah1, ah2, ah3, bl2, bl3);
            MMA16816(acc[2], ah0, ah1, ah2, ah3, bl4, bl5);
            MMA16816(acc[3], ah0, ah1, ah2, ah3, bl6, bl7);
            MMA16816(acc[0], al0, al1, al2, al3, bh0, bh1);
            MMA16816(acc[1], al0, al1, al2, al3, bh2, bh3);
            MMA16816(acc[2], al0, al1, al2, al3, bh4, bh5);
            MMA16816(acc[3], al0, al1, al2, al3, bh6, bh7);
        }
    }
    __syncthreads();

    // ---- cross-warpgroup accumulator reduction (wg1 -> wg0) ----
    {
        float* red = (float*)(smem + STGB);
        const int rbase = ((wm * 32 + l) << 4);
        if (wg == 1) {
#pragma unroll
            for (int j = 0; j < 4; ++j)
#pragma unroll
                for (int i = 0; i < 4; ++i) red[rbase + j * 4 + i] = acc[j][i];
        }
        __syncthreads();
        if (wg == 0) {
#pragma unroll
            for (int j = 0; j < 4; ++j)
#pragma unroll
                for (int i = 0; i < 4; ++i) acc[j][i] += red[rbase + j * 4 + i];
        }
    }

    const int r = l >> 2;
    const int c2 = (l & 3) * 2;

    if (mode == 0) {
        if (wg == 0) {
#pragma unroll
            for (int j = 0; j < 4; ++j) {
                int n = n0 + 8 * j + c2;
                float bv0 = biasV[n], bv1 = biasV[n + 1];
                size_t row0 = (size_t)(m0 + 16 * wm + r);
                outF[row0 * ldo + n] = acc[j][0] + bv0;
                outF[row0 * ldo + n + 1] = acc[j][1] + bv1;
                outF[(row0 + 8) * ldo + n] = acc[j][2] + bv0;
                outF[(row0 + 8) * ldo + n + 1] = acc[j][3] + bv1;
            }
        }
    } else if (mode == 2) {
        if (wg == 0) {
#pragma unroll
            for (int j = 0; j < 4; ++j) {
                int n = n0 + 8 * j + c2;
                float bv0 = biasV[n], bv1 = biasV[n + 1];
                int b0r = 16 * wm + r;
#pragma unroll
                for (int hh = 0; hh < 2; ++hh) {
                    int bb = b0r + hh * 8;
                    float v0 = tanhf(acc[j][2 * hh] + bv0);
                    float v1 = tanhf(acc[j][2 * hh + 1] + bv1);
                    outF[(size_t)bb * ldo + n] = v0;
                    outF[(size_t)bb * ldo + n + 1] = v1;
                    bf16 h0 = __float2bfloat16(v0);
                    bf16 l0 = __float2bfloat16(v0 - __bfloat162float(h0));
                    bf16 h1 = __float2bfloat16(v1);
                    bf16 l1 = __float2bfloat16(v1 - __bfloat162float(h1));
                    outHL[bb * 2048 + n] = h0;
                    outHL[bb * 2048 + 1024 + n] = l0;
                    outHL[bb * 2048 + n + 1] = h1;
                    outHL[bb * 2048 + 1024 + n + 1] = l1;
                }
            }
        }
    } else {
        float* Csm = (float*)smem;
        if (wg == 0) {
#pragma unroll
            for (int j = 0; j < 4; ++j) {
                int col = 8 * j + c2;
                int n = n0 + col;
#pragma unroll
                for (int hh = 0; hh < 2; ++hh) {
                    int m = 16 * wm + r + hh * 8;
                    float b0 = biasM ? biasM[(size_t)m * 4096 + n] : biasV[n];
                    float b1 = biasM ? biasM[(size_t)m * 4096 + n + 1] : biasV[n + 1];
                    Csm[m * 33 + col] = acc[j][2 * hh] + b0;
                    Csm[m * 33 + col + 1] = acc[j][2 * hh + 1] + b1;
                }
            }
        }
        __syncthreads();
        if (tid < 128) {
#pragma unroll
            for (int q = 0; q < 4; ++q) {
                int item = tid * 4 + q;  // 512 = 64 b x 8 hu
                int b = item >> 3;
                int hu = item & 7;
                float gi = Csm[b * 33 + hu * 4 + 0];
                float gf = Csm[b * 33 + hu * 4 + 1];
                float gg = Csm[b * 33 + hu * 4 + 2];
                float go = Csm[b * 33 + hu * 4 + 3];
                int hg = (n0 >> 2) + hu;
                int idx = b * HDIM + hg;
                float cold = cstate[idx];
                float i_ = sigm(gi), f_ = sigm(gf), g_ = tanhf(gg), o_ = sigm(go);
                float cn = f_ * cold + i_ * g_;
                cstate[idx] = cn;
                float hv = o_ * tanhf(cn);
                if (outF) outF[idx] = hv;
                bf16 hi = __float2bfloat16(hv);
                bf16 lo = __float2bfloat16(hv - __bfloat162float(hi));
                outHL[b * 2048 + hg] = hi;
                outHL[b * 2048 + 1024 + hg] = lo;
            }
        }
    }
}

// ---------------- fused attention ----------------
__global__ __launch_bounds__(256) void attn_k(const float* __restrict__ h2f,
                                              const int* __restrict__ masks,
                                              const float* __restrict__ encproj,
                                              const float* __restrict__ enc,
                                              bf16* __restrict__ athl) {
    const int b = blockIdx.x;
    __shared__ __align__(16) float sh2[HDIM];
    __shared__ float sred[LLEN];
    __shared__ float salpha[LLEN];
    __shared__ float stmp[LLEN];
    const int tid = threadIdx.x;
    const int w = tid >> 5, l = tid & 31;

    {
        const float4* src = (const float4*)(h2f + b * HDIM);
        float4* dst = (float4*)sh2;
        dst[tid] = src[tid];
    }
    __syncthreads();

    const float4* sh4 = (const float4*)sh2;
    for (int li = 0; li < 8; ++li) {
        int ll = w * 16 + li * 2;
        const float4* e0 = (const float4*)(encproj + ((size_t)(b * LLEN + ll)) * HDIM);
        const float4* e1 = (const float4*)(encproj + ((size_t)(b * LLEN + ll + 1)) * HDIM);
        float s0 = 0.f, s1 = 0.f;
#pragma unroll
        for (int j = 0; j < 8; ++j) {
            float4 hv = sh4[l + 32 * j];
            float4 v0 = e0[l + 32 * j];
            float4 v1 = e1[l + 32 * j];
            s0 += hv.x * v0.x + hv.y * v0.y + hv.z * v0.z + hv.w * v0.w;
            s1 += hv.x * v1.x + hv.y * v1.y + hv.z * v1.z + hv.w * v1.w;
        }
#pragma unroll
        for (int o = 16; o; o >>= 1) {
            s0 += __shfl_xor_sync(0xffffffffu, s0, o);
            s1 += __shfl_xor_sync(0xffffffffu, s1, o);
        }
        if (l == 0) {
            sred[ll] = masks[b * LLEN + ll] ? -1e30f : s0;
            sred[ll + 1] = masks[b * LLEN + ll + 1] ? -1e30f : s1;
        }
    }
    __syncthreads();

    if (tid < 128) stmp[tid] = sred[tid];
    __syncthreads();
    for (int s = 64; s; s >>= 1) {
        if (tid < s) stmp[tid] = fmaxf(stmp[tid], stmp[tid + s]);
        __syncthreads();
    }
    const float mx = stmp[0];
    __syncthreads();
    if (tid < 128) {
        float p = __expf(sred[tid] - mx);
        salpha[tid] = p;
        stmp[tid] = p;
    }
    __syncthreads();
    for (int s = 64; s; s >>= 1) {
        if (tid < s) stmp[tid] += stmp[tid + s];
        __syncthreads();
    }
    const float inv = 1.f / stmp[0];
    __syncthreads();
    if (tid < 128) salpha[tid] *= inv;
    __syncthreads();

    float4 p[8];
#pragma unroll
    for (int u = 0; u < 8; ++u) p[u] = make_float4(0.f, 0.f, 0.f, 0.f);
    const float4* ep4 = (const float4*)(enc + (size_t)b * LLEN * HEDIM);
    for (int l0 = 0; l0 < LLEN; l0 += 8) {
#pragma unroll
        for (int u = 0; u < 8; ++u) {
            float al = salpha[l0 + u];
            float4 v = ep4[(l0 + u) * 256 + tid];
            p[u].x += al * v.x;
            p[u].y += al * v.y;
            p[u].z += al * v.z;
            p[u].w += al * v.w;
        }
    }
#pragma unroll
    for (int u = 1; u < 8; ++u) {
        p[0].x += p[u].x; p[0].y += p[u].y; p[0].z += p[u].z; p[0].w += p[u].w;
    }
    int f = tid * 4;
    float vals[4] = {p[0].x, p[0].y, p[0].z, p[0].w};
#pragma unroll
    for (int i = 0; i < 4; ++i) {
        bf16 hi = __float2bfloat16(vals[i]);
        bf16 lo = __float2bfloat16(vals[i] - __bfloat162float(hi));
        athl[b * 2048 + f + i] = hi;
        athl[b * 2048 + 1024 + f + i] = lo;
    }
}

// ---------------- host launcher ----------------
extern "C" void kernel_launch(void* const* d_in, const int* in_sizes, int n_in,
                              void* d_out, int out_size) {
    const float* enc = (const float*)d_in[0];
    const int* masks = (const int*)d_in[1];
    const float* h1i = (const float*)d_in[2];
    const float* c1i = (const float*)d_in[3];
    const float* h2i = (const float*)d_in[4];
    const float* c2i = (const float*)d_in[5];
    const float* cap = (const float*)d_in[6];
    const float* W_ih1 = (const float*)d_in[7];
    const float* W_hh1 = (const float*)d_in[8];
    const float* b_ih1 = (const float*)d_in[9];
    const float* b_hh1 = (const float*)d_in[10];
    const float* W_ih2 = (const float*)d_in[11];
    const float* W_hh2 = (const float*)d_in[12];
    const float* b_ih2 = (const float*)d_in[13];
    const float* b_hh2 = (const float*)d_in[14];
    const float* W_att = (const float*)d_in[15];
    const float* b_att = (const float*)d_in[16];
    const float* W_comb = (const float*)d_in[17];
    const float* b_comb = (const float*)d_in[18];
    float* outs = (float*)d_out;

    bf16 *pWih1, *pWhh1, *pWih2A, *pWih2B, *pWhh2, *pWcmA, *pWcmB, *pWatt;
    bf16 *pEnchl, *pCapshl, *pOhl, *pAthl, *pH1hl0, *pH2hl0;
    float *pEncproj, *pPre, *pC1, *pC2, *pH2f, *pBg1, *pBg2;
    cudaGetSymbolAddress((void**)&pWih1, g_Wih1);
    cudaGetSymbolAddress((void**)&pWhh1, g_Whh1);
    cudaGetSymbolAddress((void**)&pWih2A, g_Wih2A);
    cudaGetSymbolAddress((void**)&pWih2B, g_Wih2B);
    cudaGetSymbolAddress((void**)&pWhh2, g_Whh2);
    cudaGetSymbolAddress((void**)&pWcmA, g_WcmA);
    cudaGetSymbolAddress((void**)&pWcmB, g_WcmB);
    cudaGetSymbolAddress((void**)&pWatt, g_Watt);
    cudaGetSymbolAddress((void**)&pEnchl, g_enchl);
    cudaGetSymbolAddress((void**)&pCapshl, g_capshl);
    cudaGetSymbolAddress((void**)&pEncproj, g_encproj);
    cudaGetSymbolAddress((void**)&pPre, g_pregates);
    cudaGetSymbolAddress((void**)&pH1hl0, g_h1hl);
    cudaGetSymbolAddress((void**)&pH2hl0, g_h2hl);
    cudaGetSymbolAddress((void**)&pOhl, g_ohl);
    cudaGetSymbolAddress((void**)&pAthl, g_athl);
    cudaGetSymbolAddress((void**)&pC1, g_c1);
    cudaGetSymbolAddress((void**)&pC2, g_c2);
    cudaGetSymbolAddress((void**)&pH2f, g_h2f);
    cudaGetSymbolAddress((void**)&pBg1, g_bg1);
    cudaGetSymbolAddress((void**)&pBg2, g_bg2);

    bf16* pH1hl[2] = {pH1hl0, pH1hl0 + BBATCH * 2048};
    bf16* pH2hl[2] = {pH2hl0, pH2hl0 + BBATCH * 2048};

    cudaFuncSetAttribute(mma3, cudaFuncAttributeMaxDynamicSharedMemorySize, NSTG * STGB);
    const int SMEM = NSTG * STGB;

    auto cgrid = [](int n) { return (n + 255) / 256; };
    conv_whl<<<cgrid(4096 * 512), 256>>>(W_ih1, 512, 0, 512, pWih1, 1, 4096);
    conv_whl<<<cgrid(4096 * 1024), 256>>>(W_hh1, 1024, 0, 1024, pWhh1, 1, 4096);
    conv_whl<<<cgrid(4096 * 1024), 256>>>(W_ih2, 2048, 0, 1024, pWih2A, 1, 4096);
    conv_whl<<<cgrid(4096 * 1024), 256>>>(W_ih2, 2048, 1024, 1024, pWih2B, 1, 4096);
    conv_whl<<<cgrid(4096 * 1024), 256>>>(W_hh2, 1024, 0, 1024, pWhh2, 1, 4096);
    conv_whl<<<cgrid(1024 * 1024), 256>>>(W_comb, 2048, 0, 1024, pWcmA, 0, 1024);
    conv_whl<<<cgrid(1024 * 1024), 256>>>(W_comb, 2048, 1024, 1024, pWcmB, 0, 1024);
    conv_whl<<<cgrid(1024 * 1024), 256>>>(W_att, 1024, 0, 1024, pWatt, 0, 1024);
    conv_whl<<<cgrid(8192 * 1024), 256>>>(enc, 1024, 0, 1024, pEnchl, 0, 8192);
    conv_whl<<<cgrid(3072 * 512), 256>>>(cap, 512, 0, 512, pCapshl, 0, 3072);
    conv_bias<<<16, 256>>>(b_ih1, b_hh1, b_ih2, b_hh2);
    init_k<<<(BBATCH * HDIM + 255) / 256, 256>>>(h1i, c1i, h2i, c2i);

    // pregates1 = captions_all @ Wih1^T + bg1
    mma3<<<dim3(128, 48), 256, SMEM>>>(
        pCapshl, pWih1, 512, nullptr, nullptr, 0, nullptr, nullptr, 0,
        1, pBg1, nullptr, pPre, 4096, nullptr, nullptr, 0);

    // enc_proj = enc @ W_att^T + b_att
    mma3<<<dim3(32, 128), 256, SMEM>>>(
        pEnchl, pWatt, 1024, nullptr, nullptr, 0, nullptr, nullptr, 0,
        1, b_att, nullptr, pEncproj, 1024, nullptr, nullptr, 0);

    for (int t = 0; t < TSTEPS; ++t) {
        const int cur = t & 1;

        mma3<<<dim3(128, 1), 256, SMEM>>>(
            pH1hl[cur], pWhh1, 1024, nullptr, nullptr, 0, nullptr, nullptr, 0,
            1, nullptr, pPre + (size_t)t * BBATCH * 4096,
            nullptr, 0, pH1hl[cur ^ 1], pC1, 1);

        mma3<<<dim3(128, 1), 256, SMEM>>>(
            pH1hl[cur ^ 1], pWih2A, 1024, pOhl, pWih2B, 1024, pH2hl[cur], pWhh2, 1024,
            3, pBg2, nullptr, pH2f, 0, pH2hl[cur ^ 1], pC2, 1);

        attn_k<<<BBATCH, 256>>>(pH2f, masks, pEncproj, enc, pAthl);

        mma3<<<dim3(32, 1), 256, SMEM>>>(
            pAthl, pWcmA, 1024, pH2hl[cur ^ 1], pWcmB, 1024, nullptr, nullptr, 0,
            2, b_comb, nullptr, outs + (size_t)t * BBATCH * HDIM, 1024, pOhl, nullptr, 2);
    }
}

// round 6
// speedup vs baseline: 1.2222x; 1.2222x over previous
#include <cuda_runtime.h>
#include <cuda_bf16.h>
#include <math.h>
#include <stdint.h>

#define BBATCH 64
#define LLEN 128
#define TSTEPS 48
#define EDIM 512
#define HEDIM 1024
#define HDIM 1024
#define NCTA 148

typedef __nv_bfloat16 bf16;

// ---------------- device scratch ----------------
__device__ bf16 g_Wih1[4096 * 1024];
__device__ bf16 g_Whh1[4096 * 2048];
__device__ bf16 g_Wih2A[4096 * 2048];
__device__ bf16 g_Wih2B[4096 * 2048];
__device__ bf16 g_Whh2[4096 * 2048];
__device__ bf16 g_WcmA[1024 * 2048];
__device__ bf16 g_WcmB[1024 * 2048];
__device__ bf16 g_Watt[1024 * 2048];
__device__ bf16 g_enchl[8192 * 2048];
__device__ bf16 g_capshl[3072 * 1024];
__device__ float g_encproj[8192 * 1024];
__device__ float g_pregates[3072 * 4096];
__device__ bf16 g_h1hl[2][BBATCH * 2048];
__device__ bf16 g_h2hl[2][BBATCH * 2048];
__device__ bf16 g_ohl[BBATCH * 2048];
__device__ bf16 g_athl[BBATCH * 2048];
__device__ float g_c1[BBATCH * HDIM];
__device__ float g_c2[BBATCH * HDIM];
__device__ float g_h2f[BBATCH * HDIM];
__device__ float g_bg1[4096];
__device__ float g_bg2[4096];

// grid barrier state (zero-initialized; cnt self-resets, gen monotonic)
__device__ unsigned g_cnt[256];
__device__ unsigned g_gen[256];

__device__ __forceinline__ float sigm(float x) { return 1.f / (1.f + __expf(-x)); }

#define CP16(dst, src) \
    asm volatile("cp.async.cg.shared.global [%0], [%1], 16;\n" ::"r"(dst), "l"(src))
#define LDSM4(R0, R1, R2, R3, ADDR)                                        \
    asm volatile("ldmatrix.sync.aligned.m8n8.x4.shared.b16 {%0,%1,%2,%3},[%4];\n" \
                 : "=r"(R0), "=r"(R1), "=r"(R2), "=r"(R3)                  \
                 : "r"(ADDR))
#define MMA16816(C, A0, A1, A2, A3, B0, B1)                                    \
    asm volatile(                                                               \
        "mma.sync.aligned.m16n8k16.row.col.f32.bf16.bf16.f32 "                  \
        "{%0,%1,%2,%3},{%4,%5,%6,%7},{%8,%9},{%0,%1,%2,%3};\n"                  \
        : "+f"((C)[0]), "+f"((C)[1]), "+f"((C)[2]), "+f"((C)[3])                \
        : "r"(A0), "r"(A1), "r"(A2), "r"(A3), "r"(B0), "r"(B1))

// ---------------- conversions ----------------
__global__ void conv_whl(const float* __restrict__ src, int srcld, int colOff, int K,
                         bf16* __restrict__ dst, int interleave, int N) {
    int idx = blockIdx.x * 256 + threadIdx.x;
    if (idx >= N * K) return;
    int n = idx / K, k = idx - n * K;
    int srcn = interleave ? ((n & 3) * HDIM + (n >> 2)) : n;
    float v = src[(size_t)srcn * srcld + colOff + k];
    bf16 hi = __float2bfloat16(v);
    bf16 lo = __float2bfloat16(v - __bfloat162float(hi));
    dst[(size_t)n * 2 * K + k] = hi;
    dst[(size_t)n * 2 * K + K + k] = lo;
}

__global__ void conv_bias(const float* __restrict__ bi1, const float* __restrict__ bh1,
                          const float* __restrict__ bi2, const float* __restrict__ bh2) {
    int n = blockIdx.x * 256 + threadIdx.x;
    if (n >= 4096) return;
    int srcn = (n & 3) * HDIM + (n >> 2);
    g_bg1[n] = bi1[srcn] + bh1[srcn];
    g_bg2[n] = bi2[srcn] + bh2[srcn];
}

__global__ void init_k(const float* __restrict__ h1i, const float* __restrict__ c1i,
                       const float* __restrict__ h2i, const float* __restrict__ c2i) {
    int i = blockIdx.x * 256 + threadIdx.x;
    if (i >= BBATCH * HDIM) return;
    int b = i >> 10, k = i & 1023;
    g_c1[i] = c1i[i];
    g_c2[i] = c2i[i];
    g_h2f[i] = h2i[i];
    float v1 = h1i[i];
    bf16 h = __float2bfloat16(v1);
    bf16 l = __float2bfloat16(v1 - __bfloat162float(h));
    g_h1hl[0][b * 2048 + k] = h;
    g_h1hl[0][b * 2048 + 1024 + k] = l;
    float v2 = h2i[i];
    h = __float2bfloat16(v2);
    l = __float2bfloat16(v2 - __bfloat162float(h));
    g_h2hl[0][b * 2048 + k] = h;
    g_h2hl[0][b * 2048 + 1024 + k] = l;
    bf16 z = __float2bfloat16(0.f);
    g_ohl[b * 2048 + k] = z;
    g_ohl[b * 2048 + 1024 + k] = z;
}

// ---------------- GEMM mainloop (64xM tile rows at m0, 32 N-cols at n0) ----------------
#define STGB 24576
#define NSTG 4

__device__ __forceinline__ void gemm_main(
    char* smem, int m0, int n0,
    const bf16* A0, const bf16* W0, int K0,
    const bf16* A1, const bf16* W1, int K1,
    const bf16* A2, const bf16* W2, int K2,
    int npairs, float acc[4][4]) {
    const int tid = threadIdx.x;
    const int w = tid >> 5;
    const int l = tid & 31;
    const int wg = w >> 2;
    const int wm = w & 3;

    const bf16* Ab[3] = {A0, A1, A2};
    const bf16* Wb[3] = {W0, W1, W2};
    const int Kp[3] = {K0, K1, K2};

    int NCH = 0;
    for (int p = 0; p < npairs; ++p) NCH += Kp[p] >> 6;

    const uint32_t sB = (uint32_t)__cvta_generic_to_shared(smem);

    int cp = 0, ckt = 0;
    auto issue = [&](int stg) {
        const bf16* A = Ab[cp];
        const bf16* W = Wb[cp];
        const int K = Kp[cp];
        const int ld = K << 1;
        const uint32_t base = sB + stg * STGB;
#pragma unroll
        for (int i = 0; i < 6; ++i) {
            int c = tid + (i << 8);
            if (c < 512) {
                int row = c >> 3, ch = c & 7;
                const bf16* src = A + (size_t)(m0 + row) * ld + ckt + (ch << 3);
                CP16(base + row * 128 + ((ch ^ (row & 7)) << 4), src);
            } else if (c < 1024) {
                int c2 = c - 512;
                int row = c2 >> 3, ch = c2 & 7;
                const bf16* src = A + (size_t)(m0 + row) * ld + K + ckt + (ch << 3);
                CP16(base + 8192 + row * 128 + ((ch ^ (row & 7)) << 4), src);
            } else if (c < 1280) {
                int c2 = c - 1024;
                int row = c2 >> 3, ch = c2 & 7;
                const bf16* src = W + (size_t)(n0 + row) * ld + ckt + (ch << 3);
                CP16(base + 16384 + row * 128 + ((ch ^ (row & 7)) << 4), src);
            } else {
                int c2 = c - 1280;
                int row = c2 >> 3, ch = c2 & 7;
                const bf16* src = W + (size_t)(n0 + row) * ld + K + ckt + (ch << 3);
                CP16(base + 20480 + row * 128 + ((ch ^ (row & 7)) << 4), src);
            }
        }
        asm volatile("cp.async.commit_group;\n" ::);
        ckt += 64;
        if (ckt >= K) { ckt = 0; ++cp; }
    };

#pragma unroll
    for (int j = 0; j < 4; ++j)
#pragma unroll
        for (int i = 0; i < 4; ++i) acc[j][i] = 0.f;

    const int npre = (NCH < NSTG - 1) ? NCH : (NSTG - 1);
    for (int i = 0; i < npre; ++i) issue(i);

    const int arow = 16 * wm + (l & 15);
    const int asel = (l >> 4) & 1;
    const int nrow0 = (l & 7) + ((l & 16) >> 1);
    const int nrow1 = nrow0 + 16;
    const int bsel = (l >> 3) & 1;

    for (int it = 0; it < NCH; ++it) {
        const int pend = ((NCH < it + NSTG - 1) ? NCH : (it + NSTG - 1)) - (it + 1);
        if (pend >= 2)      asm volatile("cp.async.wait_group 2;\n" ::);
        else if (pend == 1) asm volatile("cp.async.wait_group 1;\n" ::);
        else                asm volatile("cp.async.wait_group 0;\n" ::);
        __syncthreads();
        if (it + NSTG - 1 < NCH) issue((it + NSTG - 1) & (NSTG - 1));

        const uint32_t aHi = sB + (it & (NSTG - 1)) * STGB;
        const uint32_t aLo = aHi + 8192;
        const uint32_t wHi = aHi + 16384;
        const uint32_t wLo = aHi + 20480;
#pragma unroll
        for (int kh2 = 0; kh2 < 2; ++kh2) {
            const int kh = 2 * wg + kh2;
            const int ac = 2 * kh + asel;
            const int bc = 2 * kh + bsel;
            const uint32_t aoff = arow * 128 + ((ac ^ (arow & 7)) << 4);
            const uint32_t boff0 = nrow0 * 128 + ((bc ^ (nrow0 & 7)) << 4);
            const uint32_t boff1 = nrow1 * 128 + ((bc ^ (nrow1 & 7)) << 4);
            uint32_t ah0, ah1, ah2, ah3, al0, al1, al2, al3;
            LDSM4(ah0, ah1, ah2, ah3, aHi + aoff);
            LDSM4(al0, al1, al2, al3, aLo + aoff);
            uint32_t bh0, bh1, bh2, bh3, bh4, bh5, bh6, bh7;
            LDSM4(bh0, bh1, bh2, bh3, wHi + boff0);
            LDSM4(bh4, bh5, bh6, bh7, wHi + boff1);
            uint32_t bl0, bl1, bl2, bl3, bl4, bl5, bl6, bl7;
            LDSM4(bl0, bl1, bl2, bl3, wLo + boff0);
            LDSM4(bl4, bl5, bl6, bl7, wLo + boff1);
            MMA16816(acc[0], ah0, ah1, ah2, ah3, bh0, bh1);
            MMA16816(acc[1], ah0, ah1, ah2, ah3, bh2, bh3);
            MMA16816(acc[2], ah0, ah1, ah2, ah3, bh4, bh5);
            MMA16816(acc[3], ah0, ah1, ah2, ah3, bh6, bh7);
            MMA16816(acc[0], ah0, ah1, ah2, ah3, bl0, bl1);
            MMA16816(acc[1], ah0, ah1, ah2, ah3, bl2, bl3);
            MMA16816(acc[2], ah0, ah1, ah2, ah3, bl4, bl5);
            MMA16816(acc[3], ah0, ah1, ah2, ah3, bl6, bl7);
            MMA16816(acc[0], al0, al1, al2, al3, bh0, bh1);
            MMA16816(acc[1], al0, al1, al2, al3, bh2, bh3);
            MMA16816(acc[2], al0, al1, al2, al3, bh4, bh5);
            MMA16816(acc[3], al0, al1, al2, al3, bh6, bh7);
        }
    }
    __syncthreads();

    // cross-warpgroup reduction (wg1 -> wg0)
    {
        float* red = (float*)(smem + STGB);
        const int rbase = ((wm * 32 + l) << 4);
        if (wg == 1) {
#pragma unroll
            for (int j = 0; j < 4; ++j)
#pragma unroll
                for (int i = 0; i < 4; ++i) red[rbase + j * 4 + i] = acc[j][i];
        }
        __syncthreads();
        if (wg == 0) {
#pragma unroll
            for (int j = 0; j < 4; ++j)
#pragma unroll
                for (int i = 0; i < 4; ++i) acc[j][i] += red[rbase + j * 4 + i];
        }
    }
}

// ---------------- epilogues ----------------
__device__ __forceinline__ void epi_store(char* smem, int m0, int n0, float acc[4][4],
                                          const float* biasV, float* outF, int ldo) {
    const int tid = threadIdx.x;
    const int w = tid >> 5, l = tid & 31;
    const int wg = w >> 2, wm = w & 3;
    const int r = l >> 2, c2 = (l & 3) * 2;
    if (wg != 0) return;
#pragma unroll
    for (int j = 0; j < 4; ++j) {
        int n = n0 + 8 * j + c2;
        float bv0 = biasV[n], bv1 = biasV[n + 1];
        size_t row0 = (size_t)(m0 + 16 * wm + r);
        outF[row0 * ldo + n] = acc[j][0] + bv0;
        outF[row0 * ldo + n + 1] = acc[j][1] + bv1;
        outF[(row0 + 8) * ldo + n] = acc[j][2] + bv0;
        outF[(row0 + 8) * ldo + n + 1] = acc[j][3] + bv1;
    }
}

__device__ __forceinline__ void epi_lstm(char* smem, int n0, float acc[4][4],
                                         const float* biasV, const float* biasM,
                                         bf16* outHL, float* outF, float* cstate) {
    const int tid = threadIdx.x;
    const int w = tid >> 5, l = tid & 31;
    const int wg = w >> 2, wm = w & 3;
    const int r = l >> 2, c2 = (l & 3) * 2;
    float* Csm = (float*)smem;
    if (wg == 0) {
#pragma unroll
        for (int j = 0; j < 4; ++j) {
            int col = 8 * j + c2;
            int n = n0 + col;
#pragma unroll
            for (int hh = 0; hh < 2; ++hh) {
                int m = 16 * wm + r + hh * 8;
                float b0 = biasM ? biasM[(size_t)m * 4096 + n] : biasV[n];
                float b1 = biasM ? biasM[(size_t)m * 4096 + n + 1] : biasV[n + 1];
                Csm[m * 33 + col] = acc[j][2 * hh] + b0;
                Csm[m * 33 + col + 1] = acc[j][2 * hh + 1] + b1;
            }
        }
    }
    __syncthreads();
    if (tid < 128) {
#pragma unroll
        for (int q = 0; q < 4; ++q) {
            int item = tid * 4 + q;
            int b = item >> 3;
            int hu = item & 7;
            float gi = Csm[b * 33 + hu * 4 + 0];
            float gf = Csm[b * 33 + hu * 4 + 1];
            float gg = Csm[b * 33 + hu * 4 + 2];
            float go = Csm[b * 33 + hu * 4 + 3];
            int hg = (n0 >> 2) + hu;
            int idx = b * HDIM + hg;
            float cold = cstate[idx];
            float i_ = sigm(gi), f_ = sigm(gf), g_ = tanhf(gg), o_ = sigm(go);
            float cn = f_ * cold + i_ * g_;
            cstate[idx] = cn;
            float hv = o_ * tanhf(cn);
            if (outF) outF[idx] = hv;
            bf16 hi = __float2bfloat16(hv);
            bf16 lo = __float2bfloat16(hv - __bfloat162float(hi));
            outHL[b * 2048 + hg] = hi;
            outHL[b * 2048 + 1024 + hg] = lo;
        }
    }
    __syncthreads();
}

__device__ __forceinline__ void epi_tanh(int n0, float acc[4][4], const float* biasV,
                                         float* outF, int ldo, bf16* outHL) {
    const int tid = threadIdx.x;
    const int w = tid >> 5, l = tid & 31;
    const int wg = w >> 2, wm = w & 3;
    const int r = l >> 2, c2 = (l & 3) * 2;
    if (wg != 0) return;
#pragma unroll
    for (int j = 0; j < 4; ++j) {
        int n = n0 + 8 * j + c2;
        float bv0 = biasV[n], bv1 = biasV[n + 1];
        int b0r = 16 * wm + r;
#pragma unroll
        for (int hh = 0; hh < 2; ++hh) {
            int bb = b0r + hh * 8;
            float v0 = tanhf(acc[j][2 * hh] + bv0);
            float v1 = tanhf(acc[j][2 * hh + 1] + bv1);
            outF[(size_t)bb * ldo + n] = v0;
            outF[(size_t)bb * ldo + n + 1] = v1;
            bf16 h0 = __float2bfloat16(v0);
            bf16 l0 = __float2bfloat16(v0 - __bfloat162float(h0));
            bf16 h1 = __float2bfloat16(v1);
            bf16 l1 = __float2bfloat16(v1 - __bfloat162float(h1));
            outHL[bb * 2048 + n] = h0;
            outHL[bb * 2048 + 1024 + n] = l0;
            outHL[bb * 2048 + n + 1] = h1;
            outHL[bb * 2048 + 1024 + n + 1] = l1;
        }
    }
}

// ---------------- attention (per-b, one CTA) ----------------
__device__ __forceinline__ void attn_dev(char* smem, int b,
                                         const int* __restrict__ masks,
                                         const float* __restrict__ encproj,
                                         const float* __restrict__ enc,
                                         const float* __restrict__ h2f,
                                         bf16* __restrict__ athl) {
    float* sh2 = (float*)smem;
    float* sred = sh2 + HDIM;
    float* salpha = sred + LLEN;
    float* stmp = salpha + LLEN;
    const int tid = threadIdx.x;
    const int w = tid >> 5, l = tid & 31;

    {
        const float4* src = (const float4*)(h2f + b * HDIM);
        ((float4*)sh2)[tid] = __ldcg(src + tid);
    }
    __syncthreads();

    const float4* sh4 = (const float4*)sh2;
    for (int li = 0; li < 8; ++li) {
        int ll = w * 16 + li * 2;
        const float4* e0 = (const float4*)(encproj + ((size_t)(b * LLEN + ll)) * HDIM);
        const float4* e1 = (const float4*)(encproj + ((size_t)(b * LLEN + ll + 1)) * HDIM);
        float s0 = 0.f, s1 = 0.f;
#pragma unroll
        for (int j = 0; j < 8; ++j) {
            float4 hv = sh4[l + 32 * j];
            float4 v0 = e0[l + 32 * j];
            float4 v1 = e1[l + 32 * j];
            s0 += hv.x * v0.x + hv.y * v0.y + hv.z * v0.z + hv.w * v0.w;
            s1 += hv.x * v1.x + hv.y * v1.y + hv.z * v1.z + hv.w * v1.w;
        }
#pragma unroll
        for (int o = 16; o; o >>= 1) {
            s0 += __shfl_xor_sync(0xffffffffu, s0, o);
            s1 += __shfl_xor_sync(0xffffffffu, s1, o);
        }
        if (l == 0) {
            sred[ll] = masks[b * LLEN + ll] ? -1e30f : s0;
            sred[ll + 1] = masks[b * LLEN + ll + 1] ? -1e30f : s1;
        }
    }
    __syncthreads();

    if (tid < 128) stmp[tid] = sred[tid];
    __syncthreads();
    for (int s = 64; s; s >>= 1) {
        if (tid < s) stmp[tid] = fmaxf(stmp[tid], stmp[tid + s]);
        __syncthreads();
    }
    const float mx = stmp[0];
    __syncthreads();
    if (tid < 128) {
        float p = __expf(sred[tid] - mx);
        salpha[tid] = p;
        stmp[tid] = p;
    }
    __syncthreads();
    for (int s = 64; s; s >>= 1) {
        if (tid < s) stmp[tid] += stmp[tid + s];
        __syncthreads();
    }
    const float inv = 1.f / stmp[0];
    __syncthreads();
    if (tid < 128) salpha[tid] *= inv;
    __syncthreads();

    float4 p[8];
#pragma unroll
    for (int u = 0; u < 8; ++u) p[u] = make_float4(0.f, 0.f, 0.f, 0.f);
    const float4* ep4 = (const float4*)(enc + (size_t)b * LLEN * HEDIM);
    for (int l0 = 0; l0 < LLEN; l0 += 8) {
#pragma unroll
        for (int u = 0; u < 8; ++u) {
            float al = salpha[l0 + u];
            float4 v = ep4[(l0 + u) * 256 + tid];
            p[u].x += al * v.x;
            p[u].y += al * v.y;
            p[u].z += al * v.z;
            p[u].w += al * v.w;
        }
    }
#pragma unroll
    for (int u = 1; u < 8; ++u) {
        p[0].x += p[u].x; p[0].y += p[u].y; p[0].z += p[u].z; p[0].w += p[u].w;
    }
    int f = tid * 4;
    float vals[4] = {p[0].x, p[0].y, p[0].z, p[0].w};
#pragma unroll
    for (int i = 0; i < 4; ++i) {
        bf16 hi = __float2bfloat16(vals[i]);
        bf16 lo = __float2bfloat16(vals[i] - __bfloat162float(hi));
        athl[b * 2048 + f + i] = hi;
        athl[b * 2048 + 1024 + f + i] = lo;
    }
    __syncthreads();
}

// ---------------- grid barrier (replay-safe) ----------------
__device__ __forceinline__ void gsync(int slot) {
    __threadfence();
    __syncthreads();
    if (threadIdx.x == 0) {
        unsigned g = ((volatile unsigned*)g_gen)[slot];
        unsigned old = atomicAdd(&g_cnt[slot], 1u);
        if (old == NCTA - 1) {
            g_cnt[slot] = 0;
            __threadfence();
            atomicExch(&g_gen[slot], g + 1);
        } else {
            while (((volatile unsigned*)g_gen)[slot] == g) __nanosleep(64);
        }
    }
    __syncthreads();
    __threadfence();
}

// ---------------- prologue GEMM (fp32 store) ----------------
__global__ __launch_bounds__(256) void mma_pro(
    const bf16* A0, const bf16* W0, int K0,
    const float* __restrict__ biasV, float* __restrict__ outF, int ldo) {
    extern __shared__ __align__(16) char smem[];
    float acc[4][4];
    gemm_main(smem, blockIdx.y * 64, blockIdx.x * 32,
              A0, W0, K0, nullptr, nullptr, 0, nullptr, nullptr, 0, 1, acc);
    epi_store(smem, blockIdx.y * 64, blockIdx.x * 32, acc, biasV, outF, ldo);
}

// ---------------- persistent decoder loop ----------------
__global__ __launch_bounds__(256, 1) void decoder_loop(
    const int* __restrict__ masks, const float* __restrict__ enc,
    const float* __restrict__ b_comb, float* __restrict__ outs) {
    extern __shared__ __align__(16) char smem[];
    const int bid = blockIdx.x;
    float acc[4][4];

    // phase 0: LSTM1 @ t=0  (reads h1hl[0], writes h1hl[1])
    if (bid < 128) {
        int n0 = bid * 32;
        gemm_main(smem, 0, n0, g_h1hl[0], g_Whh1, 1024,
                  nullptr, nullptr, 0, nullptr, nullptr, 0, 1, acc);
        epi_lstm(smem, n0, acc, nullptr, g_pregates, g_h1hl[1], nullptr, g_c1);
    }
    gsync(0);

    for (int t = 0; t < TSTEPS; ++t) {
        const int cur = t & 1;
        // LSTM2 @ t: reads h1hl[cur^1] (LSTM1@t output), h2hl[cur]; writes h2hl[cur^1]
        if (bid < 128) {
            int n0 = bid * 32;
            gemm_main(smem, 0, n0, g_h1hl[cur ^ 1], g_Wih2A, 1024,
                      g_ohl, g_Wih2B, 1024, g_h2hl[cur], g_Whh2, 1024, 3, acc);
            epi_lstm(smem, n0, acc, g_bg2, nullptr, g_h2hl[cur ^ 1], g_h2f, g_c2);
        }
        gsync(1 + t * 3);

        // attention @ t
        if (bid < 64)
            attn_dev(smem, bid, masks, g_encproj, enc, g_h2f, g_athl);
        gsync(2 + t * 3);

        // merged: comb @ t (CTAs 116..147) || LSTM1 @ t+1 (CTAs 0..115)
        if (bid >= 116) {
            int n0 = (bid - 116) * 32;
            gemm_main(smem, 0, n0, g_athl, g_WcmA, 1024,
                      g_h2hl[cur ^ 1], g_WcmB, 1024, nullptr, nullptr, 0, 2, acc);
            epi_tanh(n0, acc, b_comb, outs + (size_t)t * BBATCH * HDIM, 1024, g_ohl);
        } else if (t + 1 < TSTEPS) {
            // LSTM1 @ t+1: reads h1hl[(t+1)&1] (LSTM1@t output), writes h1hl[t&1]
            for (int tile = bid; tile < 128; tile += 116) {
                int n0 = tile * 32;
                gemm_main(smem, 0, n0, g_h1hl[(t + 1) & 1], g_Whh1, 1024,
                          nullptr, nullptr, 0, nullptr, nullptr, 0, 1, acc);
                epi_lstm(smem, n0, acc, nullptr,
                         g_pregates + (size_t)(t + 1) * BBATCH * 4096,
                         g_h1hl[t & 1], nullptr, g_c1);
            }
        }
        gsync(3 + t * 3);
    }
}

// ---------------- host launcher ----------------
extern "C" void kernel_launch(void* const* d_in, const int* in_sizes, int n_in,
                              void* d_out, int out_size) {
    const float* enc = (const float*)d_in[0];
    const int* masks = (const int*)d_in[1];
    const float* h1i = (const float*)d_in[2];
    const float* c1i = (const float*)d_in[3];
    const float* h2i = (const float*)d_in[4];
    const float* c2i = (const float*)d_in[5];
    const float* cap = (const float*)d_in[6];
    const float* W_ih1 = (const float*)d_in[7];
    const float* W_hh1 = (const float*)d_in[8];
    const float* b_ih1 = (const float*)d_in[9];
    const float* b_hh1 = (const float*)d_in[10];
    const float* W_ih2 = (const float*)d_in[11];
    const float* W_hh2 = (const float*)d_in[12];
    const float* b_ih2 = (const float*)d_in[13];
    const float* b_hh2 = (const float*)d_in[14];
    const float* W_att = (const float*)d_in[15];
    const float* b_att = (const float*)d_in[16];
    const float* W_comb = (const float*)d_in[17];
    const float* b_comb = (const float*)d_in[18];
    float* outs = (float*)d_out;

    bf16 *pWih1, *pWhh1, *pWih2A, *pWih2B, *pWhh2, *pWcmA, *pWcmB, *pWatt;
    bf16 *pEnchl, *pCapshl;
    float *pEncproj, *pPre, *pBg1;
    cudaGetSymbolAddress((void**)&pWih1, g_Wih1);
    cudaGetSymbolAddress((void**)&pWhh1, g_Whh1);
    cudaGetSymbolAddress((void**)&pWih2A, g_Wih2A);
    cudaGetSymbolAddress((void**)&pWih2B, g_Wih2B);
    cudaGetSymbolAddress((void**)&pWhh2, g_Whh2);
    cudaGetSymbolAddress((void**)&pWcmA, g_WcmA);
    cudaGetSymbolAddress((void**)&pWcmB, g_WcmB);
    cudaGetSymbolAddress((void**)&pWatt, g_Watt);
    cudaGetSymbolAddress((void**)&pEnchl, g_enchl);
    cudaGetSymbolAddress((void**)&pCapshl, g_capshl);
    cudaGetSymbolAddress((void**)&pEncproj, g_encproj);
    cudaGetSymbolAddress((void**)&pPre, g_pregates);
    cudaGetSymbolAddress((void**)&pBg1, g_bg1);

    const int SMEM = NSTG * STGB;
    cudaFuncSetAttribute(mma_pro, cudaFuncAttributeMaxDynamicSharedMemorySize, SMEM);
    cudaFuncSetAttribute(decoder_loop, cudaFuncAttributeMaxDynamicSharedMemorySize, SMEM);

    auto cgrid = [](int n) { return (n + 255) / 256; };
    conv_whl<<<cgrid(4096 * 512), 256>>>(W_ih1, 512, 0, 512, pWih1, 1, 4096);
    conv_whl<<<cgrid(4096 * 1024), 256>>>(W_hh1, 1024, 0, 1024, pWhh1, 1, 4096);
    conv_whl<<<cgrid(4096 * 1024), 256>>>(W_ih2, 2048, 0, 1024, pWih2A, 1, 4096);
    conv_whl<<<cgrid(4096 * 1024), 256>>>(W_ih2, 2048, 1024, 1024, pWih2B, 1, 4096);
    conv_whl<<<cgrid(4096 * 1024), 256>>>(W_hh2, 1024, 0, 1024, pWhh2, 1, 4096);
    conv_whl<<<cgrid(1024 * 1024), 256>>>(W_comb, 2048, 0, 1024, pWcmA, 0, 1024);
    conv_whl<<<cgrid(1024 * 1024), 256>>>(W_comb, 2048, 1024, 1024, pWcmB, 0, 1024);
    conv_whl<<<cgrid(1024 * 1024), 256>>>(W_att, 1024, 0, 1024, pWatt, 0, 1024);
    conv_whl<<<cgrid(8192 * 1024), 256>>>(enc, 1024, 0, 1024, pEnchl, 0, 8192);
    conv_whl<<<cgrid(3072 * 512), 256>>>(cap, 512, 0, 512, pCapshl, 0, 3072);
    conv_bias<<<16, 256>>>(b_ih1, b_hh1, b_ih2, b_hh2);
    init_k<<<(BBATCH * HDIM + 255) / 256, 256>>>(h1i, c1i, h2i, c2i);

    // pregates = captions_all @ Wih1^T + bg1
    mma_pro<<<dim3(128, 48), 256, SMEM>>>(pCapshl, pWih1, 512, pBg1, pPre, 4096);
    // enc_proj = enc @ W_att^T + b_att
    mma_pro<<<dim3(32, 128), 256, SMEM>>>(pEnchl, pWatt, 1024, b_att, pEncproj, 1024);

    // the whole 48-step loop in one persistent kernel
    decoder_loop<<<NCTA, 256, SMEM>>>(masks, enc, b_comb, outs);
}

// round 7
// speedup vs baseline: 1.2764x; 1.0443x over previous
#include <cuda_runtime.h>
#include <cuda_bf16.h>
#include <math.h>
#include <stdint.h>

#define BBATCH 64
#define LLEN 128
#define TSTEPS 48
#define EDIM 512
#define HEDIM 1024
#define HDIM 1024
#define NCTA 148

typedef __nv_bfloat16 bf16;

// ---------------- device scratch ----------------
__device__ bf16 g_Wih1[4096 * 1024];
__device__ bf16 g_Whh1[4096 * 2048];
__device__ bf16 g_Wih2A[4096 * 2048];
__device__ bf16 g_Wih2B[4096 * 2048];
__device__ bf16 g_Whh2[4096 * 2048];
__device__ bf16 g_WcmA[1024 * 2048];
__device__ bf16 g_WcmB[1024 * 2048];
__device__ bf16 g_Watt[1024 * 2048];
__device__ bf16 g_enchl[8192 * 2048];
__device__ bf16 g_capshl[3072 * 1024];
__device__ float g_encproj[8192 * 1024];
__device__ float g_pregates[3072 * 4096];
__device__ bf16 g_h1hl[2][BBATCH * 2048];
__device__ bf16 g_h2hl[2][BBATCH * 2048];
__device__ bf16 g_ohl[BBATCH * 2048];
__device__ bf16 g_athl[BBATCH * 2048];
__device__ float g_c1[BBATCH * HDIM];
__device__ float g_c2[BBATCH * HDIM];
__device__ float g_h2f[BBATCH * HDIM];
__device__ float g_bg1[4096];
__device__ float g_bg2[4096];

// grid barrier state (zero-initialized; cnt self-resets, gen monotonic)
__device__ unsigned g_cnt[256];
__device__ unsigned g_gen[256];

__device__ __forceinline__ float sigm(float x) { return 1.f / (1.f + __expf(-x)); }

#define CP16(dst, src) \
    asm volatile("cp.async.cg.shared.global [%0], [%1], 16;\n" ::"r"(dst), "l"(src))
#define LDSM4(R0, R1, R2, R3, ADDR)                                        \
    asm volatile("ldmatrix.sync.aligned.m8n8.x4.shared.b16 {%0,%1,%2,%3},[%4];\n" \
                 : "=r"(R0), "=r"(R1), "=r"(R2), "=r"(R3)                  \
                 : "r"(ADDR))
#define MMA16816(C, A0, A1, A2, A3, B0, B1)                                    \
    asm volatile(                                                               \
        "mma.sync.aligned.m16n8k16.row.col.f32.bf16.bf16.f32 "                  \
        "{%0,%1,%2,%3},{%4,%5,%6,%7},{%8,%9},{%0,%1,%2,%3};\n"                  \
        : "+f"((C)[0]), "+f"((C)[1]), "+f"((C)[2]), "+f"((C)[3])                \
        : "r"(A0), "r"(A1), "r"(A2), "r"(A3), "r"(B0), "r"(B1))

// ---------------- fused prologue conversions (one launch) ----------------
__device__ __forceinline__ void conv_job(const float* __restrict__ src, int srcld,
                                         int colOff, int K, bf16* __restrict__ dst,
                                         int interleave, int N, int lb) {
    int idx = lb * 256 + threadIdx.x;
    if (idx >= N * K) return;
    int n = idx / K, k = idx - n * K;
    int srcn = interleave ? ((n & 3) * HDIM + (n >> 2)) : n;
    float v = src[(size_t)srcn * srcld + colOff + k];
    bf16 hi = __float2bfloat16(v);
    bf16 lo = __float2bfloat16(v - __bfloat162float(hi));
    dst[(size_t)n * 2 * K + k] = hi;
    dst[(size_t)n * 2 * K + K + k] = lo;
}

#define CONV_BLOCKS 125200

__global__ void conv_all(const float* __restrict__ enc, const float* __restrict__ cap,
                         const float* __restrict__ Wih1, const float* __restrict__ Whh1,
                         const float* __restrict__ Wih2, const float* __restrict__ Whh2,
                         const float* __restrict__ Wcomb, const float* __restrict__ Watt,
                         const float* __restrict__ bi1, const float* __restrict__ bh1,
                         const float* __restrict__ bi2, const float* __restrict__ bh2,
                         const float* __restrict__ h1i, const float* __restrict__ c1i,
                         const float* __restrict__ h2i, const float* __restrict__ c2i) {
    int b = blockIdx.x;
    if (b < 8192)        conv_job(Wih1, 512, 0, 512, g_Wih1, 1, 4096, b);
    else if (b < 24576)  conv_job(Whh1, 1024, 0, 1024, g_Whh1, 1, 4096, b - 8192);
    else if (b < 40960)  conv_job(Wih2, 2048, 0, 1024, g_Wih2A, 1, 4096, b - 24576);
    else if (b < 57344)  conv_job(Wih2, 2048, 1024, 1024, g_Wih2B, 1, 4096, b - 40960);
    else if (b < 73728)  conv_job(Whh2, 1024, 0, 1024, g_Whh2, 1, 4096, b - 57344);
    else if (b < 77824)  conv_job(Wcomb, 2048, 0, 1024, g_WcmA, 0, 1024, b - 73728);
    else if (b < 81920)  conv_job(Wcomb, 2048, 1024, 1024, g_WcmB, 0, 1024, b - 77824);
    else if (b < 86016)  conv_job(Watt, 1024, 0, 1024, g_Watt, 0, 1024, b - 81920);
    else if (b < 118784) conv_job(enc, 1024, 0, 1024, g_enchl, 0, 8192, b - 86016);
    else if (b < 124928) conv_job(cap, 512, 0, 512, g_capshl, 0, 3072, b - 118784);
    else if (b < 124944) {
        int n = (b - 124928) * 256 + threadIdx.x;
        if (n < 4096) {
            int srcn = (n & 3) * HDIM + (n >> 2);
            g_bg1[n] = bi1[srcn] + bh1[srcn];
            g_bg2[n] = bi2[srcn] + bh2[srcn];
        }
    } else {
        int i = (b - 124944) * 256 + threadIdx.x;
        if (i < BBATCH * HDIM) {
            int bb = i >> 10, k = i & 1023;
            g_c1[i] = c1i[i];
            g_c2[i] = c2i[i];
            g_h2f[i] = h2i[i];
            float v1 = h1i[i];
            bf16 h = __float2bfloat16(v1);
            bf16 l = __float2bfloat16(v1 - __bfloat162float(h));
            g_h1hl[0][bb * 2048 + k] = h;
            g_h1hl[0][bb * 2048 + 1024 + k] = l;
            float v2 = h2i[i];
            h = __float2bfloat16(v2);
            l = __float2bfloat16(v2 - __bfloat162float(h));
            g_h2hl[0][bb * 2048 + k] = h;
            g_h2hl[0][bb * 2048 + 1024 + k] = l;
            bf16 z = __float2bfloat16(0.f);
            g_ohl[bb * 2048 + k] = z;
            g_ohl[bb * 2048 + 1024 + k] = z;
        }
    }
}

// ---------------- GEMM mainloop ----------------
#define STGB 24576
#define NSTG 4

__device__ __forceinline__ void gemm_main(
    char* smem, int m0, int n0,
    const bf16* A0, const bf16* W0, int K0,
    const bf16* A1, const bf16* W1, int K1,
    const bf16* A2, const bf16* W2, int K2,
    int npairs, float acc[4][4]) {
    const int tid = threadIdx.x;
    const int w = tid >> 5;
    const int l = tid & 31;
    const int wg = w >> 2;
    const int wm = w & 3;

    const bf16* Ab[3] = {A0, A1, A2};
    const bf16* Wb[3] = {W0, W1, W2};
    const int Kp[3] = {K0, K1, K2};

    int NCH = 0;
    for (int p = 0; p < npairs; ++p) NCH += Kp[p] >> 6;

    const uint32_t sB = (uint32_t)__cvta_generic_to_shared(smem);

    int cp = 0, ckt = 0;
    auto issue = [&](int stg) {
        const bf16* A = Ab[cp];
        const bf16* W = Wb[cp];
        const int K = Kp[cp];
        const int ld = K << 1;
        const uint32_t base = sB + stg * STGB;
#pragma unroll
        for (int i = 0; i < 6; ++i) {
            int c = tid + (i << 8);
            if (c < 512) {
                int row = c >> 3, ch = c & 7;
                const bf16* src = A + (size_t)(m0 + row) * ld + ckt + (ch << 3);
                CP16(base + row * 128 + ((ch ^ (row & 7)) << 4), src);
            } else if (c < 1024) {
                int c2 = c - 512;
                int row = c2 >> 3, ch = c2 & 7;
                const bf16* src = A + (size_t)(m0 + row) * ld + K + ckt + (ch << 3);
                CP16(base + 8192 + row * 128 + ((ch ^ (row & 7)) << 4), src);
            } else if (c < 1280) {
                int c2 = c - 1024;
                int row = c2 >> 3, ch = c2 & 7;
                const bf16* src = W + (size_t)(n0 + row) * ld + ckt + (ch << 3);
                CP16(base + 16384 + row * 128 + ((ch ^ (row & 7)) << 4), src);
            } else {
                int c2 = c - 1280;
                int row = c2 >> 3, ch = c2 & 7;
                const bf16* src = W + (size_t)(n0 + row) * ld + K + ckt + (ch << 3);
                CP16(base + 20480 + row * 128 + ((ch ^ (row & 7)) << 4), src);
            }
        }
        asm volatile("cp.async.commit_group;\n" ::);
        ckt += 64;
        if (ckt >= K) { ckt = 0; ++cp; }
    };

#pragma unroll
    for (int j = 0; j < 4; ++j)
#pragma unroll
        for (int i = 0; i < 4; ++i) acc[j][i] = 0.f;

    const int npre = (NCH < NSTG - 1) ? NCH : (NSTG - 1);
    for (int i = 0; i < npre; ++i) issue(i);

    const int arow = 16 * wm + (l & 15);
    const int asel = (l >> 4) & 1;
    const int nrow0 = (l & 7) + ((l & 16) >> 1);
    const int nrow1 = nrow0 + 16;
    const int bsel = (l >> 3) & 1;

    for (int it = 0; it < NCH; ++it) {
        const int pend = ((NCH < it + NSTG - 1) ? NCH : (it + NSTG - 1)) - (it + 1);
        if (pend >= 2)      asm volatile("cp.async.wait_group 2;\n" ::);
        else if (pend == 1) asm volatile("cp.async.wait_group 1;\n" ::);
        else                asm volatile("cp.async.wait_group 0;\n" ::);
        __syncthreads();
        if (it + NSTG - 1 < NCH) issue((it + NSTG - 1) & (NSTG - 1));

        const uint32_t aHi = sB + (it & (NSTG - 1)) * STGB;
        const uint32_t aLo = aHi + 8192;
        const uint32_t wHi = aHi + 16384;
        const uint32_t wLo = aHi + 20480;
#pragma unroll
        for (int kh2 = 0; kh2 < 2; ++kh2) {
            const int kh = 2 * wg + kh2;
            const int ac = 2 * kh + asel;
            const int bc = 2 * kh + bsel;
            const uint32_t aoff = arow * 128 + ((ac ^ (arow & 7)) << 4);
            const uint32_t boff0 = nrow0 * 128 + ((bc ^ (nrow0 & 7)) << 4);
            const uint32_t boff1 = nrow1 * 128 + ((bc ^ (nrow1 & 7)) << 4);
            uint32_t ah0, ah1, ah2, ah3, al0, al1, al2, al3;
            LDSM4(ah0, ah1, ah2, ah3, aHi + aoff);
            LDSM4(al0, al1, al2, al3, aLo + aoff);
            uint32_t bh0, bh1, bh2, bh3, bh4, bh5, bh6, bh7;
            LDSM4(bh0, bh1, bh2, bh3, wHi + boff0);
            LDSM4(bh4, bh5, bh6, bh7, wHi + boff1);
            uint32_t bl0, bl1, bl2, bl3, bl4, bl5, bl6, bl7;
            LDSM4(bl0, bl1, bl2, bl3, wLo + boff0);
            LDSM4(bl4, bl5, bl6, bl7, wLo + boff1);
            MMA16816(acc[0], ah0, ah1, ah2, ah3, bh0, bh1);
            MMA16816(acc[1], ah0, ah1, ah2, ah3, bh2, bh3);
            MMA16816(acc[2], ah0, ah1, ah2, ah3, bh4, bh5);
            MMA16816(acc[3], ah0, ah1, ah2, ah3, bh6, bh7);
            MMA16816(acc[0], ah0, ah1, ah2, ah3, bl0, bl1);
            MMA16816(acc[1], ah0, ah1, ah2, ah3, bl2, bl3);
            MMA16816(acc[2], ah0, ah1, ah2, ah3, bl4, bl5);
            MMA16816(acc[3], ah0, ah1, ah2, ah3, bl6, bl7);
            MMA16816(acc[0], al0, al1, al2, al3, bh0, bh1);
            MMA16816(acc[1], al0, al1, al2, al3, bh2, bh3);
            MMA16816(acc[2], al0, al1, al2, al3, bh4, bh5);
            MMA16816(acc[3], al0, al1, al2, al3, bh6, bh7);
        }
    }
    __syncthreads();

    // cross-warpgroup reduction (wg1 -> wg0)
    {
        float* red = (float*)(smem + STGB);
        const int rbase = ((wm * 32 + l) << 4);
        if (wg == 1) {
#pragma unroll
            for (int j = 0; j < 4; ++j)
#pragma unroll
                for (int i = 0; i < 4; ++i) red[rbase + j * 4 + i] = acc[j][i];
        }
        __syncthreads();
        if (wg == 0) {
#pragma unroll
            for (int j = 0; j < 4; ++j)
#pragma unroll
                for (int i = 0; i < 4; ++i) acc[j][i] += red[rbase + j * 4 + i];
        }
    }
}

// ---------------- epilogues ----------------
__device__ __forceinline__ void epi_store(char* smem, int m0, int n0, float acc[4][4],
                                          const float* biasV, float* outF, int ldo) {
    const int tid = threadIdx.x;
    const int w = tid >> 5, l = tid & 31;
    const int wg = w >> 2, wm = w & 3;
    const int r = l >> 2, c2 = (l & 3) * 2;
    if (wg != 0) return;
#pragma unroll
    for (int j = 0; j < 4; ++j) {
        int n = n0 + 8 * j + c2;
        float bv0 = biasV[n], bv1 = biasV[n + 1];
        size_t row0 = (size_t)(m0 + 16 * wm + r);
        outF[row0 * ldo + n] = acc[j][0] + bv0;
        outF[row0 * ldo + n + 1] = acc[j][1] + bv1;
        outF[(row0 + 8) * ldo + n] = acc[j][2] + bv0;
        outF[(row0 + 8) * ldo + n + 1] = acc[j][3] + bv1;
    }
}

__device__ __forceinline__ void epi_lstm(char* smem, int n0, float acc[4][4],
                                         const float* biasV, const float* biasM,
                                         bf16* outHL, float* outF, float* cstate) {
    const int tid = threadIdx.x;
    const int w = tid >> 5, l = tid & 31;
    const int wg = w >> 2, wm = w & 3;
    const int r = l >> 2, c2 = (l & 3) * 2;
    float* Csm = (float*)smem;
    if (wg == 0) {
#pragma unroll
        for (int j = 0; j < 4; ++j) {
            int col = 8 * j + c2;
            int n = n0 + col;
#pragma unroll
            for (int hh = 0; hh < 2; ++hh) {
                int m = 16 * wm + r + hh * 8;
                float b0 = biasM ? biasM[(size_t)m * 4096 + n] : biasV[n];
                float b1 = biasM ? biasM[(size_t)m * 4096 + n + 1] : biasV[n + 1];
                Csm[m * 33 + col] = acc[j][2 * hh] + b0;
                Csm[m * 33 + col + 1] = acc[j][2 * hh + 1] + b1;
            }
        }
    }
    __syncthreads();
    if (tid < 128) {
#pragma unroll
        for (int q = 0; q < 4; ++q) {
            int item = tid * 4 + q;
            int b = item >> 3;
            int hu = item & 7;
            float gi = Csm[b * 33 + hu * 4 + 0];
            float gf = Csm[b * 33 + hu * 4 + 1];
            float gg = Csm[b * 33 + hu * 4 + 2];
            float go = Csm[b * 33 + hu * 4 + 3];
            int hg = (n0 >> 2) + hu;
            int idx = b * HDIM + hg;
            float cold = cstate[idx];
            float i_ = sigm(gi), f_ = sigm(gf), g_ = tanhf(gg), o_ = sigm(go);
            float cn = f_ * cold + i_ * g_;
            cstate[idx] = cn;
            float hv = o_ * tanhf(cn);
            if (outF) outF[idx] = hv;
            bf16 hi = __float2bfloat16(hv);
            bf16 lo = __float2bfloat16(hv - __bfloat162float(hi));
            outHL[b * 2048 + hg] = hi;
            outHL[b * 2048 + 1024 + hg] = lo;
        }
    }
    __syncthreads();
}

__device__ __forceinline__ void epi_tanh(int n0, float acc[4][4], const float* biasV,
                                         float* outF, int ldo, bf16* outHL) {
    const int tid = threadIdx.x;
    const int w = tid >> 5, l = tid & 31;
    const int wg = w >> 2, wm = w & 3;
    const int r = l >> 2, c2 = (l & 3) * 2;
    if (wg != 0) return;
#pragma unroll
    for (int j = 0; j < 4; ++j) {
        int n = n0 + 8 * j + c2;
        float bv0 = biasV[n], bv1 = biasV[n + 1];
        int b0r = 16 * wm + r;
#pragma unroll
        for (int hh = 0; hh < 2; ++hh) {
            int bb = b0r + hh * 8;
            float v0 = tanhf(acc[j][2 * hh] + bv0);
            float v1 = tanhf(acc[j][2 * hh + 1] + bv1);
            outF[(size_t)bb * ldo + n] = v0;
            outF[(size_t)bb * ldo + n + 1] = v1;
            bf16 h0 = __float2bfloat16(v0);
            bf16 l0 = __float2bfloat16(v0 - __bfloat162float(h0));
            bf16 h1 = __float2bfloat16(v1);
            bf16 l1 = __float2bfloat16(v1 - __bfloat162float(h1));
            outHL[bb * 2048 + n] = h0;
            outHL[bb * 2048 + 1024 + n] = l0;
            outHL[bb * 2048 + n + 1] = h1;
            outHL[bb * 2048 + 1024 + n + 1] = l1;
        }
    }
}

// ---------------- attention (per-b, one CTA) ----------------
__device__ __forceinline__ void attn_dev(char* smem, int b,
                                         const int* __restrict__ masks,
                                         const float* __restrict__ encproj,
                                         const float* __restrict__ enc,
                                         const float* __restrict__ h2f,
                                         bf16* __restrict__ athl) {
    float* sh2 = (float*)smem;
    float* sred = sh2 + HDIM;
    float* salpha = sred + LLEN;
    float* stmp = salpha + LLEN;
    const int tid = threadIdx.x;
    const int w = tid >> 5, l = tid & 31;

    {
        const float4* src = (const float4*)(h2f + b * HDIM);
        ((float4*)sh2)[tid] = __ldcg(src + tid);
    }
    __syncthreads();

    const float4* sh4 = (const float4*)sh2;
    for (int li = 0; li < 8; ++li) {
        int ll = w * 16 + li * 2;
        const float4* e0 = (const float4*)(encproj + ((size_t)(b * LLEN + ll)) * HDIM);
        const float4* e1 = (const float4*)(encproj + ((size_t)(b * LLEN + ll + 1)) * HDIM);
        float s0 = 0.f, s1 = 0.f;
#pragma unroll
        for (int j = 0; j < 8; ++j) {
            float4 hv = sh4[l + 32 * j];
            float4 v0 = e0[l + 32 * j];
            float4 v1 = e1[l + 32 * j];
            s0 += hv.x * v0.x + hv.y * v0.y + hv.z * v0.z + hv.w * v0.w;
            s1 += hv.x * v1.x + hv.y * v1.y + hv.z * v1.z + hv.w * v1.w;
        }
#pragma unroll
        for (int o = 16; o; o >>= 1) {
            s0 += __shfl_xor_sync(0xffffffffu, s0, o);
            s1 += __shfl_xor_sync(0xffffffffu, s1, o);
        }
        if (l == 0) {
            sred[ll] = masks[b * LLEN + ll] ? -1e30f : s0;
            sred[ll + 1] = masks[b * LLEN + ll + 1] ? -1e30f : s1;
        }
    }
    __syncthreads();

    if (tid < 128) stmp[tid] = sred[tid];
    __syncthreads();
    for (int s = 64; s; s >>= 1) {
        if (tid < s) stmp[tid] = fmaxf(stmp[tid], stmp[tid + s]);
        __syncthreads();
    }
    const float mx = stmp[0];
    __syncthreads();
    if (tid < 128) {
        float p = __expf(sred[tid] - mx);
        salpha[tid] = p;
        stmp[tid] = p;
    }
    __syncthreads();
    for (int s = 64; s; s >>= 1) {
        if (tid < s) stmp[tid] += stmp[tid + s];
        __syncthreads();
    }
    const float inv = 1.f / stmp[0];
    __syncthreads();
    if (tid < 128) salpha[tid] *= inv;
    __syncthreads();

    float4 p[8];
#pragma unroll
    for (int u = 0; u < 8; ++u) p[u] = make_float4(0.f, 0.f, 0.f, 0.f);
    const float4* ep4 = (const float4*)(enc + (size_t)b * LLEN * HEDIM);
    for (int l0 = 0; l0 < LLEN; l0 += 8) {
#pragma unroll
        for (int u = 0; u < 8; ++u) {
            float al = salpha[l0 + u];
            float4 v = ep4[(l0 + u) * 256 + tid];
            p[u].x += al * v.x;
            p[u].y += al * v.y;
            p[u].z += al * v.z;
            p[u].w += al * v.w;
        }
    }
#pragma unroll
    for (int u = 1; u < 8; ++u) {
        p[0].x += p[u].x; p[0].y += p[u].y; p[0].z += p[u].z; p[0].w += p[u].w;
    }
    int f = tid * 4;
    float vals[4] = {p[0].x, p[0].y, p[0].z, p[0].w};
#pragma unroll
    for (int i = 0; i < 4; ++i) {
        bf16 hi = __float2bfloat16(vals[i]);
        bf16 lo = __float2bfloat16(vals[i] - __bfloat162float(hi));
        athl[b * 2048 + f + i] = hi;
        athl[b * 2048 + 1024 + f + i] = lo;
    }
    __syncthreads();
}

// ---------------- grid barrier (replay-safe) ----------------
__device__ __forceinline__ void gsync(int slot) {
    __threadfence();
    __syncthreads();
    if (threadIdx.x == 0) {
        unsigned g = ((volatile unsigned*)g_gen)[slot];
        unsigned old = atomicAdd(&g_cnt[slot], 1u);
        if (old == NCTA - 1) {
            g_cnt[slot] = 0;
            __threadfence();
            atomicExch(&g_gen[slot], g + 1);
        } else {
            while (((volatile unsigned*)g_gen)[slot] == g) __nanosleep(64);
        }
    }
    __syncthreads();
    __threadfence();
}

// ---------------- prologue GEMM (fp32 store) ----------------
__global__ __launch_bounds__(256) void mma_pro(
    const bf16* A0, const bf16* W0, int K0,
    const float* __restrict__ biasV, float* __restrict__ outF, int ldo) {
    extern __shared__ __align__(16) char smem[];
    float acc[4][4];
    gemm_main(smem, blockIdx.y * 64, blockIdx.x * 32,
              A0, W0, K0, nullptr, nullptr, 0, nullptr, nullptr, 0, 1, acc);
    epi_store(smem, blockIdx.y * 64, blockIdx.x * 32, acc, biasV, outF, ldo);
}

// ---------------- LSTM1 tile helper (step tp, tile 0..127) ----------------
__device__ __forceinline__ void lstm1_tile(char* smem, int tp, int tile) {
    float acc[4][4];
    int n0 = tile * 32;
    gemm_main(smem, 0, n0, g_h1hl[tp & 1], g_Whh1, 1024,
              nullptr, nullptr, 0, nullptr, nullptr, 0, 1, acc);
    epi_lstm(smem, n0, acc, nullptr,
             g_pregates + (size_t)tp * BBATCH * 4096,
             g_h1hl[(tp & 1) ^ 1], nullptr, g_c1);
}

// ---------------- persistent decoder loop ----------------
__global__ __launch_bounds__(256, 1) void decoder_loop(
    const int* __restrict__ masks, const float* __restrict__ enc,
    const float* __restrict__ b_comb, float* __restrict__ outs) {
    extern __shared__ __align__(16) char smem[];
    const int bid = blockIdx.x;
    float acc[4][4];

    // phase 0: LSTM1 @ t=0  (reads h1hl[0], writes h1hl[1])
    if (bid < 128) lstm1_tile(smem, 0, bid);
    gsync(0);

    for (int t = 0; t < TSTEPS; ++t) {
        const int cur = t & 1;
        // PHASE A: LSTM2@t (bid<128) || LSTM1@t+1 tiles 0..19 (bid 128..147)
        if (bid < 128) {
            int n0 = bid * 32;
            gemm_main(smem, 0, n0, g_h1hl[cur ^ 1], g_Wih2A, 1024,
                      g_ohl, g_Wih2B, 1024, g_h2hl[cur], g_Whh2, 1024, 3, acc);
            epi_lstm(smem, n0, acc, g_bg2, nullptr, g_h2hl[cur ^ 1], g_h2f, g_c2);
        } else if (t + 1 < TSTEPS) {
            lstm1_tile(smem, t + 1, bid - 128);   // tiles 0..19
        }
        gsync(1 + t * 3);

        // PHASE B: attention@t (bid<64) || LSTM1@t+1 tiles 20..103 (bid 64..147)
        if (bid < 64) {
            attn_dev(smem, bid, masks, g_encproj, enc, g_h2f, g_athl);
        } else if (t + 1 < TSTEPS) {
            lstm1_tile(smem, t + 1, 20 + (bid - 64));  // tiles 20..103
        }
        gsync(2 + t * 3);

        // PHASE C: comb@t (bid 116..147) || LSTM1@t+1 tiles 104..127 (bid<24)
        if (bid >= 116) {
            int n0 = (bid - 116) * 32;
            gemm_main(smem, 0, n0, g_athl, g_WcmA, 1024,
                      g_h2hl[cur ^ 1], g_WcmB, 1024, nullptr, nullptr, 0, 2, acc);
            epi_tanh(n0, acc, b_comb, outs + (size_t)t * BBATCH * HDIM, 1024, g_ohl);
        } else if (bid < 24 && t + 1 < TSTEPS) {
            lstm1_tile(smem, t + 1, 104 + bid);   // tiles 104..127
        }
        gsync(3 + t * 3);
    }
}

// ---------------- host launcher ----------------
extern "C" void kernel_launch(void* const* d_in, const int* in_sizes, int n_in,
                              void* d_out, int out_size) {
    const float* enc = (const float*)d_in[0];
    const int* masks = (const int*)d_in[1];
    const float* h1i = (const float*)d_in[2];
    const float* c1i = (const float*)d_in[3];
    const float* h2i = (const float*)d_in[4];
    const float* c2i = (const float*)d_in[5];
    const float* cap = (const float*)d_in[6];
    const float* W_ih1 = (const float*)d_in[7];
    const float* W_hh1 = (const float*)d_in[8];
    const float* b_ih1 = (const float*)d_in[9];
    const float* b_hh1 = (const float*)d_in[10];
    const float* W_ih2 = (const float*)d_in[11];
    const float* W_hh2 = (const float*)d_in[12];
    const float* b_ih2 = (const float*)d_in[13];
    const float* b_hh2 = (const float*)d_in[14];
    const float* W_att = (const float*)d_in[15];
    const float* b_att = (const float*)d_in[16];
    const float* W_comb = (const float*)d_in[17];
    const float* b_comb = (const float*)d_in[18];
    float* outs = (float*)d_out;

    bf16 *pWih1, *pWatt, *pEnchl, *pCapshl;
    float *pEncproj, *pPre, *pBg1;
    cudaGetSymbolAddress((void**)&pWih1, g_Wih1);
    cudaGetSymbolAddress((void**)&pWatt, g_Watt);
    cudaGetSymbolAddress((void**)&pEnchl, g_enchl);
    cudaGetSymbolAddress((void**)&pCapshl, g_capshl);
    cudaGetSymbolAddress((void**)&pEncproj, g_encproj);
    cudaGetSymbolAddress((void**)&pPre, g_pregates);
    cudaGetSymbolAddress((void**)&pBg1, g_bg1);

    const int SMEM = NSTG * STGB;
    cudaFuncSetAttribute(mma_pro, cudaFuncAttributeMaxDynamicSharedMemorySize, SMEM);
    cudaFuncSetAttribute(decoder_loop, cudaFuncAttributeMaxDynamicSharedMemorySize, SMEM);

    // fused prologue: all conversions + bias + state init in ONE launch
    conv_all<<<CONV_BLOCKS, 256>>>(enc, cap, W_ih1, W_hh1, W_ih2, W_hh2, W_comb, W_att,
                                   b_ih1, b_hh1, b_ih2, b_hh2, h1i, c1i, h2i, c2i);

    // pregates = captions_all @ Wih1^T + bg1
    mma_pro<<<dim3(128, 48), 256, SMEM>>>(pCapshl, pWih1, 512, pBg1, pPre, 4096);
    // enc_proj = enc @ W_att^T + b_att
    mma_pro<<<dim3(32, 128), 256, SMEM>>>(pEnchl, pWatt, 1024, b_att, pEncproj, 1024);

    // the whole 48-step loop in one persistent kernel
    decoder_loop<<<NCTA, 256, SMEM>>>(masks, enc, b_comb, outs);
}

// round 8
// speedup vs baseline: 1.3629x; 1.0678x over previous
#include <cuda_runtime.h>
#include <cuda_bf16.h>
#include <math.h>
#include <stdint.h>

#define BBATCH 64
#define LLEN 128
#define TSTEPS 48
#define EDIM 512
#define HEDIM 1024
#define HDIM 1024
#define NCTA 148

typedef __nv_bfloat16 bf16;

// ---------------- device scratch ----------------
__device__ bf16 g_Wih1[4096 * 1024];
__device__ bf16 g_Whh1[4096 * 2048];
__device__ bf16 g_Wih2A[4096 * 2048];
__device__ bf16 g_Wih2B[4096 * 2048];
__device__ bf16 g_Whh2[4096 * 2048];
__device__ bf16 g_WcmA[1024 * 2048];
__device__ bf16 g_WcmB[1024 * 2048];
__device__ bf16 g_Watt[1024 * 2048];
__device__ bf16 g_enchl[8192 * 2048];
__device__ bf16 g_capshl[3072 * 1024];
__device__ float g_encproj[8192 * 1024];
__device__ float g_pregates[3072 * 4096];
__device__ float g_gpart[BBATCH * 4096];     // LSTM2 partial gates (incl bg2)
__device__ bf16 g_h1hl[2][BBATCH * 2048];
__device__ bf16 g_h2hl[2][BBATCH * 2048];
__device__ bf16 g_ohl[BBATCH * 2048];
__device__ bf16 g_athl[BBATCH * 2048];
__device__ float g_c1[BBATCH * HDIM];
__device__ float g_c2[BBATCH * HDIM];
__device__ float g_h2f[BBATCH * HDIM];
__device__ float g_bg1[4096];
__device__ float g_bg2[4096];

// grid barrier state
__device__ unsigned g_cnt[256];
__device__ unsigned g_gen[256];

__device__ __forceinline__ float sigm(float x) { return 1.f / (1.f + __expf(-x)); }

#define CP16(dst, src) \
    asm volatile("cp.async.cg.shared.global [%0], [%1], 16;\n" ::"r"(dst), "l"(src))
#define LDSM4(R0, R1, R2, R3, ADDR)                                        \
    asm volatile("ldmatrix.sync.aligned.m8n8.x4.shared.b16 {%0,%1,%2,%3},[%4];\n" \
                 : "=r"(R0), "=r"(R1), "=r"(R2), "=r"(R3)                  \
                 : "r"(ADDR))
#define MMA16816(C, A0, A1, A2, A3, B0, B1)                                    \
    asm volatile(                                                               \
        "mma.sync.aligned.m16n8k16.row.col.f32.bf16.bf16.f32 "                  \
        "{%0,%1,%2,%3},{%4,%5,%6,%7},{%8,%9},{%0,%1,%2,%3};\n"                  \
        : "+f"((C)[0]), "+f"((C)[1]), "+f"((C)[2]), "+f"((C)[3])                \
        : "r"(A0), "r"(A1), "r"(A2), "r"(A3), "r"(B0), "r"(B1))

// ---------------- fused prologue conversions ----------------
__device__ __forceinline__ void conv_job(const float* __restrict__ src, int srcld,
                                         int colOff, int K, bf16* __restrict__ dst,
                                         int interleave, int N, int lb) {
    int idx = lb * 256 + threadIdx.x;
    if (idx >= N * K) return;
    int n = idx / K, k = idx - n * K;
    int srcn = interleave ? ((n & 3) * HDIM + (n >> 2)) : n;
    float v = src[(size_t)srcn * srcld + colOff + k];
    bf16 hi = __float2bfloat16(v);
    bf16 lo = __float2bfloat16(v - __bfloat162float(hi));
    dst[(size_t)n * 2 * K + k] = hi;
    dst[(size_t)n * 2 * K + K + k] = lo;
}

#define CONV_BLOCKS 125200

__global__ void conv_all(const float* __restrict__ enc, const float* __restrict__ cap,
                         const float* __restrict__ Wih1, const float* __restrict__ Whh1,
                         const float* __restrict__ Wih2, const float* __restrict__ Whh2,
                         const float* __restrict__ Wcomb, const float* __restrict__ Watt,
                         const float* __restrict__ bi1, const float* __restrict__ bh1,
                         const float* __restrict__ bi2, const float* __restrict__ bh2,
                         const float* __restrict__ h1i, const float* __restrict__ c1i,
                         const float* __restrict__ h2i, const float* __restrict__ c2i) {
    int b = blockIdx.x;
    if (b < 8192)        conv_job(Wih1, 512, 0, 512, g_Wih1, 1, 4096, b);
    else if (b < 24576)  conv_job(Whh1, 1024, 0, 1024, g_Whh1, 1, 4096, b - 8192);
    else if (b < 40960)  conv_job(Wih2, 2048, 0, 1024, g_Wih2A, 1, 4096, b - 24576);
    else if (b < 57344)  conv_job(Wih2, 2048, 1024, 1024, g_Wih2B, 1, 4096, b - 40960);
    else if (b < 73728)  conv_job(Whh2, 1024, 0, 1024, g_Whh2, 1, 4096, b - 57344);
    else if (b < 77824)  conv_job(Wcomb, 2048, 0, 1024, g_WcmA, 0, 1024, b - 73728);
    else if (b < 81920)  conv_job(Wcomb, 2048, 1024, 1024, g_WcmB, 0, 1024, b - 77824);
    else if (b < 86016)  conv_job(Watt, 1024, 0, 1024, g_Watt, 0, 1024, b - 81920);
    else if (b < 118784) conv_job(enc, 1024, 0, 1024, g_enchl, 0, 8192, b - 86016);
    else if (b < 124928) conv_job(cap, 512, 0, 512, g_capshl, 0, 3072, b - 118784);
    else if (b < 124944) {
        int n = (b - 124928) * 256 + threadIdx.x;
        if (n < 4096) {
            int srcn = (n & 3) * HDIM + (n >> 2);
            g_bg1[n] = bi1[srcn] + bh1[srcn];
            g_bg2[n] = bi2[srcn] + bh2[srcn];
        }
    } else {
        int i = (b - 124944) * 256 + threadIdx.x;
        if (i < BBATCH * HDIM) {
            int bb = i >> 10, k = i & 1023;
            g_c1[i] = c1i[i];
            g_c2[i] = c2i[i];
            g_h2f[i] = h2i[i];
            float v1 = h1i[i];
            bf16 h = __float2bfloat16(v1);
            bf16 l = __float2bfloat16(v1 - __bfloat162float(h));
            g_h1hl[0][bb * 2048 + k] = h;
            g_h1hl[0][bb * 2048 + 1024 + k] = l;
            float v2 = h2i[i];
            h = __float2bfloat16(v2);
            l = __float2bfloat16(v2 - __bfloat162float(h));
            g_h2hl[0][bb * 2048 + k] = h;
            g_h2hl[0][bb * 2048 + 1024 + k] = l;
            bf16 z = __float2bfloat16(0.f);
            g_ohl[bb * 2048 + k] = z;
            g_ohl[bb * 2048 + 1024 + k] = z;
        }
    }
}

// ---------------- 64x64 GEMM mainloop (N split across warpgroups) ----------------
// Stage (32768B): [Ahi 8K][Alo 8K][Whi 8K][Wlo 8K]; NSTG=4 -> 128KB
#define STGB 32768
#define NSTG 4

__device__ __forceinline__ void gemm64(
    char* smem, int m0, int n0,
    const bf16* A0, const bf16* W0, int K0,
    const bf16* A1, const bf16* W1, int K1,
    int npairs, float acc[4][4]) {
    const int tid = threadIdx.x;
    const int w = tid >> 5;
    const int l = tid & 31;
    const int wg = w >> 2;
    const int wm = w & 3;

    const bf16* Ab[2] = {A0, A1};
    const bf16* Wb[2] = {W0, W1};
    const int Kp[2] = {K0, K1};

    int NCH = 0;
    for (int p = 0; p < npairs; ++p) NCH += Kp[p] >> 6;

    const uint32_t sB = (uint32_t)__cvta_generic_to_shared(smem);

    int cp = 0, ckt = 0;
    auto issue = [&](int stg) {
        const bf16* A = Ab[cp];
        const bf16* W = Wb[cp];
        const int K = Kp[cp];
        const int ld = K << 1;
        const uint32_t base = sB + stg * STGB;
#pragma unroll
        for (int i = 0; i < 8; ++i) {
            int c = tid + (i << 8);   // 0..2047
            if (c < 512) {            // Ahi
                int row = c >> 3, ch = c & 7;
                const bf16* src = A + (size_t)(m0 + row) * ld + ckt + (ch << 3);
                CP16(base + row * 128 + ((ch ^ (row & 7)) << 4), src);
            } else if (c < 1024) {    // Alo
                int c2 = c - 512;
                int row = c2 >> 3, ch = c2 & 7;
                const bf16* src = A + (size_t)(m0 + row) * ld + K + ckt + (ch << 3);
                CP16(base + 8192 + row * 128 + ((ch ^ (row & 7)) << 4), src);
            } else if (c < 1536) {    // Whi (64 rows)
                int c2 = c - 1024;
                int row = c2 >> 3, ch = c2 & 7;
                const bf16* src = W + (size_t)(n0 + row) * ld + ckt + (ch << 3);
                CP16(base + 16384 + row * 128 + ((ch ^ (row & 7)) << 4), src);
            } else {                  // Wlo
                int c2 = c - 1536;
                int row = c2 >> 3, ch = c2 & 7;
                const bf16* src = W + (size_t)(n0 + row) * ld + K + ckt + (ch << 3);
                CP16(base + 24576 + row * 128 + ((ch ^ (row & 7)) << 4), src);
            }
        }
        asm volatile("cp.async.commit_group;\n" ::);
        ckt += 64;
        if (ckt >= K) { ckt = 0; ++cp; }
    };

#pragma unroll
    for (int j = 0; j < 4; ++j)
#pragma unroll
        for (int i = 0; i < 4; ++i) acc[j][i] = 0.f;

    const int npre = (NCH < NSTG - 1) ? NCH : (NSTG - 1);
    for (int i = 0; i < npre; ++i) issue(i);

    const int arow = 16 * wm + (l & 15);
    const int asel = (l >> 4) & 1;
    const int nrow0 = wg * 32 + (l & 7) + ((l & 16) >> 1);
    const int nrow1 = nrow0 + 16;
    const int bsel = (l >> 3) & 1;

    for (int it = 0; it < NCH; ++it) {
        const int pend = ((NCH < it + NSTG - 1) ? NCH : (it + NSTG - 1)) - (it + 1);
        if (pend >= 2)      asm volatile("cp.async.wait_group 2;\n" ::);
        else if (pend == 1) asm volatile("cp.async.wait_group 1;\n" ::);
        else                asm volatile("cp.async.wait_group 0;\n" ::);
        __syncthreads();
        if (it + NSTG - 1 < NCH) issue((it + NSTG - 1) & (NSTG - 1));

        const uint32_t aHi = sB + (it & (NSTG - 1)) * STGB;
        const uint32_t aLo = aHi + 8192;
        const uint32_t wHi = aHi + 16384;
        const uint32_t wLo = aHi + 24576;
#pragma unroll
        for (int kh = 0; kh < 4; ++kh) {
            const int ac = 2 * kh + asel;
            const int bc = 2 * kh + bsel;
            const uint32_t aoff = arow * 128 + ((ac ^ (arow & 7)) << 4);
            const uint32_t boff0 = nrow0 * 128 + ((bc ^ (nrow0 & 7)) << 4);
            const uint32_t boff1 = nrow1 * 128 + ((bc ^ (nrow1 & 7)) << 4);
            uint32_t ah0, ah1, ah2, ah3, al0, al1, al2, al3;
            LDSM4(ah0, ah1, ah2, ah3, aHi + aoff);
            LDSM4(al0, al1, al2, al3, aLo + aoff);
            uint32_t bh0, bh1, bh2, bh3, bh4, bh5, bh6, bh7;
            LDSM4(bh0, bh1, bh2, bh3, wHi + boff0);
            LDSM4(bh4, bh5, bh6, bh7, wHi + boff1);
            uint32_t bl0, bl1, bl2, bl3, bl4, bl5, bl6, bl7;
            LDSM4(bl0, bl1, bl2, bl3, wLo + boff0);
            LDSM4(bl4, bl5, bl6, bl7, wLo + boff1);
            MMA16816(acc[0], ah0, ah1, ah2, ah3, bh0, bh1);
            MMA16816(acc[1], ah0, ah1, ah2, ah3, bh2, bh3);
            MMA16816(acc[2], ah0, ah1, ah2, ah3, bh4, bh5);
            MMA16816(acc[3], ah0, ah1, ah2, ah3, bh6, bh7);
            MMA16816(acc[0], ah0, ah1, ah2, ah3, bl0, bl1);
            MMA16816(acc[1], ah0, ah1, ah2, ah3, bl2, bl3);
            MMA16816(acc[2], ah0, ah1, ah2, ah3, bl4, bl5);
            MMA16816(acc[3], ah0, ah1, ah2, ah3, bl6, bl7);
            MMA16816(acc[0], al0, al1, al2, al3, bh0, bh1);
            MMA16816(acc[1], al0, al1, al2, al3, bh2, bh3);
            MMA16816(acc[2], al0, al1, al2, al3, bh4, bh5);
            MMA16816(acc[3], al0, al1, al2, al3, bh6, bh7);
        }
    }
    __syncthreads();
}

// ---------------- epilogues (all warps; wg owns 32-col half) ----------------
__device__ __forceinline__ void epi_store64(int m0, int n0, float acc[4][4],
                                            const float* biasV, float* outF, int ldo) {
    const int tid = threadIdx.x;
    const int w = tid >> 5, l = tid & 31;
    const int wg = w >> 2, wm = w & 3;
    const int r = l >> 2, c2 = (l & 3) * 2;
#pragma unroll
    for (int j = 0; j < 4; ++j) {
        int n = n0 + wg * 32 + 8 * j + c2;
        float bv0 = biasV[n], bv1 = biasV[n + 1];
        size_t row0 = (size_t)(m0 + 16 * wm + r);
        outF[row0 * ldo + n] = acc[j][0] + bv0;
        outF[row0 * ldo + n + 1] = acc[j][1] + bv1;
        outF[(row0 + 8) * ldo + n] = acc[j][2] + bv0;
        outF[(row0 + 8) * ldo + n + 1] = acc[j][3] + bv1;
    }
}

// LSTM epilogue: 64 gate-cols = 16 hidden units. biasM read via __ldcg (cross-CTA).
__device__ __forceinline__ void epi_lstm64(char* smem, int n0, float acc[4][4],
                                           const float* biasM,
                                           bf16* outHL, float* outF, float* cstate) {
    const int tid = threadIdx.x;
    const int w = tid >> 5, l = tid & 31;
    const int wg = w >> 2, wm = w & 3;
    const int r = l >> 2, c2 = (l & 3) * 2;
    float* Csm = (float*)smem;
#pragma unroll
    for (int j = 0; j < 4; ++j) {
        int col = wg * 32 + 8 * j + c2;
        int n = n0 + col;
#pragma unroll
        for (int hh = 0; hh < 2; ++hh) {
            int m = 16 * wm + r + hh * 8;
            float b0 = __ldcg(&biasM[(size_t)m * 4096 + n]);
            float b1 = __ldcg(&biasM[(size_t)m * 4096 + n + 1]);
            Csm[m * 65 + col] = acc[j][2 * hh] + b0;
            Csm[m * 65 + col + 1] = acc[j][2 * hh + 1] + b1;
        }
    }
    __syncthreads();
#pragma unroll
    for (int q = 0; q < 4; ++q) {
        int item = tid * 4 + q;  // 1024 = 64 b x 16 hu
        int b = item >> 4;
        int hu = item & 15;
        float gi = Csm[b * 65 + hu * 4 + 0];
        float gf = Csm[b * 65 + hu * 4 + 1];
        float gg = Csm[b * 65 + hu * 4 + 2];
        float go = Csm[b * 65 + hu * 4 + 3];
        int hg = (n0 >> 2) + hu;
        int idx = b * HDIM + hg;
        float cold = cstate[idx];
        float i_ = sigm(gi), f_ = sigm(gf), g_ = tanhf(gg), o_ = sigm(go);
        float cn = f_ * cold + i_ * g_;
        cstate[idx] = cn;
        float hv = o_ * tanhf(cn);
        if (outF) outF[idx] = hv;
        bf16 hi = __float2bfloat16(hv);
        bf16 lo = __float2bfloat16(hv - __bfloat162float(hi));
        outHL[b * 2048 + hg] = hi;
        outHL[b * 2048 + 1024 + hg] = lo;
    }
    __syncthreads();
}

__device__ __forceinline__ void epi_tanh64(int n0, float acc[4][4], const float* biasV,
                                           float* outF, int ldo, bf16* outHL) {
    const int tid = threadIdx.x;
    const int w = tid >> 5, l = tid & 31;
    const int wg = w >> 2, wm = w & 3;
    const int r = l >> 2, c2 = (l & 3) * 2;
#pragma unroll
    for (int j = 0; j < 4; ++j) {
        int n = n0 + wg * 32 + 8 * j + c2;
        float bv0 = biasV[n], bv1 = biasV[n + 1];
        int b0r = 16 * wm + r;
#pragma unroll
        for (int hh = 0; hh < 2; ++hh) {
            int bb = b0r + hh * 8;
            float v0 = tanhf(acc[j][2 * hh] + bv0);
            float v1 = tanhf(acc[j][2 * hh + 1] + bv1);
            outF[(size_t)bb * ldo + n] = v0;
            outF[(size_t)bb * ldo + n + 1] = v1;
            bf16 h0 = __float2bfloat16(v0);
            bf16 l0 = __float2bfloat16(v0 - __bfloat162float(h0));
            bf16 h1 = __float2bfloat16(v1);
            bf16 l1 = __float2bfloat16(v1 - __bfloat162float(h1));
            outHL[bb * 2048 + n] = h0;
            outHL[bb * 2048 + 1024 + n] = l0;
            outHL[bb * 2048 + n + 1] = h1;
            outHL[bb * 2048 + 1024 + n + 1] = l1;
        }
    }
}

// ---------------- attention (per-b, one CTA) ----------------
__device__ __forceinline__ void attn_dev(char* smem, int b,
                                         const int* __restrict__ masks,
                                         const float* __restrict__ encproj,
                                         const float* __restrict__ enc,
                                         const float* __restrict__ h2f,
                                         bf16* __restrict__ athl) {
    float* sh2 = (float*)smem;
    float* sred = sh2 + HDIM;
    float* salpha = sred + LLEN;
    float* stmp = salpha + LLEN;
    const int tid = threadIdx.x;
    const int w = tid >> 5, l = tid & 31;

    {
        const float4* src = (const float4*)(h2f + b * HDIM);
        ((float4*)sh2)[tid] = __ldcg(src + tid);
    }
    __syncthreads();

    const float4* sh4 = (const float4*)sh2;
    for (int li = 0; li < 8; ++li) {
        int ll = w * 16 + li * 2;
        const float4* e0 = (const float4*)(encproj + ((size_t)(b * LLEN + ll)) * HDIM);
        const float4* e1 = (const float4*)(encproj + ((size_t)(b * LLEN + ll + 1)) * HDIM);
        float s0 = 0.f, s1 = 0.f;
#pragma unroll
        for (int j = 0; j < 8; ++j) {
            float4 hv = sh4[l + 32 * j];
            float4 v0 = e0[l + 32 * j];
            float4 v1 = e1[l + 32 * j];
            s0 += hv.x * v0.x + hv.y * v0.y + hv.z * v0.z + hv.w * v0.w;
            s1 += hv.x * v1.x + hv.y * v1.y + hv.z * v1.z + hv.w * v1.w;
        }
#pragma unroll
        for (int o = 16; o; o >>= 1) {
            s0 += __shfl_xor_sync(0xffffffffu, s0, o);
            s1 += __shfl_xor_sync(0xffffffffu, s1, o);
        }
        if (l == 0) {
            sred[ll] = masks[b * LLEN + ll] ? -1e30f : s0;
            sred[ll + 1] = masks[b * LLEN + ll + 1] ? -1e30f : s1;
        }
    }
    __syncthreads();

    if (tid < 128) stmp[tid] = sred[tid];
    __syncthreads();
    for (int s = 64; s; s >>= 1) {
        if (tid < s) stmp[tid] = fmaxf(stmp[tid], stmp[tid + s]);
        __syncthreads();
    }
    const float mx = stmp[0];
    __syncthreads();
    if (tid < 128) {
        float p = __expf(sred[tid] - mx);
        salpha[tid] = p;
        stmp[tid] = p;
    }
    __syncthreads();
    for (int s = 64; s; s >>= 1) {
        if (tid < s) stmp[tid] += stmp[tid + s];
        __syncthreads();
    }
    const float inv = 1.f / stmp[0];
    __syncthreads();
    if (tid < 128) salpha[tid] *= inv;
    __syncthreads();

    float4 p[8];
#pragma unroll
    for (int u = 0; u < 8; ++u) p[u] = make_float4(0.f, 0.f, 0.f, 0.f);
    const float4* ep4 = (const float4*)(enc + (size_t)b * LLEN * HEDIM);
    for (int l0 = 0; l0 < LLEN; l0 += 8) {
#pragma unroll
        for (int u = 0; u < 8; ++u) {
            float al = salpha[l0 + u];
            float4 v = ep4[(l0 + u) * 256 + tid];
            p[u].x += al * v.x;
            p[u].y += al * v.y;
            p[u].z += al * v.z;
            p[u].w += al * v.w;
        }
    }
#pragma unroll
    for (int u = 1; u < 8; ++u) {
        p[0].x += p[u].x; p[0].y += p[u].y; p[0].z += p[u].z; p[0].w += p[u].w;
    }
    int f = tid * 4;
    float vals[4] = {p[0].x, p[0].y, p[0].z, p[0].w};
#pragma unroll
    for (int i = 0; i < 4; ++i) {
        bf16 hi = __float2bfloat16(vals[i]);
        bf16 lo = __float2bfloat16(vals[i] - __bfloat162float(hi));
        athl[b * 2048 + f + i] = hi;
        athl[b * 2048 + 1024 + f + i] = lo;
    }
    __syncthreads();
}

// ---------------- grid barrier (replay-safe) ----------------
__device__ __forceinline__ void gsync(int slot) {
    __threadfence();
    __syncthreads();
    if (threadIdx.x == 0) {
        unsigned g = ((volatile unsigned*)g_gen)[slot];
        unsigned old = atomicAdd(&g_cnt[slot], 1u);
        if (old == NCTA - 1) {
            g_cnt[slot] = 0;
            __threadfence();
            atomicExch(&g_gen[slot], g + 1);
        } else {
            while (((volatile unsigned*)g_gen)[slot] == g) __nanosleep(64);
        }
    }
    __syncthreads();
    __threadfence();
}

// ---------------- prologue GEMM (fp32 store) ----------------
__global__ __launch_bounds__(256) void mma_pro(
    const bf16* A0, const bf16* W0, int K0,
    const float* __restrict__ biasV, float* __restrict__ outF, int ldo) {
    extern __shared__ __align__(16) char smem[];
    float acc[4][4];
    gemm64(smem, blockIdx.y * 64, blockIdx.x * 64,
           A0, W0, K0, nullptr, nullptr, 0, 1, acc);
    epi_store64(blockIdx.y * 64, blockIdx.x * 64, acc, biasV, outF, ldo);
}

// ---------------- step-phase helpers ----------------
// LSTM1 @ step tp, tile 0..63 (n0 = tile*64): reads h1hl[tp&1], writes h1hl[(tp&1)^1], c1
__device__ __forceinline__ void lstm1_tile(char* smem, int tp, int tile) {
    float acc[4][4];
    int n0 = tile * 64;
    gemm64(smem, 0, n0, g_h1hl[tp & 1], g_Whh1, 1024, nullptr, nullptr, 0, 1, acc);
    epi_lstm64(smem, n0, acc, g_pregates + (size_t)tp * BBATCH * 4096,
               g_h1hl[(tp & 1) ^ 1], nullptr, g_c1);
}

// LSTM2 partial @ step tp: pairs (h1@tp . Wih2A) + (h2@(tp-1) . Whh2) + bg2 -> gpart
__device__ __forceinline__ void lstm2_partial(char* smem, int tp, int tile) {
    float acc[4][4];
    int n0 = tile * 64;
    gemm64(smem, 0, n0, g_h1hl[(tp & 1) ^ 1], g_Wih2A, 1024,
           g_h2hl[tp & 1], g_Whh2, 1024, 2, acc);
    epi_store64(0, n0, acc, g_bg2, g_gpart, 4096);
}

// LSTM2 final @ step t: pair (ohl . Wih2B) + gpart -> h2hl[(t+1)&1], c2, h2f
__device__ __forceinline__ void lstm2_final(char* smem, int t, int tile) {
    float acc[4][4];
    int n0 = tile * 64;
    gemm64(smem, 0, n0, g_ohl, g_Wih2B, 1024, nullptr, nullptr, 0, 1, acc);
    epi_lstm64(smem, n0, acc, g_gpart, g_h2hl[(t + 1) & 1], g_h2f, g_c2);
}

// comb @ step t, tile 0..15: (athl.WcmA + h2.WcmB) -> tanh -> outs[t], ohl
__device__ __forceinline__ void comb_tile(char* smem, int t, int tile,
                                          const float* b_comb, float* outs) {
    float acc[4][4];
    int n0 = tile * 64;
    gemm64(smem, 0, n0, g_athl, g_WcmA, 1024,
           g_h2hl[(t + 1) & 1], g_WcmB, 1024, 2, acc);
    epi_tanh64(n0, acc, b_comb, outs + (size_t)t * BBATCH * HDIM, 1024, g_ohl);
}

// ---------------- persistent decoder loop ----------------
__global__ __launch_bounds__(256, 1) void decoder_loop(
    const int* __restrict__ masks, const float* __restrict__ enc,
    const float* __restrict__ b_comb, float* __restrict__ outs) {
    extern __shared__ __align__(16) char smem[];
    const int bid = blockIdx.x;

    // phase 0a: LSTM1 @ t=0
    if (bid < 64) lstm1_tile(smem, 0, bid);
    gsync(0);
    // phase 0b: LSTM2 @ t=0 partial
    if (bid < 64) lstm2_partial(smem, 0, bid);
    gsync(1);

    for (int t = 0; t < TSTEPS; ++t) {
        // PHASE A: LSTM2-final@t (bid<64) || LSTM1@t+1 (bid 64..127)
        if (bid < 64) {
            lstm2_final(smem, t, bid);
        } else if (bid < 128 && t + 1 < TSTEPS) {
            lstm1_tile(smem, t + 1, bid - 64);
        }
        gsync(2 + t * 3);

        // PHASE B: attention@t (bid<64)
        if (bid < 64)
            attn_dev(smem, bid, masks, g_encproj, enc, g_h2f, g_athl);
        gsync(3 + t * 3);

        // PHASE C: comb@t (bid<16) || LSTM2@t+1 partial (bid 16..79)
        if (bid < 16) {
            comb_tile(smem, t, bid, b_comb, outs);
        } else if (bid < 80 && t + 1 < TSTEPS) {
            lstm2_partial(smem, t + 1, bid - 16);
        }
        gsync(4 + t * 3);
    }
}

// ---------------- host launcher ----------------
extern "C" void kernel_launch(void* const* d_in, const int* in_sizes, int n_in,
                              void* d_out, int out_size) {
    const float* enc = (const float*)d_in[0];
    const int* masks = (const int*)d_in[1];
    const float* h1i = (const float*)d_in[2];
    const float* c1i = (const float*)d_in[3];
    const float* h2i = (const float*)d_in[4];
    const float* c2i = (const float*)d_in[5];
    const float* cap = (const float*)d_in[6];
    const float* W_ih1 = (const float*)d_in[7];
    const float* W_hh1 = (const float*)d_in[8];
    const float* b_ih1 = (const float*)d_in[9];
    const float* b_hh1 = (const float*)d_in[10];
    const float* W_ih2 = (const float*)d_in[11];
    const float* W_hh2 = (const float*)d_in[12];
    const float* b_ih2 = (const float*)d_in[13];
    const float* b_hh2 = (const float*)d_in[14];
    const float* W_att = (const float*)d_in[15];
    const float* b_att = (const float*)d_in[16];
    const float* W_comb = (const float*)d_in[17];
    const float* b_comb = (const float*)d_in[18];
    float* outs = (float*)d_out;

    bf16 *pWih1, *pWatt, *pEnchl, *pCapshl;
    float *pEncproj, *pPre, *pBg1;
    cudaGetSymbolAddress((void**)&pWih1, g_Wih1);
    cudaGetSymbolAddress((void**)&pWatt, g_Watt);
    cudaGetSymbolAddress((void**)&pEnchl, g_enchl);
    cudaGetSymbolAddress((void**)&pCapshl, g_capshl);
    cudaGetSymbolAddress((void**)&pEncproj, g_encproj);
    cudaGetSymbolAddress((void**)&pPre, g_pregates);
    cudaGetSymbolAddress((void**)&pBg1, g_bg1);

    const int SMEM = NSTG * STGB;   // 128 KB
    cudaFuncSetAttribute(mma_pro, cudaFuncAttributeMaxDynamicSharedMemorySize, SMEM);
    cudaFuncSetAttribute(decoder_loop, cudaFuncAttributeMaxDynamicSharedMemorySize, SMEM);

    // fused prologue: all conversions + bias + state init
    conv_all<<<CONV_BLOCKS, 256>>>(enc, cap, W_ih1, W_hh1, W_ih2, W_hh2, W_comb, W_att,
                                   b_ih1, b_hh1, b_ih2, b_hh2, h1i, c1i, h2i, c2i);

    // pregates = captions_all @ Wih1^T + bg1   (M=3072, N=4096)
    mma_pro<<<dim3(64, 48), 256, SMEM>>>(pCapshl, pWih1, 512, pBg1, pPre, 4096);
    // enc_proj = enc @ W_att^T + b_att         (M=8192, N=1024)
    mma_pro<<<dim3(16, 128), 256, SMEM>>>(pEnchl, pWatt, 1024, b_att, pEncproj, 1024);

    // whole 48-step loop in one persistent kernel
    decoder_loop<<<NCTA, 256, SMEM>>>(masks, enc, b_comb, outs);
}

// round 9
// speedup vs baseline: 1.3651x; 1.0017x over previous
#include <cuda_runtime.h>
#include <cuda_bf16.h>
#include <math.h>
#include <stdint.h>

#define BBATCH 64
#define LLEN 128
#define TSTEPS 48
#define EDIM 512
#define HEDIM 1024
#define HDIM 1024
#define NCTA 148

typedef __nv_bfloat16 bf16;

// ---------------- device scratch ----------------
__device__ bf16 g_Wih1[4096 * 1024];
__device__ bf16 g_Whh1[4096 * 2048];
__device__ bf16 g_Wih2A[4096 * 2048];
__device__ bf16 g_Wih2B[4096 * 2048];
__device__ bf16 g_Whh2[4096 * 2048];
__device__ bf16 g_WcmA[1024 * 2048];
__device__ bf16 g_WcmB[1024 * 2048];
__device__ bf16 g_Watt[1024 * 2048];
__device__ bf16 g_enchl[8192 * 2048];
__device__ bf16 g_capshl[3072 * 1024];
__device__ float g_encproj[8192 * 1024];
__device__ float g_pregates[3072 * 4096];
__device__ float g_gpart[BBATCH * 4096];   // LSTM2 partial gates (incl bg2)
__device__ float g_cpart[BBATCH * 1024];   // comb partial (h2 part + b_comb)
__device__ bf16 g_h1hl[2][BBATCH * 2048];
__device__ bf16 g_h2hl[2][BBATCH * 2048];
__device__ bf16 g_ohl[BBATCH * 2048];
__device__ bf16 g_athl[BBATCH * 2048];
__device__ float g_c1[BBATCH * HDIM];
__device__ float g_c2[BBATCH * HDIM];
__device__ float g_h2f[BBATCH * HDIM];
__device__ float g_bg1[4096];
__device__ float g_bg2[4096];

// grid barrier state
__device__ unsigned g_cnt[256];
__device__ unsigned g_gen[256];

__device__ __forceinline__ float sigm(float x) { return 1.f / (1.f + __expf(-x)); }

#define CP16(dst, src) \
    asm volatile("cp.async.cg.shared.global [%0], [%1], 16;\n" ::"r"(dst), "l"(src))
#define LDSM4(R0, R1, R2, R3, ADDR)                                        \
    asm volatile("ldmatrix.sync.aligned.m8n8.x4.shared.b16 {%0,%1,%2,%3},[%4];\n" \
                 : "=r"(R0), "=r"(R1), "=r"(R2), "=r"(R3)                  \
                 : "r"(ADDR))
#define MMA16816(C, A0, A1, A2, A3, B0, B1)                                    \
    asm volatile(                                                               \
        "mma.sync.aligned.m16n8k16.row.col.f32.bf16.bf16.f32 "                  \
        "{%0,%1,%2,%3},{%4,%5,%6,%7},{%8,%9},{%0,%1,%2,%3};\n"                  \
        : "+f"((C)[0]), "+f"((C)[1]), "+f"((C)[2]), "+f"((C)[3])                \
        : "r"(A0), "r"(A1), "r"(A2), "r"(A3), "r"(B0), "r"(B1))

// ---------------- fused prologue conversions ----------------
__device__ __forceinline__ void conv_job(const float* __restrict__ src, int srcld,
                                         int colOff, int K, bf16* __restrict__ dst,
                                         int interleave, int N, int lb) {
    int idx = lb * 256 + threadIdx.x;
    if (idx >= N * K) return;
    int n = idx / K, k = idx - n * K;
    int srcn = interleave ? ((n & 3) * HDIM + (n >> 2)) : n;
    float v = src[(size_t)srcn * srcld + colOff + k];
    bf16 hi = __float2bfloat16(v);
    bf16 lo = __float2bfloat16(v - __bfloat162float(hi));
    dst[(size_t)n * 2 * K + k] = hi;
    dst[(size_t)n * 2 * K + K + k] = lo;
}

#define CONV_BLOCKS 125200

__global__ void conv_all(const float* __restrict__ enc, const float* __restrict__ cap,
                         const float* __restrict__ Wih1, const float* __restrict__ Whh1,
                         const float* __restrict__ Wih2, const float* __restrict__ Whh2,
                         const float* __restrict__ Wcomb, const float* __restrict__ Watt,
                         const float* __restrict__ bi1, const float* __restrict__ bh1,
                         const float* __restrict__ bi2, const float* __restrict__ bh2,
                         const float* __restrict__ h1i, const float* __restrict__ c1i,
                         const float* __restrict__ h2i, const float* __restrict__ c2i) {
    int b = blockIdx.x;
    if (b < 8192)        conv_job(Wih1, 512, 0, 512, g_Wih1, 1, 4096, b);
    else if (b < 24576)  conv_job(Whh1, 1024, 0, 1024, g_Whh1, 1, 4096, b - 8192);
    else if (b < 40960)  conv_job(Wih2, 2048, 0, 1024, g_Wih2A, 1, 4096, b - 24576);
    else if (b < 57344)  conv_job(Wih2, 2048, 1024, 1024, g_Wih2B, 1, 4096, b - 40960);
    else if (b < 73728)  conv_job(Whh2, 1024, 0, 1024, g_Whh2, 1, 4096, b - 57344);
    else if (b < 77824)  conv_job(Wcomb, 2048, 0, 1024, g_WcmA, 0, 1024, b - 73728);
    else if (b < 81920)  conv_job(Wcomb, 2048, 1024, 1024, g_WcmB, 0, 1024, b - 77824);
    else if (b < 86016)  conv_job(Watt, 1024, 0, 1024, g_Watt, 0, 1024, b - 81920);
    else if (b < 118784) conv_job(enc, 1024, 0, 1024, g_enchl, 0, 8192, b - 86016);
    else if (b < 124928) conv_job(cap, 512, 0, 512, g_capshl, 0, 3072, b - 118784);
    else if (b < 124944) {
        int n = (b - 124928) * 256 + threadIdx.x;
        if (n < 4096) {
            int srcn = (n & 3) * HDIM + (n >> 2);
            g_bg1[n] = bi1[srcn] + bh1[srcn];
            g_bg2[n] = bi2[srcn] + bh2[srcn];
        }
    } else {
        int i = (b - 124944) * 256 + threadIdx.x;
        if (i < BBATCH * HDIM) {
            int bb = i >> 10, k = i & 1023;
            g_c1[i] = c1i[i];
            g_c2[i] = c2i[i];
            g_h2f[i] = h2i[i];
            float v1 = h1i[i];
            bf16 h = __float2bfloat16(v1);
            bf16 l = __float2bfloat16(v1 - __bfloat162float(h));
            g_h1hl[0][bb * 2048 + k] = h;
            g_h1hl[0][bb * 2048 + 1024 + k] = l;
            float v2 = h2i[i];
            h = __float2bfloat16(v2);
            l = __float2bfloat16(v2 - __bfloat162float(h));
            g_h2hl[0][bb * 2048 + k] = h;
            g_h2hl[0][bb * 2048 + 1024 + k] = l;
            bf16 z = __float2bfloat16(0.f);
            g_ohl[bb * 2048 + k] = z;
            g_ohl[bb * 2048 + 1024 + k] = z;
        }
    }
}

// ---------------- 64x64 GEMM mainloop (N split across warpgroups) ----------------
#define STGB 32768
#define NSTG 4

__device__ __forceinline__ void gemm64(
    char* smem, int m0, int n0,
    const bf16* A0, const bf16* W0, int K0,
    const bf16* A1, const bf16* W1, int K1,
    int npairs, float acc[4][4]) {
    const int tid = threadIdx.x;
    const int w = tid >> 5;
    const int l = tid & 31;
    const int wg = w >> 2;
    const int wm = w & 3;

    const bf16* Ab[2] = {A0, A1};
    const bf16* Wb[2] = {W0, W1};
    const int Kp[2] = {K0, K1};

    int NCH = 0;
    for (int p = 0; p < npairs; ++p) NCH += Kp[p] >> 6;

    const uint32_t sB = (uint32_t)__cvta_generic_to_shared(smem);

    int cp = 0, ckt = 0;
    auto issue = [&](int stg) {
        const bf16* A = Ab[cp];
        const bf16* W = Wb[cp];
        const int K = Kp[cp];
        const int ld = K << 1;
        const uint32_t base = sB + stg * STGB;
#pragma unroll
        for (int i = 0; i < 8; ++i) {
            int c = tid + (i << 8);
            if (c < 512) {
                int row = c >> 3, ch = c & 7;
                const bf16* src = A + (size_t)(m0 + row) * ld + ckt + (ch << 3);
                CP16(base + row * 128 + ((ch ^ (row & 7)) << 4), src);
            } else if (c < 1024) {
                int c2 = c - 512;
                int row = c2 >> 3, ch = c2 & 7;
                const bf16* src = A + (size_t)(m0 + row) * ld + K + ckt + (ch << 3);
                CP16(base + 8192 + row * 128 + ((ch ^ (row & 7)) << 4), src);
            } else if (c < 1536) {
                int c2 = c - 1024;
                int row = c2 >> 3, ch = c2 & 7;
                const bf16* src = W + (size_t)(n0 + row) * ld + ckt + (ch << 3);
                CP16(base + 16384 + row * 128 + ((ch ^ (row & 7)) << 4), src);
            } else {
                int c2 = c - 1536;
                int row = c2 >> 3, ch = c2 & 7;
                const bf16* src = W + (size_t)(n0 + row) * ld + K + ckt + (ch << 3);
                CP16(base + 24576 + row * 128 + ((ch ^ (row & 7)) << 4), src);
            }
        }
        asm volatile("cp.async.commit_group;\n" ::);
        ckt += 64;
        if (ckt >= K) { ckt = 0; ++cp; }
    };

#pragma unroll
    for (int j = 0; j < 4; ++j)
#pragma unroll
        for (int i = 0; i < 4; ++i) acc[j][i] = 0.f;

    const int npre = (NCH < NSTG - 1) ? NCH : (NSTG - 1);
    for (int i = 0; i < npre; ++i) issue(i);

    const int arow = 16 * wm + (l & 15);
    const int asel = (l >> 4) & 1;
    const int nrow0 = wg * 32 + (l & 7) + ((l & 16) >> 1);
    const int nrow1 = nrow0 + 16;
    const int bsel = (l >> 3) & 1;

    for (int it = 0; it < NCH; ++it) {
        const int pend = ((NCH < it + NSTG - 1) ? NCH : (it + NSTG - 1)) - (it + 1);
        if (pend >= 2)      asm volatile("cp.async.wait_group 2;\n" ::);
        else if (pend == 1) asm volatile("cp.async.wait_group 1;\n" ::);
        else                asm volatile("cp.async.wait_group 0;\n" ::);
        __syncthreads();
        if (it + NSTG - 1 < NCH) issue((it + NSTG - 1) & (NSTG - 1));

        const uint32_t aHi = sB + (it & (NSTG - 1)) * STGB;
        const uint32_t aLo = aHi + 8192;
        const uint32_t wHi = aHi + 16384;
        const uint32_t wLo = aHi + 24576;
#pragma unroll
        for (int kh = 0; kh < 4; ++kh) {
            const int ac = 2 * kh + asel;
            const int bc = 2 * kh + bsel;
            const uint32_t aoff = arow * 128 + ((ac ^ (arow & 7)) << 4);
            const uint32_t boff0 = nrow0 * 128 + ((bc ^ (nrow0 & 7)) << 4);
            const uint32_t boff1 = nrow1 * 128 + ((bc ^ (nrow1 & 7)) << 4);
            uint32_t ah0, ah1, ah2, ah3, al0, al1, al2, al3;
            LDSM4(ah0, ah1, ah2, ah3, aHi + aoff);
            LDSM4(al0, al1, al2, al3, aLo + aoff);
            uint32_t bh0, bh1, bh2, bh3, bh4, bh5, bh6, bh7;
            LDSM4(bh0, bh1, bh2, bh3, wHi + boff0);
            LDSM4(bh4, bh5, bh6, bh7, wHi + boff1);
            uint32_t bl0, bl1, bl2, bl3, bl4, bl5, bl6, bl7;
            LDSM4(bl0, bl1, bl2, bl3, wLo + boff0);
            LDSM4(bl4, bl5, bl6, bl7, wLo + boff1);
            MMA16816(acc[0], ah0, ah1, ah2, ah3, bh0, bh1);
            MMA16816(acc[1], ah0, ah1, ah2, ah3, bh2, bh3);
            MMA16816(acc[2], ah0, ah1, ah2, ah3, bh4, bh5);
            MMA16816(acc[3], ah0, ah1, ah2, ah3, bh6, bh7);
            MMA16816(acc[0], ah0, ah1, ah2, ah3, bl0, bl1);
            MMA16816(acc[1], ah0, ah1, ah2, ah3, bl2, bl3);
            MMA16816(acc[2], ah0, ah1, ah2, ah3, bl4, bl5);
            MMA16816(acc[3], ah0, ah1, ah2, ah3, bl6, bl7);
            MMA16816(acc[0], al0, al1, al2, al3, bh0, bh1);
            MMA16816(acc[1], al0, al1, al2, al3, bh2, bh3);
            MMA16816(acc[2], al0, al1, al2, al3, bh4, bh5);
            MMA16816(acc[3], al0, al1, al2, al3, bh6, bh7);
        }
    }
    __syncthreads();
}

// ---------------- epilogues ----------------
__device__ __forceinline__ void epi_store64(int m0, int n0, float acc[4][4],
                                            const float* biasV, float* outF, int ldo) {
    const int tid = threadIdx.x;
    const int w = tid >> 5, l = tid & 31;
    const int wg = w >> 2, wm = w & 3;
    const int r = l >> 2, c2 = (l & 3) * 2;
#pragma unroll
    for (int j = 0; j < 4; ++j) {
        int n = n0 + wg * 32 + 8 * j + c2;
        float bv0 = biasV[n], bv1 = biasV[n + 1];
        size_t row0 = (size_t)(m0 + 16 * wm + r);
        outF[row0 * ldo + n] = acc[j][0] + bv0;
        outF[row0 * ldo + n + 1] = acc[j][1] + bv1;
        outF[(row0 + 8) * ldo + n] = acc[j][2] + bv0;
        outF[(row0 + 8) * ldo + n + 1] = acc[j][3] + bv1;
    }
}

__device__ __forceinline__ void epi_lstm64(char* smem, int n0, float acc[4][4],
                                           const float* biasM,
                                           bf16* outHL, float* outF, float* cstate) {
    const int tid = threadIdx.x;
    const int w = tid >> 5, l = tid & 31;
    const int wg = w >> 2, wm = w & 3;
    const int r = l >> 2, c2 = (l & 3) * 2;
    float* Csm = (float*)smem;
#pragma unroll
    for (int j = 0; j < 4; ++j) {
        int col = wg * 32 + 8 * j + c2;
        int n = n0 + col;
#pragma unroll
        for (int hh = 0; hh < 2; ++hh) {
            int m = 16 * wm + r + hh * 8;
            float b0 = __ldcg(&biasM[(size_t)m * 4096 + n]);
            float b1 = __ldcg(&biasM[(size_t)m * 4096 + n + 1]);
            Csm[m * 65 + col] = acc[j][2 * hh] + b0;
            Csm[m * 65 + col + 1] = acc[j][2 * hh + 1] + b1;
        }
    }
    __syncthreads();
#pragma unroll
    for (int q = 0; q < 4; ++q) {
        int item = tid * 4 + q;
        int b = item >> 4;
        int hu = item & 15;
        float gi = Csm[b * 65 + hu * 4 + 0];
        float gf = Csm[b * 65 + hu * 4 + 1];
        float gg = Csm[b * 65 + hu * 4 + 2];
        float go = Csm[b * 65 + hu * 4 + 3];
        int hg = (n0 >> 2) + hu;
        int idx = b * HDIM + hg;
        float cold = cstate[idx];
        float i_ = sigm(gi), f_ = sigm(gf), g_ = tanhf(gg), o_ = sigm(go);
        float cn = f_ * cold + i_ * g_;
        cstate[idx] = cn;
        float hv = o_ * tanhf(cn);
        if (outF) outF[idx] = hv;
        bf16 hi = __float2bfloat16(hv);
        bf16 lo = __float2bfloat16(hv - __bfloat162float(hi));
        outHL[b * 2048 + hg] = hi;
        outHL[b * 2048 + 1024 + hg] = lo;
    }
    __syncthreads();
}

// tanh epilogue with per-(m,n) partial (cpart, ld 1024, __ldcg)
__device__ __forceinline__ void epi_tanh_c(int n0, float acc[4][4], const float* cpartM,
                                           float* outF, int ldo, bf16* outHL) {
    const int tid = threadIdx.x;
    const int w = tid >> 5, l = tid & 31;
    const int wg = w >> 2, wm = w & 3;
    const int r = l >> 2, c2 = (l & 3) * 2;
#pragma unroll
    for (int j = 0; j < 4; ++j) {
        int n = n0 + wg * 32 + 8 * j + c2;
        int b0r = 16 * wm + r;
#pragma unroll
        for (int hh = 0; hh < 2; ++hh) {
            int bb = b0r + hh * 8;
            float p0 = __ldcg(&cpartM[(size_t)bb * 1024 + n]);
            float p1 = __ldcg(&cpartM[(size_t)bb * 1024 + n + 1]);
            float v0 = tanhf(acc[j][2 * hh] + p0);
            float v1 = tanhf(acc[j][2 * hh + 1] + p1);
            outF[(size_t)bb * ldo + n] = v0;
            outF[(size_t)bb * ldo + n + 1] = v1;
            bf16 h0 = __float2bfloat16(v0);
            bf16 l0 = __float2bfloat16(v0 - __bfloat162float(h0));
            bf16 h1 = __float2bfloat16(v1);
            bf16 l1 = __float2bfloat16(v1 - __bfloat162float(h1));
            outHL[bb * 2048 + n] = h0;
            outHL[bb * 2048 + 1024 + n] = l0;
            outHL[bb * 2048 + n + 1] = h1;
            outHL[bb * 2048 + 1024 + n + 1] = l1;
        }
    }
}

// ---------------- attention (per-b, one CTA; 4-row score streams) ----------------
__device__ __forceinline__ void attn_dev(char* smem, int b,
                                         const int* __restrict__ masks,
                                         const float* __restrict__ encproj,
                                         const float* __restrict__ enc,
                                         const float* __restrict__ h2f,
                                         bf16* __restrict__ athl) {
    float* sh2 = (float*)smem;
    float* sred = sh2 + HDIM;
    float* salpha = sred + LLEN;
    float* stmp = salpha + LLEN;
    const int tid = threadIdx.x;
    const int w = tid >> 5, l = tid & 31;

    {
        const float4* src = (const float4*)(h2f + b * HDIM);
        ((float4*)sh2)[tid] = __ldcg(src + tid);
    }
    __syncthreads();

    const float4* sh4 = (const float4*)sh2;
#pragma unroll
    for (int li = 0; li < 4; ++li) {
        int ll = w * 16 + li * 4;
        const float4* e0 = (const float4*)(encproj + ((size_t)(b * LLEN + ll + 0)) * HDIM);
        const float4* e1 = (const float4*)(encproj + ((size_t)(b * LLEN + ll + 1)) * HDIM);
        const float4* e2 = (const float4*)(encproj + ((size_t)(b * LLEN + ll + 2)) * HDIM);
        const float4* e3 = (const float4*)(encproj + ((size_t)(b * LLEN + ll + 3)) * HDIM);
        float s0 = 0.f, s1 = 0.f, s2 = 0.f, s3 = 0.f;
#pragma unroll
        for (int j = 0; j < 8; ++j) {
            float4 hv = sh4[l + 32 * j];
            float4 v0 = e0[l + 32 * j];
            float4 v1 = e1[l + 32 * j];
            float4 v2 = e2[l + 32 * j];
            float4 v3 = e3[l + 32 * j];
            s0 += hv.x * v0.x + hv.y * v0.y + hv.z * v0.z + hv.w * v0.w;
            s1 += hv.x * v1.x + hv.y * v1.y + hv.z * v1.z + hv.w * v1.w;
            s2 += hv.x * v2.x + hv.y * v2.y + hv.z * v2.z + hv.w * v2.w;
            s3 += hv.x * v3.x + hv.y * v3.y + hv.z * v3.z + hv.w * v3.w;
        }
#pragma unroll
        for (int o = 16; o; o >>= 1) {
            s0 += __shfl_xor_sync(0xffffffffu, s0, o);
            s1 += __shfl_xor_sync(0xffffffffu, s1, o);
            s2 += __shfl_xor_sync(0xffffffffu, s2, o);
            s3 += __shfl_xor_sync(0xffffffffu, s3, o);
        }
        if (l == 0) {
            sred[ll + 0] = masks[b * LLEN + ll + 0] ? -1e30f : s0;
            sred[ll + 1] = masks[b * LLEN + ll + 1] ? -1e30f : s1;
            sred[ll + 2] = masks[b * LLEN + ll + 2] ? -1e30f : s2;
            sred[ll + 3] = masks[b * LLEN + ll + 3] ? -1e30f : s3;
        }
    }
    __syncthreads();

    if (tid < 128) stmp[tid] = sred[tid];
    __syncthreads();
    for (int s = 64; s; s >>= 1) {
        if (tid < s) stmp[tid] = fmaxf(stmp[tid], stmp[tid + s]);
        __syncthreads();
    }
    const float mx = stmp[0];
    __syncthreads();
    if (tid < 128) {
        float p = __expf(sred[tid] - mx);
        salpha[tid] = p;
        stmp[tid] = p;
    }
    __syncthreads();
    for (int s = 64; s; s >>= 1) {
        if (tid < s) stmp[tid] += stmp[tid + s];
        __syncthreads();
    }
    const float inv = 1.f / stmp[0];
    __syncthreads();
    if (tid < 128) salpha[tid] *= inv;
    __syncthreads();

    float4 p[8];
#pragma unroll
    for (int u = 0; u < 8; ++u) p[u] = make_float4(0.f, 0.f, 0.f, 0.f);
    const float4* ep4 = (const float4*)(enc + (size_t)b * LLEN * HEDIM);
    for (int l0 = 0; l0 < LLEN; l0 += 8) {
#pragma unroll
        for (int u = 0; u < 8; ++u) {
            float al = salpha[l0 + u];
            float4 v = ep4[(l0 + u) * 256 + tid];
            p[u].x += al * v.x;
            p[u].y += al * v.y;
            p[u].z += al * v.z;
            p[u].w += al * v.w;
        }
    }
#pragma unroll
    for (int u = 1; u < 8; ++u) {
        p[0].x += p[u].x; p[0].y += p[u].y; p[0].z += p[u].z; p[0].w += p[u].w;
    }
    int f = tid * 4;
    float vals[4] = {p[0].x, p[0].y, p[0].z, p[0].w};
#pragma unroll
    for (int i = 0; i < 4; ++i) {
        bf16 hi = __float2bfloat16(vals[i]);
        bf16 lo = __float2bfloat16(vals[i] - __bfloat162float(hi));
        athl[b * 2048 + f + i] = hi;
        athl[b * 2048 + 1024 + f + i] = lo;
    }
    __syncthreads();
}

// ---------------- grid barrier (replay-safe) ----------------
__device__ __forceinline__ void gsync(int slot) {
    __threadfence();
    __syncthreads();
    if (threadIdx.x == 0) {
        unsigned g = ((volatile unsigned*)g_gen)[slot];
        unsigned old = atomicAdd(&g_cnt[slot], 1u);
        if (old == NCTA - 1) {
            g_cnt[slot] = 0;
            __threadfence();
            atomicExch(&g_gen[slot], g + 1);
        } else {
            while (((volatile unsigned*)g_gen)[slot] == g) __nanosleep(32);
        }
    }
    __syncthreads();
    __threadfence();
}

// ---------------- prologue GEMM (fp32 store) ----------------
__global__ __launch_bounds__(256) void mma_pro(
    const bf16* A0, const bf16* W0, int K0,
    const float* __restrict__ biasV, float* __restrict__ outF, int ldo) {
    extern __shared__ __align__(16) char smem[];
    float acc[4][4];
    gemm64(smem, blockIdx.y * 64, blockIdx.x * 64,
           A0, W0, K0, nullptr, nullptr, 0, 1, acc);
    epi_store64(blockIdx.y * 64, blockIdx.x * 64, acc, biasV, outF, ldo);
}

// ---------------- step-phase helpers ----------------
__device__ __forceinline__ void lstm1_tile(char* smem, int tp, int tile) {
    float acc[4][4];
    int n0 = tile * 64;
    gemm64(smem, 0, n0, g_h1hl[tp & 1], g_Whh1, 1024, nullptr, nullptr, 0, 1, acc);
    epi_lstm64(smem, n0, acc, g_pregates + (size_t)tp * BBATCH * 4096,
               g_h1hl[(tp & 1) ^ 1], nullptr, g_c1);
}

__device__ __forceinline__ void lstm2_partial(char* smem, int tp, int tile) {
    float acc[4][4];
    int n0 = tile * 64;
    gemm64(smem, 0, n0, g_h1hl[(tp & 1) ^ 1], g_Wih2A, 1024,
           g_h2hl[tp & 1], g_Whh2, 1024, 2, acc);
    epi_store64(0, n0, acc, g_bg2, g_gpart, 4096);
}

__device__ __forceinline__ void lstm2_final(char* smem, int t, int tile) {
    float acc[4][4];
    int n0 = tile * 64;
    gemm64(smem, 0, n0, g_ohl, g_Wih2B, 1024, nullptr, nullptr, 0, 1, acc);
    epi_lstm64(smem, n0, acc, g_gpart, g_h2hl[(t + 1) & 1], g_h2f, g_c2);
}

// comb partial: h2@t . WcmB + b_comb -> cpart (phase B)
__device__ __forceinline__ void comb_partial(char* smem, int t, int tile) {
    float acc[4][4];
    int n0 = tile * 64;
    gemm64(smem, 0, n0, g_h2hl[(t + 1) & 1], g_WcmB, 1024, nullptr, nullptr, 0, 1, acc);
    epi_store64(0, n0, acc, g_cpart /*unused path*/, g_cpart, 1024);
}

// comb final: athl . WcmA + cpart -> tanh -> outs, ohl (phase C)
__device__ __forceinline__ void comb_final(char* smem, int t, int tile,
                                           float* outs) {
    float acc[4][4];
    int n0 = tile * 64;
    gemm64(smem, 0, n0, g_athl, g_WcmA, 1024, nullptr, nullptr, 0, 1, acc);
    epi_tanh_c(n0, acc, g_cpart, outs + (size_t)t * BBATCH * HDIM, 1024, g_ohl);
}

// comb partial needs b_comb as plain bias vector:
__device__ __forceinline__ void comb_partial_b(char* smem, int t, int tile,
                                               const float* b_comb) {
    float acc[4][4];
    int n0 = tile * 64;
    gemm64(smem, 0, n0, g_h2hl[(t + 1) & 1], g_WcmB, 1024, nullptr, nullptr, 0, 1, acc);
    epi_store64(0, n0, acc, b_comb, g_cpart, 1024);
}

// ---------------- persistent decoder loop ----------------
__global__ __launch_bounds__(256, 1) void decoder_loop(
    const int* __restrict__ masks, const float* __restrict__ enc,
    const float* __restrict__ b_comb, float* __restrict__ outs) {
    extern __shared__ __align__(16) char smem[];
    const int bid = blockIdx.x;

    // phase 0a: LSTM1 @ t=0
    if (bid < 64) lstm1_tile(smem, 0, bid);
    gsync(0);
    // phase 0b: LSTM2 @ t=0 partial
    if (bid < 64) lstm2_partial(smem, 0, bid);
    gsync(1);

    for (int t = 0; t < TSTEPS; ++t) {
        // PHASE A: LSTM2-final@t (bid<64) || LSTM1@t+1 (bid 64..127)
        if (bid < 64) {
            lstm2_final(smem, t, bid);
        } else if (bid < 128 && t + 1 < TSTEPS) {
            lstm1_tile(smem, t + 1, bid - 64);
        }
        gsync(2 + t * 3);

        // PHASE B: attn@t (bid<64) || LSTM2-partial@t+1 (64..127) || comb-partial@t (128..143)
        if (bid < 64) {
            attn_dev(smem, bid, masks, g_encproj, enc, g_h2f, g_athl);
        } else if (bid < 128) {
            if (t + 1 < TSTEPS) lstm2_partial(smem, t + 1, bid - 64);
        } else if (bid < 144) {
            comb_partial_b(smem, t, bid - 128, b_comb);
        }
        gsync(3 + t * 3);

        // PHASE C: comb-final@t (bid<16)
        if (bid < 16) comb_final(smem, t, bid, outs);
        gsync(4 + t * 3);
    }
}

// ---------------- host launcher ----------------
extern "C" void kernel_launch(void* const* d_in, const int* in_sizes, int n_in,
                              void* d_out, int out_size) {
    const float* enc = (const float*)d_in[0];
    const int* masks = (const int*)d_in[1];
    const float* h1i = (const float*)d_in[2];
    const float* c1i = (const float*)d_in[3];
    const float* h2i = (const float*)d_in[4];
    const float* c2i = (const float*)d_in[5];
    const float* cap = (const float*)d_in[6];
    const float* W_ih1 = (const float*)d_in[7];
    const float* W_hh1 = (const float*)d_in[8];
    const float* b_ih1 = (const float*)d_in[9];
    const float* b_hh1 = (const float*)d_in[10];
    const float* W_ih2 = (const float*)d_in[11];
    const float* W_hh2 = (const float*)d_in[12];
    const float* b_ih2 = (const float*)d_in[13];
    const float* b_hh2 = (const float*)d_in[14];
    const float* W_att = (const float*)d_in[15];
    const float* b_att = (const float*)d_in[16];
    const float* W_comb = (const float*)d_in[17];
    const float* b_comb = (const float*)d_in[18];
    float* outs = (float*)d_out;

    bf16 *pWih1, *pWatt, *pEnchl, *pCapshl;
    float *pEncproj, *pPre, *pBg1;
    cudaGetSymbolAddress((void**)&pWih1, g_Wih1);
    cudaGetSymbolAddress((void**)&pWatt, g_Watt);
    cudaGetSymbolAddress((void**)&pEnchl, g_enchl);
    cudaGetSymbolAddress((void**)&pCapshl, g_capshl);
    cudaGetSymbolAddress((void**)&pEncproj, g_encproj);
    cudaGetSymbolAddress((void**)&pPre, g_pregates);
    cudaGetSymbolAddress((void**)&pBg1, g_bg1);

    const int SMEM = NSTG * STGB;   // 128 KB
    cudaFuncSetAttribute(mma_pro, cudaFuncAttributeMaxDynamicSharedMemorySize, SMEM);
    cudaFuncSetAttribute(decoder_loop, cudaFuncAttributeMaxDynamicSharedMemorySize, SMEM);

    conv_all<<<CONV_BLOCKS, 256>>>(enc, cap, W_ih1, W_hh1, W_ih2, W_hh2, W_comb, W_att,
                                   b_ih1, b_hh1, b_ih2, b_hh2, h1i, c1i, h2i, c2i);

    mma_pro<<<dim3(64, 48), 256, SMEM>>>(pCapshl, pWih1, 512, pBg1, pPre, 4096);
    mma_pro<<<dim3(16, 128), 256, SMEM>>>(pEnchl, pWatt, 1024, b_att, pEncproj, 1024);

    decoder_loop<<<NCTA, 256, SMEM>>>(masks, enc, b_comb, outs);
}

// round 10
// speedup vs baseline: 1.3931x; 1.0205x over previous
#include <cuda_runtime.h>
#include <cuda_bf16.h>
#include <math.h>
#include <stdint.h>

#define BBATCH 64
#define LLEN 128
#define TSTEPS 48
#define EDIM 512
#define HEDIM 1024
#define HDIM 1024
#define NCTA 148

typedef __nv_bfloat16 bf16;

// ---------------- device scratch ----------------
__device__ bf16 g_Wih1[4096 * 1024];
__device__ bf16 g_Whh1[4096 * 2048];
__device__ bf16 g_Wih2A[4096 * 2048];
__device__ bf16 g_Wih2B[4096 * 2048];
__device__ bf16 g_Whh2[4096 * 2048];
__device__ bf16 g_WcmA[1024 * 2048];
__device__ bf16 g_WcmB[1024 * 2048];
__device__ bf16 g_Watt[1024 * 2048];
__device__ bf16 g_enchl[8192 * 2048];
__device__ bf16 g_capshl[3072 * 1024];
__device__ float g_encproj[8192 * 1024];
__device__ float g_pregates[3072 * 4096];
__device__ float g_gpart[BBATCH * 4096];
__device__ float g_cpart[BBATCH * 1024];
__device__ bf16 g_h1hl[2][BBATCH * 2048];
__device__ bf16 g_h2hl[2][BBATCH * 2048];
__device__ bf16 g_ohl[BBATCH * 2048];
__device__ bf16 g_athl[BBATCH * 2048];
__device__ float g_c1[BBATCH * HDIM];
__device__ float g_c2[BBATCH * HDIM];
__device__ float g_h2f[BBATCH * HDIM];
__device__ float g_bg1[4096];
__device__ float g_bg2[4096];

__device__ unsigned g_cnt[256];
__device__ unsigned g_gen[256];

__device__ __forceinline__ float sigm(float x) { return 1.f / (1.f + __expf(-x)); }

#define CP16(dst, src) \
    asm volatile("cp.async.cg.shared.global [%0], [%1], 16;\n" ::"r"(dst), "l"(src))
#define LDSM4(R0, R1, R2, R3, ADDR)                                        \
    asm volatile("ldmatrix.sync.aligned.m8n8.x4.shared.b16 {%0,%1,%2,%3},[%4];\n" \
                 : "=r"(R0), "=r"(R1), "=r"(R2), "=r"(R3)                  \
                 : "r"(ADDR))
#define MMA16816(C, A0, A1, A2, A3, B0, B1)                                    \
    asm volatile(                                                               \
        "mma.sync.aligned.m16n8k16.row.col.f32.bf16.bf16.f32 "                  \
        "{%0,%1,%2,%3},{%4,%5,%6,%7},{%8,%9},{%0,%1,%2,%3};\n"                  \
        : "+f"((C)[0]), "+f"((C)[1]), "+f"((C)[2]), "+f"((C)[3])                \
        : "r"(A0), "r"(A1), "r"(A2), "r"(A3), "r"(B0), "r"(B1))

// ---------------- fused prologue conversions ----------------
__device__ __forceinline__ void conv_job(const float* __restrict__ src, int srcld,
                                         int colOff, int K, bf16* __restrict__ dst,
                                         int interleave, int N, int lb) {
    int idx = lb * 256 + threadIdx.x;
    if (idx >= N * K) return;
    int n = idx / K, k = idx - n * K;
    int srcn = interleave ? ((n & 3) * HDIM + (n >> 2)) : n;
    float v = src[(size_t)srcn * srcld + colOff + k];
    bf16 hi = __float2bfloat16(v);
    bf16 lo = __float2bfloat16(v - __bfloat162float(hi));
    dst[(size_t)n * 2 * K + k] = hi;
    dst[(size_t)n * 2 * K + K + k] = lo;
}

#define CONV_BLOCKS 125200

__global__ void conv_all(const float* __restrict__ enc, const float* __restrict__ cap,
                         const float* __restrict__ Wih1, const float* __restrict__ Whh1,
                         const float* __restrict__ Wih2, const float* __restrict__ Whh2,
                         const float* __restrict__ Wcomb, const float* __restrict__ Watt,
                         const float* __restrict__ bi1, const float* __restrict__ bh1,
                         const float* __restrict__ bi2, const float* __restrict__ bh2,
                         const float* __restrict__ h1i, const float* __restrict__ c1i,
                         const float* __restrict__ h2i, const float* __restrict__ c2i) {
    int b = blockIdx.x;
    if (b < 8192)        conv_job(Wih1, 512, 0, 512, g_Wih1, 1, 4096, b);
    else if (b < 24576)  conv_job(Whh1, 1024, 0, 1024, g_Whh1, 1, 4096, b - 8192);
    else if (b < 40960)  conv_job(Wih2, 2048, 0, 1024, g_Wih2A, 1, 4096, b - 24576);
    else if (b < 57344)  conv_job(Wih2, 2048, 1024, 1024, g_Wih2B, 1, 4096, b - 40960);
    else if (b < 73728)  conv_job(Whh2, 1024, 0, 1024, g_Whh2, 1, 4096, b - 57344);
    else if (b < 77824)  conv_job(Wcomb, 2048, 0, 1024, g_WcmA, 0, 1024, b - 73728);
    else if (b < 81920)  conv_job(Wcomb, 2048, 1024, 1024, g_WcmB, 0, 1024, b - 77824);
    else if (b < 86016)  conv_job(Watt, 1024, 0, 1024, g_Watt, 0, 1024, b - 81920);
    else if (b < 118784) conv_job(enc, 1024, 0, 1024, g_enchl, 0, 8192, b - 86016);
    else if (b < 124928) conv_job(cap, 512, 0, 512, g_capshl, 0, 3072, b - 118784);
    else if (b < 124944) {
        int n = (b - 124928) * 256 + threadIdx.x;
        if (n < 4096) {
            int srcn = (n & 3) * HDIM + (n >> 2);
            g_bg1[n] = bi1[srcn] + bh1[srcn];
            g_bg2[n] = bi2[srcn] + bh2[srcn];
        }
    } else {
        int i = (b - 124944) * 256 + threadIdx.x;
        if (i < BBATCH * HDIM) {
            int bb = i >> 10, k = i & 1023;
            g_c1[i] = c1i[i];
            g_c2[i] = c2i[i];
            g_h2f[i] = h2i[i];
            float v1 = h1i[i];
            bf16 h = __float2bfloat16(v1);
            bf16 l = __float2bfloat16(v1 - __bfloat162float(h));
            g_h1hl[0][bb * 2048 + k] = h;
            g_h1hl[0][bb * 2048 + 1024 + k] = l;
            float v2 = h2i[i];
            h = __float2bfloat16(v2);
            l = __float2bfloat16(v2 - __bfloat162float(h));
            g_h2hl[0][bb * 2048 + k] = h;
            g_h2hl[0][bb * 2048 + 1024 + k] = l;
            bf16 z = __float2bfloat16(0.f);
            g_ohl[bb * 2048 + k] = z;
            g_ohl[bb * 2048 + 1024 + k] = z;
        }
    }
}

// ---------------- 64x64 GEMM mainloop ----------------
#define STGB 32768
#define NSTG 4

__device__ __forceinline__ void gemm64(
    char* smem, int m0, int n0,
    const bf16* A0, const bf16* W0, int K0,
    const bf16* A1, const bf16* W1, int K1,
    int npairs, float acc[4][4]) {
    const int tid = threadIdx.x;
    const int w = tid >> 5;
    const int l = tid & 31;
    const int wg = w >> 2;
    const int wm = w & 3;

    const bf16* Ab[2] = {A0, A1};
    const bf16* Wb[2] = {W0, W1};
    const int Kp[2] = {K0, K1};

    int NCH = 0;
    for (int p = 0; p < npairs; ++p) NCH += Kp[p] >> 6;

    const uint32_t sB = (uint32_t)__cvta_generic_to_shared(smem);

    int cp = 0, ckt = 0;
    auto issue = [&](int stg) {
        const bf16* A = Ab[cp];
        const bf16* W = Wb[cp];
        const int K = Kp[cp];
        const int ld = K << 1;
        const uint32_t base = sB + stg * STGB;
#pragma unroll
        for (int i = 0; i < 8; ++i) {
            int c = tid + (i << 8);
            if (c < 512) {
                int row = c >> 3, ch = c & 7;
                const bf16* src = A + (size_t)(m0 + row) * ld + ckt + (ch << 3);
                CP16(base + row * 128 + ((ch ^ (row & 7)) << 4), src);
            } else if (c < 1024) {
                int c2 = c - 512;
                int row = c2 >> 3, ch = c2 & 7;
                const bf16* src = A + (size_t)(m0 + row) * ld + K + ckt + (ch << 3);
                CP16(base + 8192 + row * 128 + ((ch ^ (row & 7)) << 4), src);
            } else if (c < 1536) {
                int c2 = c - 1024;
                int row = c2 >> 3, ch = c2 & 7;
                const bf16* src = W + (size_t)(n0 + row) * ld + ckt + (ch << 3);
                CP16(base + 16384 + row * 128 + ((ch ^ (row & 7)) << 4), src);
            } else {
                int c2 = c - 1536;
                int row = c2 >> 3, ch = c2 & 7;
                const bf16* src = W + (size_t)(n0 + row) * ld + K + ckt + (ch << 3);
                CP16(base + 24576 + row * 128 + ((ch ^ (row & 7)) << 4), src);
            }
        }
        asm volatile("cp.async.commit_group;\n" ::);
        ckt += 64;
        if (ckt >= K) { ckt = 0; ++cp; }
    };

#pragma unroll
    for (int j = 0; j < 4; ++j)
#pragma unroll
        for (int i = 0; i < 4; ++i) acc[j][i] = 0.f;

    const int npre = (NCH < NSTG - 1) ? NCH : (NSTG - 1);
    for (int i = 0; i < npre; ++i) issue(i);

    const int arow = 16 * wm + (l & 15);
    const int asel = (l >> 4) & 1;
    const int nrow0 = wg * 32 + (l & 7) + ((l & 16) >> 1);
    const int nrow1 = nrow0 + 16;
    const int bsel = (l >> 3) & 1;

    for (int it = 0; it < NCH; ++it) {
        const int pend = ((NCH < it + NSTG - 1) ? NCH : (it + NSTG - 1)) - (it + 1);
        if (pend >= 2)      asm volatile("cp.async.wait_group 2;\n" ::);
        else if (pend == 1) asm volatile("cp.async.wait_group 1;\n" ::);
        else                asm volatile("cp.async.wait_group 0;\n" ::);
        __syncthreads();
        if (it + NSTG - 1 < NCH) issue((it + NSTG - 1) & (NSTG - 1));

        const uint32_t aHi = sB + (it & (NSTG - 1)) * STGB;
        const uint32_t aLo = aHi + 8192;
        const uint32_t wHi = aHi + 16384;
        const uint32_t wLo = aHi + 24576;
#pragma unroll
        for (int kh = 0; kh < 4; ++kh) {
            const int ac = 2 * kh + asel;
            const int bc = 2 * kh + bsel;
            const uint32_t aoff = arow * 128 + ((ac ^ (arow & 7)) << 4);
            const uint32_t boff0 = nrow0 * 128 + ((bc ^ (nrow0 & 7)) << 4);
            const uint32_t boff1 = nrow1 * 128 + ((bc ^ (nrow1 & 7)) << 4);
            uint32_t ah0, ah1, ah2, ah3, al0, al1, al2, al3;
            LDSM4(ah0, ah1, ah2, ah3, aHi + aoff);
            LDSM4(al0, al1, al2, al3, aLo + aoff);
            uint32_t bh0, bh1, bh2, bh3, bh4, bh5, bh6, bh7;
            LDSM4(bh0, bh1, bh2, bh3, wHi + boff0);
            LDSM4(bh4, bh5, bh6, bh7, wHi + boff1);
            uint32_t bl0, bl1, bl2, bl3, bl4, bl5, bl6, bl7;
            LDSM4(bl0, bl1, bl2, bl3, wLo + boff0);
            LDSM4(bl4, bl5, bl6, bl7, wLo + boff1);
            MMA16816(acc[0], ah0, ah1, ah2, ah3, bh0, bh1);
            MMA16816(acc[1], ah0, ah1, ah2, ah3, bh2, bh3);
            MMA16816(acc[2], ah0, ah1, ah2, ah3, bh4, bh5);
            MMA16816(acc[3], ah0, ah1, ah2, ah3, bh6, bh7);
            MMA16816(acc[0], ah0, ah1, ah2, ah3, bl0, bl1);
            MMA16816(acc[1], ah0, ah1, ah2, ah3, bl2, bl3);
            MMA16816(acc[2], ah0, ah1, ah2, ah3, bl4, bl5);
            MMA16816(acc[3], ah0, ah1, ah2, ah3, bl6, bl7);
            MMA16816(acc[0], al0, al1, al2, al3, bh0, bh1);
            MMA16816(acc[1], al0, al1, al2, al3, bh2, bh3);
            MMA16816(acc[2], al0, al1, al2, al3, bh4, bh5);
            MMA16816(acc[3], al0, al1, al2, al3, bh6, bh7);
        }
    }
    __syncthreads();
}

// ---------------- epilogues ----------------
__device__ __forceinline__ void epi_store64(int m0, int n0, float acc[4][4],
                                            const float* biasV, float* outF, int ldo) {
    const int tid = threadIdx.x;
    const int w = tid >> 5, l = tid & 31;
    const int wg = w >> 2, wm = w & 3;
    const int r = l >> 2, c2 = (l & 3) * 2;
#pragma unroll
    for (int j = 0; j < 4; ++j) {
        int n = n0 + wg * 32 + 8 * j + c2;
        float bv0 = biasV[n], bv1 = biasV[n + 1];
        size_t row0 = (size_t)(m0 + 16 * wm + r);
        outF[row0 * ldo + n] = acc[j][0] + bv0;
        outF[row0 * ldo + n + 1] = acc[j][1] + bv1;
        outF[(row0 + 8) * ldo + n] = acc[j][2] + bv0;
        outF[(row0 + 8) * ldo + n + 1] = acc[j][3] + bv1;
    }
}

__device__ __forceinline__ void epi_lstm64(char* smem, int n0, float acc[4][4],
                                           const float* biasM,
                                           bf16* outHL, float* outF, float* cstate) {
    const int tid = threadIdx.x;
    const int w = tid >> 5, l = tid & 31;
    const int wg = w >> 2, wm = w & 3;
    const int r = l >> 2, c2 = (l & 3) * 2;
    float* Csm = (float*)smem;
#pragma unroll
    for (int j = 0; j < 4; ++j) {
        int col = wg * 32 + 8 * j + c2;
        int n = n0 + col;
#pragma unroll
        for (int hh = 0; hh < 2; ++hh) {
            int m = 16 * wm + r + hh * 8;
            float b0 = __ldcg(&biasM[(size_t)m * 4096 + n]);
            float b1 = __ldcg(&biasM[(size_t)m * 4096 + n + 1]);
            Csm[m * 65 + col] = acc[j][2 * hh] + b0;
            Csm[m * 65 + col + 1] = acc[j][2 * hh + 1] + b1;
        }
    }
    __syncthreads();
#pragma unroll
    for (int q = 0; q < 4; ++q) {
        int item = tid * 4 + q;
        int b = item >> 4;
        int hu = item & 15;
        float gi = Csm[b * 65 + hu * 4 + 0];
        float gf = Csm[b * 65 + hu * 4 + 1];
        float gg = Csm[b * 65 + hu * 4 + 2];
        float go = Csm[b * 65 + hu * 4 + 3];
        int hg = (n0 >> 2) + hu;
        int idx = b * HDIM + hg;
        float cold = cstate[idx];
        float i_ = sigm(gi), f_ = sigm(gf), g_ = tanhf(gg), o_ = sigm(go);
        float cn = f_ * cold + i_ * g_;
        cstate[idx] = cn;
        float hv = o_ * tanhf(cn);
        if (outF) outF[idx] = hv;
        bf16 hi = __float2bfloat16(hv);
        bf16 lo = __float2bfloat16(hv - __bfloat162float(hi));
        outHL[b * 2048 + hg] = hi;
        outHL[b * 2048 + 1024 + hg] = lo;
    }
    __syncthreads();
}

__device__ __forceinline__ void epi_tanh_c(int n0, float acc[4][4], const float* cpartM,
                                           float* outF, int ldo, bf16* outHL) {
    const int tid = threadIdx.x;
    const int w = tid >> 5, l = tid & 31;
    const int wg = w >> 2, wm = w & 3;
    const int r = l >> 2, c2 = (l & 3) * 2;
#pragma unroll
    for (int j = 0; j < 4; ++j) {
        int n = n0 + wg * 32 + 8 * j + c2;
        int b0r = 16 * wm + r;
#pragma unroll
        for (int hh = 0; hh < 2; ++hh) {
            int bb = b0r + hh * 8;
            float p0 = __ldcg(&cpartM[(size_t)bb * 1024 + n]);
            float p1 = __ldcg(&cpartM[(size_t)bb * 1024 + n + 1]);
            float v0 = tanhf(acc[j][2 * hh] + p0);
            float v1 = tanhf(acc[j][2 * hh + 1] + p1);
            outF[(size_t)bb * ldo + n] = v0;
            outF[(size_t)bb * ldo + n + 1] = v1;
            bf16 h0 = __float2bfloat16(v0);
            bf16 l0 = __float2bfloat16(v0 - __bfloat162float(h0));
            bf16 h1 = __float2bfloat16(v1);
            bf16 l1 = __float2bfloat16(v1 - __bfloat162float(h1));
            outHL[bb * 2048 + n] = h0;
            outHL[bb * 2048 + 1024 + n] = l0;
            outHL[bb * 2048 + n + 1] = h1;
            outHL[bb * 2048 + 1024 + n + 1] = l1;
        }
    }
}

// ---------------- attention: cp.async-pipelined scores + context ----------------
// smem layout: [0,98304) 3x32KB row stages | sh2 4KB @98304 | sred/salpha @102400..
#define ATT_STG 32768
__device__ __forceinline__ void attn_dev(char* smem, int b,
                                         const int* __restrict__ masks,
                                         const float* __restrict__ encproj,
                                         const float* __restrict__ enc,
                                         const float* __restrict__ h2f,
                                         bf16* __restrict__ athl) {
    float* sh2 = (float*)(smem + 3 * ATT_STG);
    float* sred = (float*)(smem + 3 * ATT_STG + 4096);
    float* salpha = sred + LLEN;
    float* stmp = salpha + LLEN;
    const int tid = threadIdx.x;
    const int w = tid >> 5, l = tid & 31;
    const uint32_t sB = (uint32_t)__cvta_generic_to_shared(smem);

    {
        const float4* src = (const float4*)(h2f + b * HDIM);
        ((float4*)sh2)[tid] = __ldcg(src + tid);
    }

    // ---- scores: 16 stages of 8 rows (32KB) over encproj[b] ----
    const char* epbase = (const char*)(encproj + (size_t)b * LLEN * HDIM);
    auto issueS = [&](int s) {
        const uint32_t base = sB + (s % 3) * ATT_STG;
        const char* src = epbase + (size_t)s * ATT_STG;
#pragma unroll
        for (int i = 0; i < 8; ++i) {
            int c = tid + (i << 8);               // 0..2047 chunks of 16B
            CP16(base + c * 16, src + c * 16);
        }
        asm volatile("cp.async.commit_group;\n" ::);
    };
    issueS(0); issueS(1); issueS(2);
    __syncthreads();   // sh2 visible to all

    const float4* sh4 = (const float4*)sh2;
    for (int s = 0; s < 16; ++s) {
        if (s <= 12)      asm volatile("cp.async.wait_group 2;\n" ::);
        else if (s == 13) asm volatile("cp.async.wait_group 2;\n" ::);
        else if (s == 14) asm volatile("cp.async.wait_group 1;\n" ::);
        else              asm volatile("cp.async.wait_group 0;\n" ::);
        __syncthreads();
        // warp w computes dot for row w of this stage
        const float4* row = (const float4*)(smem + (s % 3) * ATT_STG + w * 4096);
        float sdot = 0.f;
#pragma unroll
        for (int j = 0; j < 8; ++j) {
            float4 hv = sh4[l + 32 * j];
            float4 ev = row[l + 32 * j];
            sdot += hv.x * ev.x + hv.y * ev.y + hv.z * ev.z + hv.w * ev.w;
        }
#pragma unroll
        for (int o = 16; o; o >>= 1) sdot += __shfl_xor_sync(0xffffffffu, sdot, o);
        if (l == 0) sred[s * 8 + w] = sdot;
        __syncthreads();
        if (s + 3 < 16) issueS(s + 3);
    }

    // ---- softmax over 128 (with mask) ----
    if (tid < 128) {
        float v = masks[b * LLEN + tid] ? -1e30f : sred[tid];
        sred[tid] = v;
        stmp[tid] = v;
    }
    __syncthreads();
    for (int s = 64; s; s >>= 1) {
        if (tid < s) stmp[tid] = fmaxf(stmp[tid], stmp[tid + s]);
        __syncthreads();
    }
    const float mx = stmp[0];
    __syncthreads();
    if (tid < 128) {
        float p = __expf(sred[tid] - mx);
        salpha[tid] = p;
        stmp[tid] = p;
    }
    __syncthreads();
    for (int s = 64; s; s >>= 1) {
        if (tid < s) stmp[tid] += stmp[tid + s];
        __syncthreads();
    }
    const float inv = 1.f / stmp[0];
    __syncthreads();
    if (tid < 128) salpha[tid] *= inv;
    __syncthreads();

    // ---- context: 16 stages of 8 rows over enc[b]; thread owns f=tid*4 ----
    const char* enbase = (const char*)(enc + (size_t)b * LLEN * HEDIM);
    auto issueC = [&](int s) {
        const uint32_t base = sB + (s % 3) * ATT_STG;
        const char* src = enbase + (size_t)s * ATT_STG;
#pragma unroll
        for (int i = 0; i < 8; ++i) {
            int c = tid + (i << 8);
            CP16(base + c * 16, src + c * 16);
        }
        asm volatile("cp.async.commit_group;\n" ::);
    };
    issueC(0); issueC(1); issueC(2);

    float4 accv = make_float4(0.f, 0.f, 0.f, 0.f);
    for (int s = 0; s < 16; ++s) {
        if (s <= 13)      asm volatile("cp.async.wait_group 2;\n" ::);
        else if (s == 14) asm volatile("cp.async.wait_group 1;\n" ::);
        else              asm volatile("cp.async.wait_group 0;\n" ::);
        __syncthreads();
        const float4* stage4 = (const float4*)(smem + (s % 3) * ATT_STG);
#pragma unroll
        for (int rrow = 0; rrow < 8; ++rrow) {
            float al = salpha[s * 8 + rrow];
            float4 v = stage4[rrow * 256 + tid];
            accv.x += al * v.x;
            accv.y += al * v.y;
            accv.z += al * v.z;
            accv.w += al * v.w;
        }
        __syncthreads();
        if (s + 3 < 16) issueC(s + 3);
    }

    int f = tid * 4;
    float vals[4] = {accv.x, accv.y, accv.z, accv.w};
#pragma unroll
    for (int i = 0; i < 4; ++i) {
        bf16 hi = __float2bfloat16(vals[i]);
        bf16 lo = __float2bfloat16(vals[i] - __bfloat162float(hi));
        athl[b * 2048 + f + i] = hi;
        athl[b * 2048 + 1024 + f + i] = lo;
    }
    __syncthreads();
}

// ---------------- grid barrier (replay-safe) ----------------
__device__ __forceinline__ void gsync(int slot) {
    __threadfence();
    __syncthreads();
    if (threadIdx.x == 0) {
        unsigned g = ((volatile unsigned*)g_gen)[slot];
        unsigned old = atomicAdd(&g_cnt[slot], 1u);
        if (old == NCTA - 1) {
            g_cnt[slot] = 0;
            __threadfence();
            atomicExch(&g_gen[slot], g + 1);
        } else {
            while (((volatile unsigned*)g_gen)[slot] == g) __nanosleep(32);
        }
    }
    __syncthreads();
    __threadfence();
}

// ---------------- prologue GEMM (fp32 store) ----------------
__global__ __launch_bounds__(256) void mma_pro(
    const bf16* A0, const bf16* W0, int K0,
    const float* __restrict__ biasV, float* __restrict__ outF, int ldo) {
    extern __shared__ __align__(16) char smem[];
    float acc[4][4];
    gemm64(smem, blockIdx.y * 64, blockIdx.x * 64,
           A0, W0, K0, nullptr, nullptr, 0, 1, acc);
    epi_store64(blockIdx.y * 64, blockIdx.x * 64, acc, biasV, outF, ldo);
}

// ---------------- step-phase helpers ----------------
__device__ __forceinline__ void lstm1_tile(char* smem, int tp, int tile) {
    float acc[4][4];
    int n0 = tile * 64;
    gemm64(smem, 0, n0, g_h1hl[tp & 1], g_Whh1, 1024, nullptr, nullptr, 0, 1, acc);
    epi_lstm64(smem, n0, acc, g_pregates + (size_t)tp * BBATCH * 4096,
               g_h1hl[(tp & 1) ^ 1], nullptr, g_c1);
}

__device__ __forceinline__ void lstm2_partial(char* smem, int tp, int tile) {
    float acc[4][4];
    int n0 = tile * 64;
    gemm64(smem, 0, n0, g_h1hl[(tp & 1) ^ 1], g_Wih2A, 1024,
           g_h2hl[tp & 1], g_Whh2, 1024, 2, acc);
    epi_store64(0, n0, acc, g_bg2, g_gpart, 4096);
}

__device__ __forceinline__ void lstm2_final(char* smem, int t, int tile) {
    float acc[4][4];
    int n0 = tile * 64;
    gemm64(smem, 0, n0, g_ohl, g_Wih2B, 1024, nullptr, nullptr, 0, 1, acc);
    epi_lstm64(smem, n0, acc, g_gpart, g_h2hl[(t + 1) & 1], g_h2f, g_c2);
}

__device__ __forceinline__ void comb_partial_b(char* smem, int t, int tile,
                                               const float* b_comb) {
    float acc[4][4];
    int n0 = tile * 64;
    gemm64(smem, 0, n0, g_h2hl[(t + 1) & 1], g_WcmB, 1024, nullptr, nullptr, 0, 1, acc);
    epi_store64(0, n0, acc, b_comb, g_cpart, 1024);
}

__device__ __forceinline__ void comb_final(char* smem, int t, int tile, float* outs) {
    float acc[4][4];
    int n0 = tile * 64;
    gemm64(smem, 0, n0, g_athl, g_WcmA, 1024, nullptr, nullptr, 0, 1, acc);
    epi_tanh_c(n0, acc, g_cpart, outs + (size_t)t * BBATCH * HDIM, 1024, g_ohl);
}

// ---------------- persistent decoder loop ----------------
__global__ __launch_bounds__(256, 1) void decoder_loop(
    const int* __restrict__ masks, const float* __restrict__ enc,
    const float* __restrict__ b_comb, float* __restrict__ outs) {
    extern __shared__ __align__(16) char smem[];
    const int bid = blockIdx.x;

    if (bid < 64) lstm1_tile(smem, 0, bid);
    gsync(0);
    if (bid < 64) lstm2_partial(smem, 0, bid);
    gsync(1);

    for (int t = 0; t < TSTEPS; ++t) {
        // PHASE A: LSTM2-final@t (bid<64) || LSTM1@t+1 (bid 64..127)
        if (bid < 64) {
            lstm2_final(smem, t, bid);
        } else if (bid < 128 && t + 1 < TSTEPS) {
            lstm1_tile(smem, t + 1, bid - 64);
        }
        gsync(2 + t * 3);

        // PHASE B: attn@t (bid<64) || LSTM2-partial@t+1 (64..127) || comb-partial@t (128..143)
        if (bid < 64) {
            attn_dev(smem, bid, masks, g_encproj, enc, g_h2f, g_athl);
        } else if (bid < 128) {
            if (t + 1 < TSTEPS) lstm2_partial(smem, t + 1, bid - 64);
        } else if (bid < 144) {
            comb_partial_b(smem, t, bid - 128, b_comb);
        }
        gsync(3 + t * 3);

        // PHASE C: comb-final@t (bid<16)
        if (bid < 16) comb_final(smem, t, bid, outs);
        gsync(4 + t * 3);
    }
}

// ---------------- host launcher ----------------
extern "C" void kernel_launch(void* const* d_in, const int* in_sizes, int n_in,
                              void* d_out, int out_size) {
    const float* enc = (const float*)d_in[0];
    const int* masks = (const int*)d_in[1];
    const float* h1i = (const float*)d_in[2];
    const float* c1i = (const float*)d_in[3];
    const float* h2i = (const float*)d_in[4];
    const float* c2i = (const float*)d_in[5];
    const float* cap = (const float*)d_in[6];
    const float* W_ih1 = (const float*)d_in[7];
    const float* W_hh1 = (const float*)d_in[8];
    const float* b_ih1 = (const float*)d_in[9];
    const float* b_hh1 = (const float*)d_in[10];
    const float* W_ih2 = (const float*)d_in[11];
    const float* W_hh2 = (const float*)d_in[12];
    const float* b_ih2 = (const float*)d_in[13];
    const float* b_hh2 = (const float*)d_in[14];
    const float* W_att = (const float*)d_in[15];
    const float* b_att = (const float*)d_in[16];
    const float* W_comb = (const float*)d_in[17];
    const float* b_comb = (const float*)d_in[18];
    float* outs = (float*)d_out;

    bf16 *pWih1, *pWatt, *pEnchl, *pCapshl;
    float *pEncproj, *pPre, *pBg1;
    cudaGetSymbolAddress((void**)&pWih1, g_Wih1);
    cudaGetSymbolAddress((void**)&pWatt, g_Watt);
    cudaGetSymbolAddress((void**)&pEnchl, g_enchl);
    cudaGetSymbolAddress((void**)&pCapshl, g_capshl);
    cudaGetSymbolAddress((void**)&pEncproj, g_encproj);
    cudaGetSymbolAddress((void**)&pPre, g_pregates);
    cudaGetSymbolAddress((void**)&pBg1, g_bg1);

    const int SMEM = NSTG * STGB;   // 128 KB
    cudaFuncSetAttribute(mma_pro, cudaFuncAttributeMaxDynamicSharedMemorySize, SMEM);
    cudaFuncSetAttribute(decoder_loop, cudaFuncAttributeMaxDynamicSharedMemorySize, SMEM);

    conv_all<<<CONV_BLOCKS, 256>>>(enc, cap, W_ih1, W_hh1, W_ih2, W_hh2, W_comb, W_att,
                                   b_ih1, b_hh1, b_ih2, b_hh2, h1i, c1i, h2i, c2i);

    mma_pro<<<dim3(64, 48), 256, SMEM>>>(pCapshl, pWih1, 512, pBg1, pPre, 4096);
    mma_pro<<<dim3(16, 128), 256, SMEM>>>(pEnchl, pWatt, 1024, b_att, pEncproj, 1024);

    decoder_loop<<<NCTA, 256, SMEM>>>(masks, enc, b_comb, outs);
}

// round 12
// speedup vs baseline: 1.5570x; 1.1176x over previous
#include <cuda_runtime.h>
#include <cuda_bf16.h>
#include <math.h>
#include <stdint.h>

#define BBATCH 64
#define LLEN 128
#define TSTEPS 48
#define EDIM 512
#define HEDIM 1024
#define HDIM 1024
#define NCTA 148

typedef __nv_bfloat16 bf16;

// ---------------- device scratch ----------------
__device__ bf16 g_Wih1[4096 * 1024];
__device__ bf16 g_Whh1[4096 * 2048];
__device__ bf16 g_Wih2A[4096 * 2048];
__device__ bf16 g_Wih2B[4096 * 2048];
__device__ bf16 g_Whh2[4096 * 2048];
__device__ bf16 g_WcmA[1024 * 2048];
__device__ bf16 g_WcmB[1024 * 2048];
__device__ bf16 g_Watt[1024 * 2048];
__device__ bf16 g_enchl[8192 * 2048];
__device__ bf16 g_capshl[3072 * 1024];
__device__ float g_encproj[8192 * 1024];
__device__ float g_pregates[3072 * 4096];
__device__ float g_gpartA[BBATCH * 4096];   // LSTM2 partial: h1*Wih2A + bg2
__device__ float g_gpartB[BBATCH * 4096];   // LSTM2 partial: h2*Whh2
__device__ float g_cpart[BBATCH * 1024];    // comb partial: h2*WcmB + b_comb
__device__ bf16 g_h1hl[2][BBATCH * 2048];
__device__ bf16 g_h2hl[2][BBATCH * 2048];
__device__ bf16 g_ohl[BBATCH * 2048];
__device__ bf16 g_athl[BBATCH * 2048];
__device__ float g_c1[BBATCH * HDIM];
__device__ float g_c2[BBATCH * HDIM];
__device__ float g_h2f[BBATCH * HDIM];
__device__ float g_bg1[4096];
__device__ float g_bg2[4096];
__device__ float g_zero[4096];

__device__ unsigned g_cnt[256];
__device__ unsigned g_gen[256];

__device__ __forceinline__ float sigm(float x) { return 1.f / (1.f + __expf(-x)); }

#define CP16(dst, src) \
    asm volatile("cp.async.cg.shared.global [%0], [%1], 16;\n" ::"r"(dst), "l"(src))
#define LDSM4(R0, R1, R2, R3, ADDR)                                        \
    asm volatile("ldmatrix.sync.aligned.m8n8.x4.shared.b16 {%0,%1,%2,%3},[%4];\n" \
                 : "=r"(R0), "=r"(R1), "=r"(R2), "=r"(R3)                  \
                 : "r"(ADDR))
#define MMA16816(C, A0, A1, A2, A3, B0, B1)                                    \
    asm volatile(                                                               \
        "mma.sync.aligned.m16n8k16.row.col.f32.bf16.bf16.f32 "                  \
        "{%0,%1,%2,%3},{%4,%5,%6,%7},{%8,%9},{%0,%1,%2,%3};\n"                  \
        : "+f"((C)[0]), "+f"((C)[1]), "+f"((C)[2]), "+f"((C)[3])                \
        : "r"(A0), "r"(A1), "r"(A2), "r"(A3), "r"(B0), "r"(B1))

// ---------------- fused prologue conversions ----------------
__device__ __forceinline__ void conv_job(const float* __restrict__ src, int srcld,
                                         int colOff, int K, bf16* __restrict__ dst,
                                         int interleave, int N, int lb) {
    int idx = lb * 256 + threadIdx.x;
    if (idx >= N * K) return;
    int n = idx / K, k = idx - n * K;
    int srcn = interleave ? ((n & 3) * HDIM + (n >> 2)) : n;
    float v = src[(size_t)srcn * srcld + colOff + k];
    bf16 hi = __float2bfloat16(v);
    bf16 lo = __float2bfloat16(v - __bfloat162float(hi));
    dst[(size_t)n * 2 * K + k] = hi;
    dst[(size_t)n * 2 * K + K + k] = lo;
}

#define CONV_BLOCKS 125200

__global__ void conv_all(const float* __restrict__ enc, const float* __restrict__ cap,
                         const float* __restrict__ Wih1, const float* __restrict__ Whh1,
                         const float* __restrict__ Wih2, const float* __restrict__ Whh2,
                         const float* __restrict__ Wcomb, const float* __restrict__ Watt,
                         const float* __restrict__ bi1, const float* __restrict__ bh1,
                         const float* __restrict__ bi2, const float* __restrict__ bh2,
                         const float* __restrict__ h1i, const float* __restrict__ c1i,
                         const float* __restrict__ h2i, const float* __restrict__ c2i) {
    int b = blockIdx.x;
    if (b < 8192)        conv_job(Wih1, 512, 0, 512, g_Wih1, 1, 4096, b);
    else if (b < 24576)  conv_job(Whh1, 1024, 0, 1024, g_Whh1, 1, 4096, b - 8192);
    else if (b < 40960)  conv_job(Wih2, 2048, 0, 1024, g_Wih2A, 1, 4096, b - 24576);
    else if (b < 57344)  conv_job(Wih2, 2048, 1024, 1024, g_Wih2B, 1, 4096, b - 40960);
    else if (b < 73728)  conv_job(Whh2, 1024, 0, 1024, g_Whh2, 1, 4096, b - 57344);
    else if (b < 77824)  conv_job(Wcomb, 2048, 0, 1024, g_WcmA, 0, 1024, b - 73728);
    else if (b < 81920)  conv_job(Wcomb, 2048, 1024, 1024, g_WcmB, 0, 1024, b - 77824);
    else if (b < 86016)  conv_job(Watt, 1024, 0, 1024, g_Watt, 0, 1024, b - 81920);
    else if (b < 118784) conv_job(enc, 1024, 0, 1024, g_enchl, 0, 8192, b - 86016);
    else if (b < 124928) conv_job(cap, 512, 0, 512, g_capshl, 0, 3072, b - 118784);
    else if (b < 124944) {
        int n = (b - 124928) * 256 + threadIdx.x;
        if (n < 4096) {
            int srcn = (n & 3) * HDIM + (n >> 2);
            g_bg1[n] = bi1[srcn] + bh1[srcn];
            g_bg2[n] = bi2[srcn] + bh2[srcn];
            g_zero[n] = 0.f;
        }
    } else {
        int i = (b - 124944) * 256 + threadIdx.x;
        if (i < BBATCH * HDIM) {
            int bb = i >> 10, k = i & 1023;
            g_c1[i] = c1i[i];
            g_c2[i] = c2i[i];
            g_h2f[i] = h2i[i];
            float v1 = h1i[i];
            bf16 h = __float2bfloat16(v1);
            bf16 l = __float2bfloat16(v1 - __bfloat162float(h));
            g_h1hl[0][bb * 2048 + k] = h;
            g_h1hl[0][bb * 2048 + 1024 + k] = l;
            float v2 = h2i[i];
            h = __float2bfloat16(v2);
            l = __float2bfloat16(v2 - __bfloat162float(h));
            g_h2hl[0][bb * 2048 + k] = h;
            g_h2hl[0][bb * 2048 + 1024 + k] = l;
            bf16 z = __float2bfloat16(0.f);
            g_ohl[bb * 2048 + k] = z;
            g_ohl[bb * 2048 + 1024 + k] = z;
        }
    }
}

// ---------------- 64x64 GEMM mainloop (single pair, dual accumulators) ----------------
#define STGB 32768
#define NSTG 4

__device__ __forceinline__ void gemm64(
    char* smem, int m0, int n0,
    const bf16* A0, const bf16* W0, int K0, float acc[4][4]) {
    const int tid = threadIdx.x;
    const int w = tid >> 5;
    const int l = tid & 31;
    const int wg = w >> 2;
    const int wm = w & 3;

    const int NCH = K0 >> 6;
    const uint32_t sB = (uint32_t)__cvta_generic_to_shared(smem);

    int ckt = 0;
    auto issue = [&](int stg) {
        const int ld = K0 << 1;
        const uint32_t base = sB + stg * STGB;
#pragma unroll
        for (int i = 0; i < 8; ++i) {
            int c = tid + (i << 8);
            if (c < 512) {
                int row = c >> 3, ch = c & 7;
                const bf16* src = A0 + (size_t)(m0 + row) * ld + ckt + (ch << 3);
                CP16(base + row * 128 + ((ch ^ (row & 7)) << 4), src);
            } else if (c < 1024) {
                int c2 = c - 512;
                int row = c2 >> 3, ch = c2 & 7;
                const bf16* src = A0 + (size_t)(m0 + row) * ld + K0 + ckt + (ch << 3);
                CP16(base + 8192 + row * 128 + ((ch ^ (row & 7)) << 4), src);
            } else if (c < 1536) {
                int c2 = c - 1024;
                int row = c2 >> 3, ch = c2 & 7;
                const bf16* src = W0 + (size_t)(n0 + row) * ld + ckt + (ch << 3);
                CP16(base + 16384 + row * 128 + ((ch ^ (row & 7)) << 4), src);
            } else {
                int c2 = c - 1536;
                int row = c2 >> 3, ch = c2 & 7;
                const bf16* src = W0 + (size_t)(n0 + row) * ld + K0 + ckt + (ch << 3);
                CP16(base + 24576 + row * 128 + ((ch ^ (row & 7)) << 4), src);
            }
        }
        asm volatile("cp.async.commit_group;\n" ::);
        ckt += 64;
    };

    float accA[4][4], accB[4][4];
#pragma unroll
    for (int j = 0; j < 4; ++j)
#pragma unroll
        for (int i = 0; i < 4; ++i) { accA[j][i] = 0.f; accB[j][i] = 0.f; }

    const int npre = (NCH < NSTG - 1) ? NCH : (NSTG - 1);
    for (int i = 0; i < npre; ++i) issue(i);

    const int arow = 16 * wm + (l & 15);
    const int asel = (l >> 4) & 1;
    const int nrow0 = wg * 32 + (l & 7) + ((l & 16) >> 1);
    const int nrow1 = nrow0 + 16;
    const int bsel = (l >> 3) & 1;

    for (int it = 0; it < NCH; ++it) {
        const int pend = ((NCH < it + NSTG - 1) ? NCH : (it + NSTG - 1)) - (it + 1);
        if (pend >= 2)      asm volatile("cp.async.wait_group 2;\n" ::);
        else if (pend == 1) asm volatile("cp.async.wait_group 1;\n" ::);
        else                asm volatile("cp.async.wait_group 0;\n" ::);
        __syncthreads();
        if (it + NSTG - 1 < NCH) issue((it + NSTG - 1) & (NSTG - 1));

        const uint32_t aHi = sB + (it & (NSTG - 1)) * STGB;
        const uint32_t aLo = aHi + 8192;
        const uint32_t wHi = aHi + 16384;
        const uint32_t wLo = aHi + 24576;
#pragma unroll
        for (int kh = 0; kh < 4; ++kh) {
            const int ac = 2 * kh + asel;
            const int bc = 2 * kh + bsel;
            const uint32_t aoff = arow * 128 + ((ac ^ (arow & 7)) << 4);
            const uint32_t boff0 = nrow0 * 128 + ((bc ^ (nrow0 & 7)) << 4);
            const uint32_t boff1 = nrow1 * 128 + ((bc ^ (nrow1 & 7)) << 4);
            uint32_t ah0, ah1, ah2, ah3, al0, al1, al2, al3;
            LDSM4(ah0, ah1, ah2, ah3, aHi + aoff);
            LDSM4(al0, al1, al2, al3, aLo + aoff);
            uint32_t bh0, bh1, bh2, bh3, bh4, bh5, bh6, bh7;
            LDSM4(bh0, bh1, bh2, bh3, wHi + boff0);
            LDSM4(bh4, bh5, bh6, bh7, wHi + boff1);
            uint32_t bl0, bl1, bl2, bl3, bl4, bl5, bl6, bl7;
            LDSM4(bl0, bl1, bl2, bl3, wLo + boff0);
            LDSM4(bl4, bl5, bl6, bl7, wLo + boff1);
            // hh -> accA ; hl, lh -> accB  (shorter dependent chains per register)
            MMA16816(accA[0], ah0, ah1, ah2, ah3, bh0, bh1);
            MMA16816(accA[1], ah0, ah1, ah2, ah3, bh2, bh3);
            MMA16816(accA[2], ah0, ah1, ah2, ah3, bh4, bh5);
            MMA16816(accA[3], ah0, ah1, ah2, ah3, bh6, bh7);
            MMA16816(accB[0], ah0, ah1, ah2, ah3, bl0, bl1);
            MMA16816(accB[1], ah0, ah1, ah2, ah3, bl2, bl3);
            MMA16816(accB[2], ah0, ah1, ah2, ah3, bl4, bl5);
            MMA16816(accB[3], ah0, ah1, ah2, ah3, bl6, bl7);
            MMA16816(accB[0], al0, al1, al2, al3, bh0, bh1);
            MMA16816(accB[1], al0, al1, al2, al3, bh2, bh3);
            MMA16816(accB[2], al0, al1, al2, al3, bh4, bh5);
            MMA16816(accB[3], al0, al1, al2, al3, bh6, bh7);
        }
    }
#pragma unroll
    for (int j = 0; j < 4; ++j)
#pragma unroll
        for (int i = 0; i < 4; ++i) acc[j][i] = accA[j][i] + accB[j][i];
    __syncthreads();
}

// ---------------- epilogues ----------------
__device__ __forceinline__ void epi_store64(int m0, int n0, float acc[4][4],
                                            const float* biasV, float* outF, int ldo) {
    const int tid = threadIdx.x;
    const int w = tid >> 5, l = tid & 31;
    const int wg = w >> 2, wm = w & 3;
    const int r = l >> 2, c2 = (l & 3) * 2;
#pragma unroll
    for (int j = 0; j < 4; ++j) {
        int n = n0 + wg * 32 + 8 * j + c2;
        float bv0 = biasV[n], bv1 = biasV[n + 1];
        size_t row0 = (size_t)(m0 + 16 * wm + r);
        outF[row0 * ldo + n] = acc[j][0] + bv0;
        outF[row0 * ldo + n + 1] = acc[j][1] + bv1;
        outF[(row0 + 8) * ldo + n] = acc[j][2] + bv0;
        outF[(row0 + 8) * ldo + n + 1] = acc[j][3] + bv1;
    }
}

// LSTM epilogue: bias = biasM1[m][n] (+ biasM2[m][n] if non-null), both ld 4096
__device__ __forceinline__ void epi_lstm64(char* smem, int n0, float acc[4][4],
                                           const float* biasM1, const float* biasM2,
                                           bf16* outHL, float* outF, float* cstate) {
    const int tid = threadIdx.x;
    const int w = tid >> 5, l = tid & 31;
    const int wg = w >> 2, wm = w & 3;
    const int r = l >> 2, c2 = (l & 3) * 2;
    float* Csm = (float*)smem;
#pragma unroll
    for (int j = 0; j < 4; ++j) {
        int col = wg * 32 + 8 * j + c2;
        int n = n0 + col;
#pragma unroll
        for (int hh = 0; hh < 2; ++hh) {
            int m = 16 * wm + r + hh * 8;
            float b0 = __ldcg(&biasM1[(size_t)m * 4096 + n]);
            float b1 = __ldcg(&biasM1[(size_t)m * 4096 + n + 1]);
            if (biasM2) {
                b0 += __ldcg(&biasM2[(size_t)m * 4096 + n]);
                b1 += __ldcg(&biasM2[(size_t)m * 4096 + n + 1]);
            }
            Csm[m * 65 + col] = acc[j][2 * hh] + b0;
            Csm[m * 65 + col + 1] = acc[j][2 * hh + 1] + b1;
        }
    }
    __syncthreads();
#pragma unroll
    for (int q = 0; q < 4; ++q) {
        int item = tid * 4 + q;
        int b = item >> 4;
        int hu = item & 15;
        float gi = Csm[b * 65 + hu * 4 + 0];
        float gf = Csm[b * 65 + hu * 4 + 1];
        float gg = Csm[b * 65 + hu * 4 + 2];
        float go = Csm[b * 65 + hu * 4 + 3];
        int hg = (n0 >> 2) + hu;
        int idx = b * HDIM + hg;
        float cold = cstate[idx];
        float i_ = sigm(gi), f_ = sigm(gf), g_ = tanhf(gg), o_ = sigm(go);
        float cn = f_ * cold + i_ * g_;
        cstate[idx] = cn;
        float hv = o_ * tanhf(cn);
        if (outF) outF[idx] = hv;
        bf16 hi = __float2bfloat16(hv);
        bf16 lo = __float2bfloat16(hv - __bfloat162float(hi));
        outHL[b * 2048 + hg] = hi;
        outHL[b * 2048 + 1024 + hg] = lo;
    }
    __syncthreads();
}

__device__ __forceinline__ void epi_tanh_c(int n0, float acc[4][4], const float* cpartM,
                                           float* outF, int ldo, bf16* outHL) {
    const int tid = threadIdx.x;
    const int w = tid >> 5, l = tid & 31;
    const int wg = w >> 2, wm = w & 3;
    const int r = l >> 2, c2 = (l & 3) * 2;
#pragma unroll
    for (int j = 0; j < 4; ++j) {
        int n = n0 + wg * 32 + 8 * j + c2;
        int b0r = 16 * wm + r;
#pragma unroll
        for (int hh = 0; hh < 2; ++hh) {
            int bb = b0r + hh * 8;
            float p0 = __ldcg(&cpartM[(size_t)bb * 1024 + n]);
            float p1 = __ldcg(&cpartM[(size_t)bb * 1024 + n + 1]);
            float v0 = tanhf(acc[j][2 * hh] + p0);
            float v1 = tanhf(acc[j][2 * hh + 1] + p1);
            outF[(size_t)bb * ldo + n] = v0;
            outF[(size_t)bb * ldo + n + 1] = v1;
            bf16 h0 = __float2bfloat16(v0);
            bf16 l0 = __float2bfloat16(v0 - __bfloat162float(h0));
            bf16 h1 = __float2bfloat16(v1);
            bf16 l1 = __float2bfloat16(v1 - __bfloat162float(h1));
            outHL[bb * 2048 + n] = h0;
            outHL[bb * 2048 + 1024 + n] = l0;
            outHL[bb * 2048 + n + 1] = h1;
            outHL[bb * 2048 + 1024 + n + 1] = l1;
        }
    }
}

// ---------------- attention (cp.async pipelined, unchanged) ----------------
#define ATT_STG 32768
__device__ __forceinline__ void attn_dev(char* smem, int b,
                                         const int* __restrict__ masks,
                                         const float* __restrict__ encproj,
                                         const float* __restrict__ enc,
                                         const float* __restrict__ h2f,
                                         bf16* __restrict__ athl) {
    float* sh2 = (float*)(smem + 3 * ATT_STG);
    float* sred = (float*)(smem + 3 * ATT_STG + 4096);
    float* salpha = sred + LLEN;
    float* stmp = salpha + LLEN;
    const int tid = threadIdx.x;
    const int w = tid >> 5, l = tid & 31;
    const uint32_t sB = (uint32_t)__cvta_generic_to_shared(smem);

    {
        const float4* src = (const float4*)(h2f + b * HDIM);
        ((float4*)sh2)[tid] = __ldcg(src + tid);
    }

    const char* epbase = (const char*)(encproj + (size_t)b * LLEN * HDIM);
    auto issueS = [&](int s) {
        const uint32_t base = sB + (s % 3) * ATT_STG;
        const char* src = epbase + (size_t)s * ATT_STG;
#pragma unroll
        for (int i = 0; i < 8; ++i) {
            int c = tid + (i << 8);
            CP16(base + c * 16, src + c * 16);
        }
        asm volatile("cp.async.commit_group;\n" ::);
    };
    issueS(0); issueS(1); issueS(2);
    __syncthreads();

    const float4* sh4 = (const float4*)sh2;
    for (int s = 0; s < 16; ++s) {
        if (s <= 13)      asm volatile("cp.async.wait_group 2;\n" ::);
        else if (s == 14) asm volatile("cp.async.wait_group 1;\n" ::);
        else              asm volatile("cp.async.wait_group 0;\n" ::);
        __syncthreads();
        const float4* row = (const float4*)(smem + (s % 3) * ATT_STG + w * 4096);
        float sdot = 0.f;
#pragma unroll
        for (int j = 0; j < 8; ++j) {
            float4 hv = sh4[l + 32 * j];
            float4 ev = row[l + 32 * j];
            sdot += hv.x * ev.x + hv.y * ev.y + hv.z * ev.z + hv.w * ev.w;
        }
#pragma unroll
        for (int o = 16; o; o >>= 1) sdot += __shfl_xor_sync(0xffffffffu, sdot, o);
        if (l == 0) sred[s * 8 + w] = sdot;
        __syncthreads();
        if (s + 3 < 16) issueS(s + 3);
    }

    if (tid < 128) {
        float v = masks[b * LLEN + tid] ? -1e30f : sred[tid];
        sred[tid] = v;
        stmp[tid] = v;
    }
    __syncthreads();
    for (int s = 64; s; s >>= 1) {
        if (tid < s) stmp[tid] = fmaxf(stmp[tid], stmp[tid + s]);
        __syncthreads();
    }
    const float mx = stmp[0];
    __syncthreads();
    if (tid < 128) {
        float p = __expf(sred[tid] - mx);
        salpha[tid] = p;
        stmp[tid] = p;
    }
    __syncthreads();
    for (int s = 64; s; s >>= 1) {
        if (tid < s) stmp[tid] += stmp[tid + s];
        __syncthreads();
    }
    const float inv = 1.f / stmp[0];
    __syncthreads();
    if (tid < 128) salpha[tid] *= inv;
    __syncthreads();

    const char* enbase = (const char*)(enc + (size_t)b * LLEN * HEDIM);
    auto issueC = [&](int s) {
        const uint32_t base = sB + (s % 3) * ATT_STG;
        const char* src = enbase + (size_t)s * ATT_STG;
#pragma unroll
        for (int i = 0; i < 8; ++i) {
            int c = tid + (i << 8);
            CP16(base + c * 16, src + c * 16);
        }
        asm volatile("cp.async.commit_group;\n" ::);
    };
    issueC(0); issueC(1); issueC(2);

    float4 accv = make_float4(0.f, 0.f, 0.f, 0.f);
    for (int s = 0; s < 16; ++s) {
        if (s <= 13)      asm volatile("cp.async.wait_group 2;\n" ::);
        else if (s == 14) asm volatile("cp.async.wait_group 1;\n" ::);
        else              asm volatile("cp.async.wait_group 0;\n" ::);
        __syncthreads();
        const float4* stage4 = (const float4*)(smem + (s % 3) * ATT_STG);
#pragma unroll
        for (int rrow = 0; rrow < 8; ++rrow) {
            float al = salpha[s * 8 + rrow];
            float4 v = stage4[rrow * 256 + tid];
            accv.x += al * v.x;
            accv.y += al * v.y;
            accv.z += al * v.z;
            accv.w += al * v.w;
        }
        __syncthreads();
        if (s + 3 < 16) issueC(s + 3);
    }

    int f = tid * 4;
    float vals[4] = {accv.x, accv.y, accv.z, accv.w};
#pragma unroll
    for (int i = 0; i < 4; ++i) {
        bf16 hi = __float2bfloat16(vals[i]);
        bf16 lo = __float2bfloat16(vals[i] - __bfloat162float(hi));
        athl[b * 2048 + f + i] = hi;
        athl[b * 2048 + 1024 + f + i] = lo;
    }
    __syncthreads();
}

// ---------------- grid barrier ----------------
__device__ __forceinline__ void gsync(int slot) {
    __threadfence();
    __syncthreads();
    if (threadIdx.x == 0) {
        unsigned g = ((volatile unsigned*)g_gen)[slot];
        unsigned old = atomicAdd(&g_cnt[slot], 1u);
        if (old == NCTA - 1) {
            g_cnt[slot] = 0;
            __threadfence();
            atomicExch(&g_gen[slot], g + 1);
        } else {
            while (((volatile unsigned*)g_gen)[slot] == g) __nanosleep(32);
        }
    }
    __syncthreads();
    __threadfence();
}

// ---------------- prologue GEMM ----------------
__global__ __launch_bounds__(256) void mma_pro(
    const bf16* A0, const bf16* W0, int K0,
    const float* __restrict__ biasV, float* __restrict__ outF, int ldo) {
    extern __shared__ __align__(16) char smem[];
    float acc[4][4];
    gemm64(smem, blockIdx.y * 64, blockIdx.x * 64, A0, W0, K0, acc);
    epi_store64(blockIdx.y * 64, blockIdx.x * 64, acc, biasV, outF, ldo);
}

// ---------------- step-phase helpers ----------------
__device__ __forceinline__ void lstm1_tile(char* smem, int tp, int tile) {
    float acc[4][4];
    int n0 = tile * 64;
    gemm64(smem, 0, n0, g_h1hl[tp & 1], g_Whh1, 1024, acc);
    epi_lstm64(smem, n0, acc, g_pregates + (size_t)tp * BBATCH * 4096, nullptr,
               g_h1hl[(tp & 1) ^ 1], nullptr, g_c1);
}

// pair1: h1@tp . Wih2A + bg2 -> gpartA
__device__ __forceinline__ void lstm2_pair1(char* smem, int tp, int tile) {
    float acc[4][4];
    int n0 = tile * 64;
    gemm64(smem, 0, n0, g_h1hl[(tp & 1) ^ 1], g_Wih2A, 1024, acc);
    epi_store64(0, n0, acc, g_bg2, g_gpartA, 4096);
}

// pair2: h2@(tp-1) . Whh2 -> gpartB
__device__ __forceinline__ void lstm2_pair2(char* smem, int tp, int tile) {
    float acc[4][4];
    int n0 = tile * 64;
    gemm64(smem, 0, n0, g_h2hl[tp & 1], g_Whh2, 1024, acc);
    epi_store64(0, n0, acc, g_zero, g_gpartB, 4096);
}

// final: ohl . Wih2B + gpartA + gpartB -> h2, c2, h2f
__device__ __forceinline__ void lstm2_final(char* smem, int t, int tile) {
    float acc[4][4];
    int n0 = tile * 64;
    gemm64(smem, 0, n0, g_ohl, g_Wih2B, 1024, acc);
    epi_lstm64(smem, n0, acc, g_gpartA, g_gpartB, g_h2hl[(t + 1) & 1], g_h2f, g_c2);
}

__device__ __forceinline__ void comb_partial_b(char* smem, int t, int tile,
                                               const float* b_comb) {
    float acc[4][4];
    int n0 = tile * 64;
    gemm64(smem, 0, n0, g_h2hl[(t + 1) & 1], g_WcmB, 1024, acc);
    epi_store64(0, n0, acc, b_comb, g_cpart, 1024);
}

__device__ __forceinline__ void comb_final(char* smem, int t, int tile, float* outs) {
    float acc[4][4];
    int n0 = tile * 64;
    gemm64(smem, 0, n0, g_athl, g_WcmA, 1024, acc);
    epi_tanh_c(n0, acc, g_cpart, outs + (size_t)t * BBATCH * HDIM, 1024, g_ohl);
}

// ---------------- persistent decoder loop ----------------
__global__ __launch_bounds__(256, 1) void decoder_loop(
    const int* __restrict__ masks, const float* __restrict__ enc,
    const float* __restrict__ b_comb, float* __restrict__ outs) {
    extern __shared__ __align__(16) char smem[];
    const int bid = blockIdx.x;

    // pre0: LSTM1 @ t=0
    if (bid < 64) lstm1_tile(smem, 0, bid);
    gsync(0);
    // pre1: LSTM2 pair1@0 (bid<64) || pair2@0 (bid 64..127)
    if (bid < 64) lstm2_pair1(smem, 0, bid);
    else if (bid < 128) lstm2_pair2(smem, 0, bid - 64);
    gsync(1);

    for (int t = 0; t < TSTEPS; ++t) {
        // PHASE A: LSTM2-final@t (0-63) || LSTM1@t+1 (64-127)
        if (bid < 64) {
            lstm2_final(smem, t, bid);
        } else if (bid < 128 && t + 1 < TSTEPS) {
            lstm1_tile(smem, t + 1, bid - 64);
        }
        gsync(2 + t * 3);

        // PHASE B: attn@t (0-63) || pair1@t+1 (64-127) || comb-partial@t (128-143)
        if (bid < 64) {
            attn_dev(smem, bid, masks, g_encproj, enc, g_h2f, g_athl);
        } else if (bid < 128) {
            if (t + 1 < TSTEPS) lstm2_pair1(smem, t + 1, bid - 64);
        } else if (bid < 144) {
            comb_partial_b(smem, t, bid - 128, b_comb);
        }
        gsync(3 + t * 3);

        // PHASE C: comb-final@t (0-15) || pair2@t+1 (16-79)
        if (bid < 16) {
            comb_final(smem, t, bid, outs);
        } else if (bid < 80 && t + 1 < TSTEPS) {
            lstm2_pair2(smem, t + 1, bid - 16);
        }
        gsync(4 + t * 3);
    }
}

// ---------------- host launcher ----------------
extern "C" void kernel_launch(void* const* d_in, const int* in_sizes, int n_in,
                              void* d_out, int out_size) {
    const float* enc = (const float*)d_in[0];
    const int* masks = (const int*)d_in[1];
    const float* h1i = (const float*)d_in[2];
    const float* c1i = (const float*)d_in[3];
    const float* h2i = (const float*)d_in[4];
    const float* c2i = (const float*)d_in[5];
    const float* cap = (const float*)d_in[6];
    const float* W_ih1 = (const float*)d_in[7];
    const float* W_hh1 = (const float*)d_in[8];
    const float* b_ih1 = (const float*)d_in[9];
    const float* b_hh1 = (const float*)d_in[10];
    const float* W_ih2 = (const float*)d_in[11];
    const float* W_hh2 = (const float*)d_in[12];
    const float* b_ih2 = (const float*)d_in[13];
    const float* b_hh2 = (const float*)d_in[14];
    const float* W_att = (const float*)d_in[15];
    const float* b_att = (const float*)d_in[16];
    const float* W_comb = (const float*)d_in[17];
    const float* b_comb = (const float*)d_in[18];
    float* outs = (float*)d_out;

    bf16 *pWih1, *pWatt, *pEnchl, *pCapshl;
    float *pEncproj, *pPre, *pBg1;
    cudaGetSymbolAddress((void**)&pWih1, g_Wih1);
    cudaGetSymbolAddress((void**)&pWatt, g_Watt);
    cudaGetSymbolAddress((void**)&pEnchl, g_enchl);
    cudaGetSymbolAddress((void**)&pCapshl, g_capshl);
    cudaGetSymbolAddress((void**)&pEncproj, g_encproj);
    cudaGetSymbolAddress((void**)&pPre, g_pregates);
    cudaGetSymbolAddress((void**)&pBg1, g_bg1);

    const int SMEM = NSTG * STGB;   // 128 KB
    cudaFuncSetAttribute(mma_pro, cudaFuncAttributeMaxDynamicSharedMemorySize, SMEM);
    cudaFuncSetAttribute(decoder_loop, cudaFuncAttributeMaxDynamicSharedMemorySize, SMEM);

    conv_all<<<CONV_BLOCKS, 256>>>(enc, cap, W_ih1, W_hh1, W_ih2, W_hh2, W_comb, W_att,
                                   b_ih1, b_hh1, b_ih2, b_hh2, h1i, c1i, h2i, c2i);

    mma_pro<<<dim3(64, 48), 256, SMEM>>>(pCapshl, pWih1, 512, pBg1, pPre, 4096);
    mma_pro<<<dim3(16, 128), 256, SMEM>>>(pEnchl, pWatt, 1024, b_att, pEncproj, 1024);

    decoder_loop<<<NCTA, 256, SMEM>>>(masks, enc, b_comb, outs);
}